// round 10
// baseline (speedup 1.0000x reference)
#include <cuda_runtime.h>
#include <cuda_bf16.h>
#include <cstdint>
#include <math.h>

// Problem constants
#define Bb   8
#define Nn   1024
#define Cc   768
#define Hh   8
#define HD   96
#define DFF  3072
#define NT_  (Bb * Nn)          // 8192 tokens

// ---------------------------------------------------------------------------
// Scratch (device globals — no allocation allowed)
// ---------------------------------------------------------------------------
__device__ float g_q[(size_t)Bb * Hh * Nn * HD];          // [b][h][n][d]
__device__ float g_qt[(size_t)Bb * Hh * HD * Nn];         // [b][h][d][n]  (V^T)
__device__ float g_attn[(size_t)Bb * Hh * Nn * Nn];       // [b][h][n][m]
__device__ float g_x[(size_t)NT_ * Cc];
__device__ float g_y[(size_t)NT_ * Cc];
__device__ float g_h[(size_t)NT_ * DFF];
__device__ float g_pwt[(size_t)Cc * Cc];                  // proj_w^T
__device__ float g_w1t[(size_t)DFF * Cc];                 // ffn_w1^T
__device__ float g_w2t[(size_t)Cc * DFF];                 // ffn_w2^T

// ---------------------------------------------------------------------------
// helpers
// ---------------------------------------------------------------------------
__device__ __forceinline__ unsigned int smem_u32(const void* p) {
    return (unsigned int)__cvta_generic_to_shared(p);
}
__device__ __forceinline__ void cp_async16(unsigned int dst, const void* src) {
    asm volatile("cp.async.ca.shared.global [%0], [%1], 16;\n" :: "r"(dst), "l"(src));
}
__device__ __forceinline__ void cp_commit() {
    asm volatile("cp.async.commit_group;\n");
}
template<int N>
__device__ __forceinline__ void cp_wait() {
    asm volatile("cp.async.wait_group %0;\n" :: "n"(N));
}
__device__ __forceinline__ void ldmatrix_x4(unsigned int* r, unsigned int addr) {
    asm volatile("ldmatrix.sync.aligned.m8n8.x4.shared.b16 {%0,%1,%2,%3}, [%4];"
                 : "=r"(r[0]), "=r"(r[1]), "=r"(r[2]), "=r"(r[3]) : "r"(addr));
}
__device__ __forceinline__ void mma_tf32(float* c, const unsigned int* a, const unsigned int* b) {
    asm volatile(
        "mma.sync.aligned.m16n8k8.row.col.f32.tf32.tf32.f32 "
        "{%0,%1,%2,%3}, {%4,%5,%6,%7}, {%8,%9}, {%0,%1,%2,%3};"
        : "+f"(c[0]), "+f"(c[1]), "+f"(c[2]), "+f"(c[3])
        : "r"(a[0]), "r"(a[1]), "r"(a[2]), "r"(a[3]), "r"(b[0]), "r"(b[1]));
}

// ---------------------------------------------------------------------------
// Kernel 1: per-patch 3x3 conv (SAME, NHWC, HWIO), q=k=v, write [b][h][n][d]
// ---------------------------------------------------------------------------
__global__ void qconv_kernel(const float* __restrict__ x, const float* __restrict__ w)
{
    __shared__ float s_in[768];
    __shared__ float s_w[81];
    int bn = blockIdx.x;
    int b  = bn >> 10, n = bn & 1023;
    int t  = threadIdx.x;                // 256
    const float* xin = x + (size_t)bn * 768;
    s_in[t]       = xin[t];
    s_in[t + 256] = xin[t + 256];
    s_in[t + 512] = xin[t + 512];
    if (t < 81) s_w[t] = w[t];
    __syncthreads();

    int r = t >> 4, c = t & 15;
    float acc0 = 0.f, acc1 = 0.f, acc2 = 0.f;
    #pragma unroll
    for (int kh = 0; kh < 3; kh++) {
        int rr = r + kh - 1;
        if (rr < 0 || rr > 15) continue;
        #pragma unroll
        for (int kw = 0; kw < 3; kw++) {
            int cc = c + kw - 1;
            if (cc < 0 || cc > 15) continue;
            const float* wp = s_w + (kh * 3 + kw) * 9;
            int ip = (rr * 16 + cc) * 3;
            #pragma unroll
            for (int ci = 0; ci < 3; ci++) {
                float v = s_in[ip + ci];
                acc0 += v * wp[ci * 3 + 0];
                acc1 += v * wp[ci * 3 + 1];
                acc2 += v * wp[ci * 3 + 2];
            }
        }
    }
    float accs[3] = {acc0, acc1, acc2};
    #pragma unroll
    for (int co = 0; co < 3; co++) {
        int cidx = t * 3 + co;
        int h = cidx / HD, d = cidx % HD;
        g_q[(((size_t)b * Hh + h) * Nn + n) * HD + d] = accs[co];
    }
}

// ---------------------------------------------------------------------------
// Batched tiled transpose: in[z][R][C] -> out[z][C][R]. Block (32,8).
// ---------------------------------------------------------------------------
__global__ void transpose_kernel(const float* __restrict__ in, float* __restrict__ out,
                                 int R, int C, size_t sIn, size_t sOut)
{
    __shared__ float tile[32][33];
    int z = blockIdx.z;
    const float* ip = in + (size_t)z * sIn;
    float* op = out + (size_t)z * sOut;
    int c0 = blockIdx.x * 32, r0 = blockIdx.y * 32;
    int tx = threadIdx.x, ty = threadIdx.y;
    #pragma unroll
    for (int j = 0; j < 4; j++)
        tile[ty + 8 * j][tx] = ip[(size_t)(r0 + ty + 8 * j) * C + c0 + tx];
    __syncthreads();
    #pragma unroll
    for (int j = 0; j < 4; j++)
        op[(size_t)(c0 + ty + 8 * j) * R + r0 + tx] = tile[tx][ty + 8 * j];
}

// ===========================================================================
// GEMM variant A: swizzled smem, BN=64, 4 CTAs/SM (scores/proj/ffn1/ffn2)
//   NT: B is [N][K] row-major. BK=32. 8 warps, warp tile 32x32.
//   Swizzle: 16B group column k4' = k4 ^ (row & 7); row stride 32 floats.
// MODE 0: C=acc*scale | 1: acc+bias+res | 2: gelu(acc+bias)
// ===========================================================================
template<int BM, int BN, int MODE>
__global__ __launch_bounds__(256, 4)
void mma_gemm_sw(const float* __restrict__ A, const float* __restrict__ Bm,
                 float* __restrict__ Cm,
                 int K, int lda, int ldb, int ldc,
                 size_t strideA, size_t strideB, size_t strideC,
                 const float* __restrict__ bias, const float* __restrict__ res,
                 int ldres, float scale)
{
    constexpr int BK  = 32;
    constexpr int MFRAG = 2;
    constexpr int NFRAG = BN / 2 / 8;        // 4 for BN=64
    constexpr int ASZ = BM * BK;             // floats per A stage
    constexpr int BSZ = BN * BK;

    extern __shared__ float smem_dyn[];
    float* As = smem_dyn;                    // [2][ASZ]
    float* Bs = smem_dyn + 2 * ASZ;          // [2][BSZ]

    int bz = blockIdx.z;
    A  += strideA * bz;
    Bm += strideB * bz;
    Cm += strideC * bz;

    int m0 = blockIdx.y * BM;
    int n0 = blockIdx.x * BN;
    int t    = threadIdx.x;
    int warp = t >> 5, lane = t & 31;
    int wm0 = (warp & 3) * 32;
    int wn0 = (warp >> 2) * (BN / 2);

    float acc[MFRAG][NFRAG][4];
    #pragma unroll
    for (int i = 0; i < MFRAG; i++)
        #pragma unroll
        for (int j = 0; j < NFRAG; j++)
            #pragma unroll
            for (int e = 0; e < 4; e++) acc[i][j][e] = 0.f;

    int a_row = ((lane >> 3) & 1) * 8 + (lane & 7);
    int a_g   = (lane >> 4);                 // 0/1 k4-group within k-step
    int bp_row = ((lane >> 4) & 1) * 8 + (lane & 7);
    int bp_g   = ((lane >> 3) & 1);

    // cp.async loader: thread writes 16B at logical (row, k4); swizzled col.
    auto load_stage = [&](int st, int kk) {
        float* Asd = As + st * ASZ;
        float* Bsd = Bs + st * BSZ;
        #pragma unroll
        for (int v = 0; v < BM * BK / 1024; v++) {
            int idx = (t + v * 256) * 4;
            int m = idx >> 5, k4 = (idx & 31) >> 2;
            cp_async16(smem_u32(&Asd[m * 32 + ((k4 ^ (m & 7)) << 2)]),
                       &A[(size_t)(m0 + m) * lda + kk + k4 * 4]);
        }
        #pragma unroll
        for (int v = 0; v < BN * BK / 1024; v++) {
            int idx = (t + v * 256) * 4;
            int n = idx >> 5, k4 = (idx & 31) >> 2;
            cp_async16(smem_u32(&Bsd[n * 32 + ((k4 ^ (n & 7)) << 2)]),
                       &Bm[(size_t)(n0 + n) * ldb + kk + k4 * 4]);
        }
    };

    int nIter = K / BK;
    load_stage(0, 0);
    cp_commit();

    for (int it = 0; it < nIter; ++it) {
        int s = it & 1;
        if (it + 1 < nIter) {
            load_stage(s ^ 1, (it + 1) * BK);
            cp_commit();
            cp_wait<1>();
        } else {
            cp_wait<0>();
        }
        __syncthreads();

        float* Asd = As + s * ASZ;
        float* Bsd = Bs + s * BSZ;
        #pragma unroll
        for (int ks = 0; ks < BK / 8; ks++) {
            unsigned int afr[MFRAG][4];
            #pragma unroll
            for (int mf = 0; mf < MFRAG; mf++) {
                int r = wm0 + mf * 16 + a_row;
                int g = (ks * 2 + a_g) ^ (r & 7);
                ldmatrix_x4(afr[mf], smem_u32(&Asd[r * 32 + (g << 2)]));
            }
            unsigned int bfr[NFRAG][2];
            #pragma unroll
            for (int np = 0; np < NFRAG / 2; np++) {
                int r = wn0 + np * 16 + bp_row;
                int g = (ks * 2 + bp_g) ^ (r & 7);
                ldmatrix_x4(&bfr[np * 2][0], smem_u32(&Bsd[r * 32 + (g << 2)]));
            }
            #pragma unroll
            for (int mf = 0; mf < MFRAG; mf++)
                #pragma unroll
                for (int nf = 0; nf < NFRAG; nf++)
                    mma_tf32(acc[mf][nf], afr[mf], bfr[nf]);
        }
        __syncthreads();
    }

    // ---- epilogue
    #pragma unroll
    for (int mf = 0; mf < MFRAG; mf++) {
        #pragma unroll
        for (int half = 0; half < 2; half++) {
            int row = m0 + wm0 + mf * 16 + (lane >> 2) + half * 8;
            #pragma unroll
            for (int nf = 0; nf < NFRAG; nf++) {
                int col = n0 + wn0 + nf * 8 + (lane & 3) * 2;
                float v0 = acc[mf][nf][half * 2 + 0];
                float v1 = acc[mf][nf][half * 2 + 1];
                if constexpr (MODE == 0) {
                    v0 *= scale; v1 *= scale;
                    *reinterpret_cast<float2*>(&Cm[(size_t)row * ldc + col]) = make_float2(v0, v1);
                } else if constexpr (MODE == 1) {
                    float2 bb = *reinterpret_cast<const float2*>(&bias[col]);
                    float2 rr = *reinterpret_cast<const float2*>(&res[(size_t)row * ldres + col]);
                    *reinterpret_cast<float2*>(&Cm[(size_t)row * ldc + col]) =
                        make_float2(v0 + bb.x + rr.x, v1 + bb.y + rr.y);
                } else {
                    float2 bb = *reinterpret_cast<const float2*>(&bias[col]);
                    v0 += bb.x; v1 += bb.y;
                    v0 = 0.5f * v0 * (1.0f + erff(v0 * 0.70710678118654752f));
                    v1 = 0.5f * v1 * (1.0f + erff(v1 * 0.70710678118654752f));
                    *reinterpret_cast<float2*>(&Cm[(size_t)row * ldc + col]) = make_float2(v0, v1);
                }
            }
        }
    }
}

// ===========================================================================
// GEMM variant B: padded smem, BN=96, MODE 3 (AV), as in the 936us baseline.
// ===========================================================================
template<int BM, int BN, int BK>
__global__ __launch_bounds__(256, 2)
void mma_gemm_av(const float* __restrict__ A, const float* __restrict__ Bm,
                 float* __restrict__ Cm,
                 int K, int lda, int ldb, int ldc,
                 size_t strideA, size_t strideB)
{
    constexpr int BKP = BK + 4;
    constexpr int WTN = BN / 2;
    constexpr int MFRAG = 2;
    constexpr int NFRAG = WTN / 8;
    constexpr int ASZ = BM * BKP;
    constexpr int BSZ = BN * BKP;

    extern __shared__ float smem_dyn[];
    float* As = smem_dyn;
    float* Bs = smem_dyn + 2 * ASZ;

    int bz = blockIdx.z;
    A  += strideA * bz;
    Bm += strideB * bz;

    int m0 = blockIdx.y * BM;
    int n0 = blockIdx.x * BN;
    int t    = threadIdx.x;
    int warp = t >> 5, lane = t & 31;
    int wm0 = (warp & 3) * 32;
    int wn0 = (warp >> 2) * WTN;

    float acc[MFRAG][NFRAG][4];
    #pragma unroll
    for (int i = 0; i < MFRAG; i++)
        #pragma unroll
        for (int j = 0; j < NFRAG; j++)
            #pragma unroll
            for (int e = 0; e < 4; e++) acc[i][j][e] = 0.f;

    int a_row = ((lane >> 3) & 1) * 8 + (lane & 7);
    int a_col = (lane >> 4) * 4;
    int bp_row = ((lane >> 4) & 1) * 8 + (lane & 7);
    int bp_col = ((lane >> 3) & 1) * 4;

    auto load_stage = [&](int st, int kk) {
        float* Asd = As + st * ASZ;
        float* Bsd = Bs + st * BSZ;
        #pragma unroll
        for (int v = 0; v < BM * BK / 1024; v++) {
            int idx = (t + v * 256) * 4;
            int m = idx / BK, k = idx % BK;
            cp_async16(smem_u32(&Asd[m * BKP + k]),
                       &A[(size_t)(m0 + m) * lda + kk + k]);
        }
        #pragma unroll
        for (int v = 0; v < BN * BK / 1024; v++) {
            int idx = (t + v * 256) * 4;
            int n = idx / BK, k = idx % BK;
            cp_async16(smem_u32(&Bsd[n * BKP + k]),
                       &Bm[(size_t)(n0 + n) * ldb + kk + k]);
        }
    };

    int nIter = K / BK;
    load_stage(0, 0);
    cp_commit();

    for (int it = 0; it < nIter; ++it) {
        int s = it & 1;
        if (it + 1 < nIter) {
            load_stage(s ^ 1, (it + 1) * BK);
            cp_commit();
            cp_wait<1>();
        } else {
            cp_wait<0>();
        }
        __syncthreads();

        float* Asd = As + s * ASZ;
        float* Bsd = Bs + s * BSZ;
        #pragma unroll
        for (int ks = 0; ks < BK / 8; ks++) {
            unsigned int afr[MFRAG][4];
            #pragma unroll
            for (int mf = 0; mf < MFRAG; mf++) {
                unsigned int addr = smem_u32(&Asd[(wm0 + mf * 16 + a_row) * BKP + ks * 8 + a_col]);
                ldmatrix_x4(afr[mf], addr);
            }
            unsigned int bfr[NFRAG][2];
            #pragma unroll
            for (int np = 0; np < NFRAG / 2; np++) {
                unsigned int addr = smem_u32(&Bsd[(wn0 + np * 16 + bp_row) * BKP + ks * 8 + bp_col]);
                ldmatrix_x4(&bfr[np * 2][0], addr);
            }
            #pragma unroll
            for (int mf = 0; mf < MFRAG; mf++)
                #pragma unroll
                for (int nf = 0; nf < NFRAG; nf++)
                    mma_tf32(acc[mf][nf], afr[mf], bfr[nf]);
        }
        __syncthreads();
    }

    // epilogue: attn-output layout (bz = b*8+h -> g_x[b][row][h*96+col])
    size_t out_off = (size_t)(bz >> 3) * ((size_t)Nn * Cc) + (size_t)(bz & 7) * HD;
    #pragma unroll
    for (int mf = 0; mf < MFRAG; mf++) {
        #pragma unroll
        for (int half = 0; half < 2; half++) {
            int row = m0 + wm0 + mf * 16 + (lane >> 2) + half * 8;
            #pragma unroll
            for (int nf = 0; nf < NFRAG; nf++) {
                int col = n0 + wn0 + nf * 8 + (lane & 3) * 2;
                *reinterpret_cast<float2*>(&Cm[out_off + (size_t)row * ldc + col]) =
                    make_float2(acc[mf][nf][half * 2 + 0], acc[mf][nf][half * 2 + 1]);
            }
        }
    }
}

// ---------------------------------------------------------------------------
// fused per-row softmax (all 8 heads) + re-attention head mix + BN (float4 I/O)
// ---------------------------------------------------------------------------
__global__ void softmax_mix_kernel(const float* __restrict__ rw, const float* __restrict__ rb,
                                   const float* __restrict__ bng, const float* __restrict__ bnb)
{
    __shared__ __align__(16) float sp[8][1024];
    __shared__ float s_w[64];
    __shared__ float s_s[8], s_o[8];

    int bn = blockIdx.x;
    int b  = bn >> 10, n = bn & 1023;
    int t  = threadIdx.x;                    // 256

    if (t < 64) s_w[t] = rw[t];
    if (t < 8) {
        float bs = bng[t] * rsqrtf(1.0f + 1e-3f);
        s_s[t] = bs;
        s_o[t] = rb[t] * bs + bnb[t];
    }
    #pragma unroll
    for (int h = 0; h < 8; h++) {
        const float4* rp4 = reinterpret_cast<const float4*>(
            g_attn + (((size_t)b * Hh + h) * Nn + n) * Nn);
        reinterpret_cast<float4*>(sp[h])[t] = rp4[t];
    }
    __syncthreads();

    int w = t >> 5, lane = t & 31;
    {
        float* sr = sp[w];
        float mx = -1e30f;
        for (int m = lane; m < 1024; m += 32) mx = fmaxf(mx, sr[m]);
        #pragma unroll
        for (int off = 16; off; off >>= 1) mx = fmaxf(mx, __shfl_xor_sync(0xffffffffu, mx, off));
        float sum = 0.f;
        for (int m = lane; m < 1024; m += 32) {
            float e = __expf(sr[m] - mx);
            sr[m] = e;
            sum += e;
        }
        #pragma unroll
        for (int off = 16; off; off >>= 1) sum += __shfl_xor_sync(0xffffffffu, sum, off);
        float inv = 1.0f / sum;
        for (int m = lane; m < 1024; m += 32) sr[m] *= inv;
    }
    __syncthreads();

    float4 p[8];
    #pragma unroll
    for (int h = 0; h < 8; h++) p[h] = reinterpret_cast<const float4*>(sp[h])[t];
    #pragma unroll
    for (int g = 0; g < 8; g++) {
        float4 a = make_float4(0.f, 0.f, 0.f, 0.f);
        #pragma unroll
        for (int h = 0; h < 8; h++) {
            float wgh = s_w[g * 8 + h];
            a.x = fmaf(p[h].x, wgh, a.x);
            a.y = fmaf(p[h].y, wgh, a.y);
            a.z = fmaf(p[h].z, wgh, a.z);
            a.w = fmaf(p[h].w, wgh, a.w);
        }
        float ss = s_s[g], oo = s_o[g];
        a.x = a.x * ss + oo; a.y = a.y * ss + oo;
        a.z = a.z * ss + oo; a.w = a.w * ss + oo;
        reinterpret_cast<float4*>(
            g_attn + (((size_t)b * Hh + g) * Nn + n) * Nn)[t] = a;
    }
}

// ---------------------------------------------------------------------------
// LayerNorm over last dim (768). One block per row.
// ---------------------------------------------------------------------------
__global__ void layernorm_kernel(const float* __restrict__ in, float* __restrict__ out,
                                 const float* __restrict__ g, const float* __restrict__ bta)
{
    __shared__ float red[16];
    __shared__ float s_mu, s_rs;
    int row = blockIdx.x;
    int t   = threadIdx.x;       // 256
    const float* rp = in + (size_t)row * Cc;
    float x0 = rp[t], x1 = rp[t + 256], x2 = rp[t + 512];
    float s  = x0 + x1 + x2;
    float ss = x0 * x0 + x1 * x1 + x2 * x2;
    #pragma unroll
    for (int off = 16; off; off >>= 1) {
        s  += __shfl_xor_sync(0xffffffffu, s, off);
        ss += __shfl_xor_sync(0xffffffffu, ss, off);
    }
    int w = t >> 5, lane = t & 31;
    if (lane == 0) { red[w] = s; red[8 + w] = ss; }
    __syncthreads();
    if (t == 0) {
        float S = 0.f, SS = 0.f;
        #pragma unroll
        for (int i = 0; i < 8; i++) { S += red[i]; SS += red[8 + i]; }
        float mu  = S * (1.0f / 768.0f);
        float var = SS * (1.0f / 768.0f) - mu * mu;
        s_mu = mu;
        s_rs = rsqrtf(var + 1e-3f);
    }
    __syncthreads();
    float mu = s_mu, rs = s_rs;
    float* op = out + (size_t)row * Cc;
    op[t]       = (x0 - mu) * rs * g[t]       + bta[t];
    op[t + 256] = (x1 - mu) * rs * g[t + 256] + bta[t + 256];
    op[t + 512] = (x2 - mu) * rs * g[t + 512] + bta[t + 512];
}

// ---------------------------------------------------------------------------
// Host-side launch helpers
// ---------------------------------------------------------------------------
#define SMEM_SW  (2 * (128 + 64) * 32 * 4)                 // 48 KB
#define SMEM_AV  (2 * (128 * 36 + 96 * 36) * 4)            // ~64.5 KB

static void launch_scores(const float* qp, float* ap, float scale)
{
    static bool init = false;
    if (!init) {
        cudaFuncSetAttribute((const void*)mma_gemm_sw<128, 64, 0>,
                             cudaFuncAttributeMaxDynamicSharedMemorySize, SMEM_SW);
        init = true;
    }
    mma_gemm_sw<128, 64, 0><<<dim3(16, 8, 64), 256, SMEM_SW>>>(
        qp, qp, ap, HD, HD, HD, Nn,
        (size_t)Nn * HD, (size_t)Nn * HD, (size_t)Nn * Nn,
        nullptr, nullptr, 0, scale);
}
static void launch_av(const float* ap, const float* vtp, float* xp)
{
    static bool init = false;
    if (!init) {
        cudaFuncSetAttribute((const void*)mma_gemm_av<128, 96, 32>,
                             cudaFuncAttributeMaxDynamicSharedMemorySize, SMEM_AV);
        init = true;
    }
    mma_gemm_av<128, 96, 32><<<dim3(1, 8, 64), 256, SMEM_AV>>>(
        ap, vtp, xp, Nn, Nn, Nn, Cc,
        (size_t)Nn * Nn, (size_t)Nn * HD);
}
static void launch_proj(const float* xp, const float* wt, float* yp,
                        const float* b, const float* res)
{
    static bool init = false;
    if (!init) {
        cudaFuncSetAttribute((const void*)mma_gemm_sw<128, 64, 1>,
                             cudaFuncAttributeMaxDynamicSharedMemorySize, SMEM_SW);
        init = true;
    }
    mma_gemm_sw<128, 64, 1><<<dim3(12, 64, 1), 256, SMEM_SW>>>(
        xp, wt, yp, Cc, Cc, Cc, Cc,
        0, 0, 0, b, res, Cc, 1.0f);
}
static void launch_ffn1(const float* yp, const float* wt, float* hp, const float* b)
{
    static bool init = false;
    if (!init) {
        cudaFuncSetAttribute((const void*)mma_gemm_sw<128, 64, 2>,
                             cudaFuncAttributeMaxDynamicSharedMemorySize, SMEM_SW);
        init = true;
    }
    mma_gemm_sw<128, 64, 2><<<dim3(48, 64, 1), 256, SMEM_SW>>>(
        yp, wt, hp, Cc, Cc, Cc, DFF,
        0, 0, 0, b, nullptr, 0, 1.0f);
}
static void launch_ffn2(const float* hp, const float* wt, float* xp,
                        const float* b, const float* res)
{
    mma_gemm_sw<128, 64, 1><<<dim3(12, 64, 1), 256, SMEM_SW>>>(
        hp, wt, xp, DFF, DFF, DFF, Cc,
        0, 0, 0, b, res, Cc, 1.0f);
}

// ---------------------------------------------------------------------------
// Launch
// ---------------------------------------------------------------------------
extern "C" void kernel_launch(void* const* d_in, const int* in_sizes, int n_in,
                              void* d_out, int out_size)
{
    (void)in_sizes; (void)n_in; (void)out_size;
    const float* enc       = (const float*)d_in[0];
    const float* qconv_w   = (const float*)d_in[1];
    const float* reatten_w = (const float*)d_in[2];
    const float* reatten_b = (const float*)d_in[3];
    const float* bn_gamma  = (const float*)d_in[4];
    const float* bn_beta   = (const float*)d_in[5];
    const float* proj_w    = (const float*)d_in[6];
    const float* proj_b    = (const float*)d_in[7];
    const float* ffn_w1    = (const float*)d_in[8];
    const float* ffn_b1    = (const float*)d_in[9];
    const float* ffn_w2    = (const float*)d_in[10];
    const float* ffn_b2    = (const float*)d_in[11];
    const float* ln1_g     = (const float*)d_in[12];
    const float* ln1_b     = (const float*)d_in[13];
    const float* ln2_g     = (const float*)d_in[14];
    const float* ln2_b     = (const float*)d_in[15];
    float* out = (float*)d_out;

    float *qp, *qtp, *ap, *xp, *yp, *hp, *pwt, *w1t, *w2t;
    cudaGetSymbolAddress((void**)&qp,  g_q);
    cudaGetSymbolAddress((void**)&qtp, g_qt);
    cudaGetSymbolAddress((void**)&ap,  g_attn);
    cudaGetSymbolAddress((void**)&xp,  g_x);
    cudaGetSymbolAddress((void**)&yp,  g_y);
    cudaGetSymbolAddress((void**)&hp,  g_h);
    cudaGetSymbolAddress((void**)&pwt, g_pwt);
    cudaGetSymbolAddress((void**)&w1t, g_w1t);
    cudaGetSymbolAddress((void**)&w2t, g_w2t);

    const float scale = 0.1020620726159658f;   // 96^-0.5

    // weight transposes ([K][N] -> [N][K])
    transpose_kernel<<<dim3(24, 24, 1), dim3(32, 8)>>>(proj_w, pwt, Cc, Cc, 0, 0);
    transpose_kernel<<<dim3(96, 24, 1), dim3(32, 8)>>>(ffn_w1, w1t, Cc, DFF, 0, 0);
    transpose_kernel<<<dim3(24, 96, 1), dim3(32, 8)>>>(ffn_w2, w2t, DFF, Cc, 0, 0);

    qconv_kernel<<<NT_, 256>>>(enc, qconv_w);
    // V^T per (b,h): [1024][96] -> [96][1024]
    transpose_kernel<<<dim3(3, 32, 64), dim3(32, 8)>>>(qp, qtp, Nn, HD,
                                                       (size_t)Nn * HD, (size_t)Nn * HD);

    launch_scores(qp, ap, scale);
    softmax_mix_kernel<<<NT_, 256>>>(reatten_w, reatten_b, bn_gamma, bn_beta);
    launch_av(ap, qtp, xp);
    launch_proj(xp, pwt, yp, proj_b, enc);
    layernorm_kernel<<<NT_, 256>>>(yp, yp, ln1_g, ln1_b);
    launch_ffn1(yp, w1t, hp, ffn_b1);
    launch_ffn2(hp, w2t, xp, ffn_b2, yp);
    layernorm_kernel<<<NT_, 256>>>(xp, out, ln2_g, ln2_b);
}

// round 11
// speedup vs baseline: 1.2861x; 1.2861x over previous
#include <cuda_runtime.h>
#include <cuda_bf16.h>
#include <cstdint>
#include <math.h>

// Problem constants
#define Bb   8
#define Nn   1024
#define Cc   768
#define Hh   8
#define HD   96
#define DFF  3072
#define NT_  (Bb * Nn)          // 8192 tokens

// ---------------------------------------------------------------------------
// Scratch (device globals — no allocation allowed)
// ---------------------------------------------------------------------------
__device__ float g_q[(size_t)Bb * Hh * Nn * HD];           // [b][h][n][d]
__device__ __nv_bfloat16 g_vt[(size_t)Bb * Hh * HD * Nn];  // V^T bf16 [b][h][d][n]
__device__ float g_attn[(size_t)Bb * Hh * Nn * Nn];        // scores fp32
__device__ __nv_bfloat16 g_pbf[(size_t)Bb * Hh * Nn * Nn]; // probs bf16 (post mix+BN)
__device__ float g_x[(size_t)NT_ * Cc];
__device__ float g_y[(size_t)NT_ * Cc];
__device__ float g_h[(size_t)NT_ * DFF];
__device__ float g_pwt[(size_t)Cc * Cc];                   // proj_w^T
__device__ float g_w1t[(size_t)DFF * Cc];                  // ffn_w1^T
__device__ float g_w2t[(size_t)Cc * DFF];                  // ffn_w2^T

// ---------------------------------------------------------------------------
// helpers
// ---------------------------------------------------------------------------
__device__ __forceinline__ unsigned int smem_u32(const void* p) {
    return (unsigned int)__cvta_generic_to_shared(p);
}
__device__ __forceinline__ void cp_async16(unsigned int dst, const void* src) {
    asm volatile("cp.async.ca.shared.global [%0], [%1], 16;\n" :: "r"(dst), "l"(src));
}
__device__ __forceinline__ void cp_commit() {
    asm volatile("cp.async.commit_group;\n");
}
template<int N>
__device__ __forceinline__ void cp_wait() {
    asm volatile("cp.async.wait_group %0;\n" :: "n"(N));
}
__device__ __forceinline__ void ldmatrix_x4(unsigned int* r, unsigned int addr) {
    asm volatile("ldmatrix.sync.aligned.m8n8.x4.shared.b16 {%0,%1,%2,%3}, [%4];"
                 : "=r"(r[0]), "=r"(r[1]), "=r"(r[2]), "=r"(r[3]) : "r"(addr));
}
__device__ __forceinline__ void mma_tf32(float* c, const unsigned int* a, const unsigned int* b) {
    asm volatile(
        "mma.sync.aligned.m16n8k8.row.col.f32.tf32.tf32.f32 "
        "{%0,%1,%2,%3}, {%4,%5,%6,%7}, {%8,%9}, {%0,%1,%2,%3};"
        : "+f"(c[0]), "+f"(c[1]), "+f"(c[2]), "+f"(c[3])
        : "r"(a[0]), "r"(a[1]), "r"(a[2]), "r"(a[3]), "r"(b[0]), "r"(b[1]));
}
__device__ __forceinline__ void mma_bf16(float* c, const unsigned int* a, const unsigned int* b) {
    asm volatile(
        "mma.sync.aligned.m16n8k16.row.col.f32.bf16.bf16.f32 "
        "{%0,%1,%2,%3}, {%4,%5,%6,%7}, {%8,%9}, {%0,%1,%2,%3};"
        : "+f"(c[0]), "+f"(c[1]), "+f"(c[2]), "+f"(c[3])
        : "r"(a[0]), "r"(a[1]), "r"(a[2]), "r"(a[3]), "r"(b[0]), "r"(b[1]));
}

// ---------------------------------------------------------------------------
// Kernel 1: per-patch 3x3 conv (SAME, NHWC, HWIO), q=k=v, write [b][h][n][d]
// ---------------------------------------------------------------------------
__global__ void qconv_kernel(const float* __restrict__ x, const float* __restrict__ w)
{
    __shared__ float s_in[768];
    __shared__ float s_w[81];
    int bn = blockIdx.x;
    int b  = bn >> 10, n = bn & 1023;
    int t  = threadIdx.x;                // 256
    const float* xin = x + (size_t)bn * 768;
    s_in[t]       = xin[t];
    s_in[t + 256] = xin[t + 256];
    s_in[t + 512] = xin[t + 512];
    if (t < 81) s_w[t] = w[t];
    __syncthreads();

    int r = t >> 4, c = t & 15;
    float acc0 = 0.f, acc1 = 0.f, acc2 = 0.f;
    #pragma unroll
    for (int kh = 0; kh < 3; kh++) {
        int rr = r + kh - 1;
        if (rr < 0 || rr > 15) continue;
        #pragma unroll
        for (int kw = 0; kw < 3; kw++) {
            int cc = c + kw - 1;
            if (cc < 0 || cc > 15) continue;
            const float* wp = s_w + (kh * 3 + kw) * 9;
            int ip = (rr * 16 + cc) * 3;
            #pragma unroll
            for (int ci = 0; ci < 3; ci++) {
                float v = s_in[ip + ci];
                acc0 += v * wp[ci * 3 + 0];
                acc1 += v * wp[ci * 3 + 1];
                acc2 += v * wp[ci * 3 + 2];
            }
        }
    }
    float accs[3] = {acc0, acc1, acc2};
    #pragma unroll
    for (int co = 0; co < 3; co++) {
        int cidx = t * 3 + co;
        int h = cidx / HD, d = cidx % HD;
        g_q[(((size_t)b * Hh + h) * Nn + n) * HD + d] = accs[co];
    }
}

// ---------------------------------------------------------------------------
// Batched tiled transpose fp32: in[z][R][C] -> out[z][C][R]. Block (32,8).
// ---------------------------------------------------------------------------
__global__ void transpose_kernel(const float* __restrict__ in, float* __restrict__ out,
                                 int R, int C, size_t sIn, size_t sOut)
{
    __shared__ float tile[32][33];
    int z = blockIdx.z;
    const float* ip = in + (size_t)z * sIn;
    float* op = out + (size_t)z * sOut;
    int c0 = blockIdx.x * 32, r0 = blockIdx.y * 32;
    int tx = threadIdx.x, ty = threadIdx.y;
    #pragma unroll
    for (int j = 0; j < 4; j++)
        tile[ty + 8 * j][tx] = ip[(size_t)(r0 + ty + 8 * j) * C + c0 + tx];
    __syncthreads();
    #pragma unroll
    for (int j = 0; j < 4; j++)
        op[(size_t)(c0 + ty + 8 * j) * R + r0 + tx] = tile[tx][ty + 8 * j];
}

// ---------------------------------------------------------------------------
// Batched tiled transpose fp32 -> bf16: in[z][R][C] -> out[z][C][R].
// ---------------------------------------------------------------------------
__global__ void transpose_bf16_kernel(const float* __restrict__ in,
                                      __nv_bfloat16* __restrict__ out,
                                      int R, int C, size_t sIn, size_t sOut)
{
    __shared__ float tile[32][33];
    int z = blockIdx.z;
    const float* ip = in + (size_t)z * sIn;
    __nv_bfloat16* op = out + (size_t)z * sOut;
    int c0 = blockIdx.x * 32, r0 = blockIdx.y * 32;
    int tx = threadIdx.x, ty = threadIdx.y;
    #pragma unroll
    for (int j = 0; j < 4; j++)
        tile[ty + 8 * j][tx] = ip[(size_t)(r0 + ty + 8 * j) * C + c0 + tx];
    __syncthreads();
    #pragma unroll
    for (int j = 0; j < 4; j++)
        op[(size_t)(c0 + ty + 8 * j) * R + r0 + tx] = __float2bfloat16(tile[tx][ty + 8 * j]);
}

// ---------------------------------------------------------------------------
// TF32 tensor-core GEMM (NT only: B is [N][K] row-major), cp.async 2-stage.
// (exact R6 936us configuration)
// MODE 0: C = acc*scale  | 1: acc+bias+res | 2: gelu(acc+bias)
// ---------------------------------------------------------------------------
template<int BM, int BN, int BK, int MODE>
__global__ __launch_bounds__(256, 2)
void mma_gemm(const float* __restrict__ A, const float* __restrict__ Bm,
              float* __restrict__ Cm,
              int K, int lda, int ldb, int ldc,
              size_t strideA, size_t strideB, size_t strideC,
              const float* __restrict__ bias, const float* __restrict__ res,
              int ldres, float scale)
{
    constexpr int BKP = BK + 4;
    constexpr int WTN = BN / 2;
    constexpr int MFRAG = 2;
    constexpr int NFRAG = WTN / 8;
    constexpr int ASZ = BM * BKP;
    constexpr int BSZ = BN * BKP;

    extern __shared__ float smem_dyn[];
    float* As = smem_dyn;
    float* Bs = smem_dyn + 2 * ASZ;

    int bz = blockIdx.z;
    A  += strideA * bz;
    Bm += strideB * bz;
    Cm += strideC * bz;

    int m0 = blockIdx.y * BM;
    int n0 = blockIdx.x * BN;
    int t    = threadIdx.x;
    int warp = t >> 5, lane = t & 31;
    int wm0 = (warp & 3) * 32;
    int wn0 = (warp >> 2) * WTN;

    float acc[MFRAG][NFRAG][4];
    #pragma unroll
    for (int i = 0; i < MFRAG; i++)
        #pragma unroll
        for (int j = 0; j < NFRAG; j++)
            #pragma unroll
            for (int e = 0; e < 4; e++) acc[i][j][e] = 0.f;

    int a_row = ((lane >> 3) & 1) * 8 + (lane & 7);
    int a_col = (lane >> 4) * 4;
    int bp_row = ((lane >> 4) & 1) * 8 + (lane & 7);
    int bp_col = ((lane >> 3) & 1) * 4;

    auto load_stage = [&](int st, int kk) {
        float* Asd = As + st * ASZ;
        float* Bsd = Bs + st * BSZ;
        #pragma unroll
        for (int v = 0; v < BM * BK / 1024; v++) {
            int idx = (t + v * 256) * 4;
            int m = idx / BK, k = idx % BK;
            cp_async16(smem_u32(&Asd[m * BKP + k]),
                       &A[(size_t)(m0 + m) * lda + kk + k]);
        }
        #pragma unroll
        for (int v = 0; v < BN * BK / 1024; v++) {
            int idx = (t + v * 256) * 4;
            int n = idx / BK, k = idx % BK;
            cp_async16(smem_u32(&Bsd[n * BKP + k]),
                       &Bm[(size_t)(n0 + n) * ldb + kk + k]);
        }
    };

    int nIter = K / BK;
    load_stage(0, 0);
    cp_commit();

    for (int it = 0; it < nIter; ++it) {
        int s = it & 1;
        if (it + 1 < nIter) {
            load_stage(s ^ 1, (it + 1) * BK);
            cp_commit();
            cp_wait<1>();
        } else {
            cp_wait<0>();
        }
        __syncthreads();

        float* Asd = As + s * ASZ;
        float* Bsd = Bs + s * BSZ;
        #pragma unroll
        for (int ks = 0; ks < BK / 8; ks++) {
            unsigned int afr[MFRAG][4];
            #pragma unroll
            for (int mf = 0; mf < MFRAG; mf++) {
                unsigned int addr = smem_u32(&Asd[(wm0 + mf * 16 + a_row) * BKP + ks * 8 + a_col]);
                ldmatrix_x4(afr[mf], addr);
            }
            unsigned int bfr[NFRAG][2];
            #pragma unroll
            for (int np = 0; np < NFRAG / 2; np++) {
                unsigned int addr = smem_u32(&Bsd[(wn0 + np * 16 + bp_row) * BKP + ks * 8 + bp_col]);
                ldmatrix_x4(&bfr[np * 2][0], addr);
            }
            #pragma unroll
            for (int mf = 0; mf < MFRAG; mf++)
                #pragma unroll
                for (int nf = 0; nf < NFRAG; nf++)
                    mma_tf32(acc[mf][nf], afr[mf], bfr[nf]);
        }
        __syncthreads();
    }

    // ---- epilogue
    #pragma unroll
    for (int mf = 0; mf < MFRAG; mf++) {
        #pragma unroll
        for (int half = 0; half < 2; half++) {
            int row = m0 + wm0 + mf * 16 + (lane >> 2) + half * 8;
            #pragma unroll
            for (int nf = 0; nf < NFRAG; nf++) {
                int col = n0 + wn0 + nf * 8 + (lane & 3) * 2;
                float v0 = acc[mf][nf][half * 2 + 0];
                float v1 = acc[mf][nf][half * 2 + 1];
                if constexpr (MODE == 0) {
                    v0 *= scale; v1 *= scale;
                    *reinterpret_cast<float2*>(&Cm[(size_t)row * ldc + col]) = make_float2(v0, v1);
                } else if constexpr (MODE == 1) {
                    float2 bb = *reinterpret_cast<const float2*>(&bias[col]);
                    float2 rr = *reinterpret_cast<const float2*>(&res[(size_t)row * ldres + col]);
                    *reinterpret_cast<float2*>(&Cm[(size_t)row * ldc + col]) =
                        make_float2(v0 + bb.x + rr.x, v1 + bb.y + rr.y);
                } else {
                    float2 bb = *reinterpret_cast<const float2*>(&bias[col]);
                    v0 += bb.x; v1 += bb.y;
                    v0 = 0.5f * v0 * (1.0f + erff(v0 * 0.70710678118654752f));
                    v1 = 0.5f * v1 * (1.0f + erff(v1 * 0.70710678118654752f));
                    *reinterpret_cast<float2*>(&Cm[(size_t)row * ldc + col]) = make_float2(v0, v1);
                }
            }
        }
    }
}

// ---------------------------------------------------------------------------
// BF16 AV GEMM: O = P(bf16)[Nn x Nn] @ V, with V^T(bf16) [HD x Nn] as NT B.
// mma.m16n8k16 bf16, fp32 accum. BM=128, BN=96, BK=32. 80B padded smem rows.
// Epilogue: attn-output layout (bz=b*8+h -> C[b][row][h*96+col]).
// ---------------------------------------------------------------------------
__global__ __launch_bounds__(256, 2)
void mma_gemm_avbf(const __nv_bfloat16* __restrict__ A,
                   const __nv_bfloat16* __restrict__ Bm,
                   float* __restrict__ Cm,
                   int K, int lda, int ldb, int ldc,
                   size_t strideA, size_t strideB)
{
    constexpr int BM = 128, BN = 96, BK = 32;
    constexpr int ROWB = 80;                      // bytes per padded row (64 data + 16 pad)
    constexpr int ASZB = BM * ROWB;               // 10240 B
    constexpr int BSZB = BN * ROWB;               // 7680 B
    constexpr int MFRAG = 2;
    constexpr int NFRAG = 6;                      // warp tile 32 x 48

    extern __shared__ char smem_c[];
    char* As = smem_c;
    char* Bs = smem_c + 2 * ASZB;

    int bz = blockIdx.z;
    A  += strideA * bz;
    Bm += strideB * bz;

    int m0 = blockIdx.y * BM;
    int n0 = blockIdx.x * BN;                     // grid.x = 1 -> 0
    int t    = threadIdx.x;
    int warp = t >> 5, lane = t & 31;
    int wm0 = (warp & 3) * 32;
    int wn0 = (warp >> 2) * 48;

    float acc[MFRAG][NFRAG][4];
    #pragma unroll
    for (int i = 0; i < MFRAG; i++)
        #pragma unroll
        for (int j = 0; j < NFRAG; j++)
            #pragma unroll
            for (int e = 0; e < 4; e++) acc[i][j][e] = 0.f;

    int arow  = lane & 15;                        // A ldmatrix row within 16
    int ahalf = lane >> 4;                        // k half (16B group)
    int brow  = (lane & 7) + ((lane >> 4) & 1) * 8;  // B n-row
    int bhalf = (lane >> 3) & 1;                  // B k half

    auto load_stage = [&](int st, int kk) {
        char* Asd = As + st * ASZB;
        char* Bsd = Bs + st * BSZB;
        #pragma unroll
        for (int v = 0; v < 2; v++) {             // 512 A groups
            int idx = t + v * 256;
            int r = idx >> 2, g = idx & 3;
            cp_async16(smem_u32(Asd + r * ROWB + g * 16),
                       A + (size_t)(m0 + r) * lda + kk + g * 8);
        }
        #pragma unroll
        for (int v = 0; v < 2; v++) {             // 384 B groups
            int idx = t + v * 256;
            if (idx < 384) {
                int r = idx >> 2, g = idx & 3;
                cp_async16(smem_u32(Bsd + r * ROWB + g * 16),
                           Bm + (size_t)(n0 + r) * ldb + kk + g * 8);
            }
        }
    };

    int nIter = K / BK;                           // 32
    load_stage(0, 0);
    cp_commit();

    for (int it = 0; it < nIter; ++it) {
        int s = it & 1;
        if (it + 1 < nIter) {
            load_stage(s ^ 1, (it + 1) * BK);
            cp_commit();
            cp_wait<1>();
        } else {
            cp_wait<0>();
        }
        __syncthreads();

        char* Asd = As + s * ASZB;
        char* Bsd = Bs + s * BSZB;
        #pragma unroll
        for (int ks = 0; ks < 2; ks++) {          // two k16 steps per BK=32
            unsigned int afr[MFRAG][4];
            #pragma unroll
            for (int mf = 0; mf < MFRAG; mf++) {
                unsigned int addr = smem_u32(
                    Asd + (wm0 + mf * 16 + arow) * ROWB + (ks * 2 + ahalf) * 16);
                ldmatrix_x4(afr[mf], addr);
            }
            unsigned int bfr[NFRAG][2];
            #pragma unroll
            for (int np = 0; np < 3; np++) {
                unsigned int addr = smem_u32(
                    Bsd + (wn0 + np * 16 + brow) * ROWB + (ks * 2 + bhalf) * 16);
                ldmatrix_x4(&bfr[np * 2][0], addr);
            }
            #pragma unroll
            for (int mf = 0; mf < MFRAG; mf++)
                #pragma unroll
                for (int nf = 0; nf < NFRAG; nf++)
                    mma_bf16(acc[mf][nf], afr[mf], bfr[nf]);
        }
        __syncthreads();
    }

    // epilogue: attn-output layout (bz = b*8+h -> C[b][row][h*96+col])
    size_t out_off = (size_t)(bz >> 3) * ((size_t)Nn * Cc) + (size_t)(bz & 7) * HD;
    #pragma unroll
    for (int mf = 0; mf < MFRAG; mf++) {
        #pragma unroll
        for (int half = 0; half < 2; half++) {
            int row = m0 + wm0 + mf * 16 + (lane >> 2) + half * 8;
            #pragma unroll
            for (int nf = 0; nf < NFRAG; nf++) {
                int col = n0 + wn0 + nf * 8 + (lane & 3) * 2;
                *reinterpret_cast<float2*>(&Cm[out_off + (size_t)row * ldc + col]) =
                    make_float2(acc[mf][nf][half * 2 + 0], acc[mf][nf][half * 2 + 1]);
            }
        }
    }
}

// ---------------------------------------------------------------------------
// fused per-row softmax (8 heads) + re-attention head mix + BN.
// Reads fp32 scores from g_attn, writes bf16 probs to g_pbf.
// ---------------------------------------------------------------------------
__global__ void softmax_mix_kernel(const float* __restrict__ rw, const float* __restrict__ rb,
                                   const float* __restrict__ bng, const float* __restrict__ bnb)
{
    __shared__ __align__(16) float sp[8][1024];
    __shared__ float s_w[64];
    __shared__ float s_s[8], s_o[8];

    int bn = blockIdx.x;
    int b  = bn >> 10, n = bn & 1023;
    int t  = threadIdx.x;                    // 256

    if (t < 64) s_w[t] = rw[t];
    if (t < 8) {
        float bs = bng[t] * rsqrtf(1.0f + 1e-3f);
        s_s[t] = bs;
        s_o[t] = rb[t] * bs + bnb[t];
    }
    #pragma unroll
    for (int h = 0; h < 8; h++) {
        const float4* rp4 = reinterpret_cast<const float4*>(
            g_attn + (((size_t)b * Hh + h) * Nn + n) * Nn);
        reinterpret_cast<float4*>(sp[h])[t] = rp4[t];
    }
    __syncthreads();

    int w = t >> 5, lane = t & 31;
    {
        float* sr = sp[w];
        float mx = -1e30f;
        for (int m = lane; m < 1024; m += 32) mx = fmaxf(mx, sr[m]);
        #pragma unroll
        for (int off = 16; off; off >>= 1) mx = fmaxf(mx, __shfl_xor_sync(0xffffffffu, mx, off));
        float sum = 0.f;
        for (int m = lane; m < 1024; m += 32) {
            float e = __expf(sr[m] - mx);
            sr[m] = e;
            sum += e;
        }
        #pragma unroll
        for (int off = 16; off; off >>= 1) sum += __shfl_xor_sync(0xffffffffu, sum, off);
        float inv = 1.0f / sum;
        for (int m = lane; m < 1024; m += 32) sr[m] *= inv;
    }
    __syncthreads();

    float4 p[8];
    #pragma unroll
    for (int h = 0; h < 8; h++) p[h] = reinterpret_cast<const float4*>(sp[h])[t];
    #pragma unroll
    for (int g = 0; g < 8; g++) {
        float4 a = make_float4(0.f, 0.f, 0.f, 0.f);
        #pragma unroll
        for (int h = 0; h < 8; h++) {
            float wgh = s_w[g * 8 + h];
            a.x = fmaf(p[h].x, wgh, a.x);
            a.y = fmaf(p[h].y, wgh, a.y);
            a.z = fmaf(p[h].z, wgh, a.z);
            a.w = fmaf(p[h].w, wgh, a.w);
        }
        float ss = s_s[g], oo = s_o[g];
        a.x = a.x * ss + oo; a.y = a.y * ss + oo;
        a.z = a.z * ss + oo; a.w = a.w * ss + oo;
        __nv_bfloat162 p0 = __float22bfloat162_rn(make_float2(a.x, a.y));
        __nv_bfloat162 p1 = __float22bfloat162_rn(make_float2(a.z, a.w));
        uint2 packed;
        packed.x = *reinterpret_cast<unsigned int*>(&p0);
        packed.y = *reinterpret_cast<unsigned int*>(&p1);
        reinterpret_cast<uint2*>(
            g_pbf + (((size_t)b * Hh + g) * Nn + n) * Nn)[t] = packed;
    }
}

// ---------------------------------------------------------------------------
// LayerNorm over last dim (768). One block per row.
// ---------------------------------------------------------------------------
__global__ void layernorm_kernel(const float* __restrict__ in, float* __restrict__ out,
                                 const float* __restrict__ g, const float* __restrict__ bta)
{
    __shared__ float red[16];
    __shared__ float s_mu, s_rs;
    int row = blockIdx.x;
    int t   = threadIdx.x;       // 256
    const float* rp = in + (size_t)row * Cc;
    float x0 = rp[t], x1 = rp[t + 256], x2 = rp[t + 512];
    float s  = x0 + x1 + x2;
    float ss = x0 * x0 + x1 * x1 + x2 * x2;
    #pragma unroll
    for (int off = 16; off; off >>= 1) {
        s  += __shfl_xor_sync(0xffffffffu, s, off);
        ss += __shfl_xor_sync(0xffffffffu, ss, off);
    }
    int w = t >> 5, lane = t & 31;
    if (lane == 0) { red[w] = s; red[8 + w] = ss; }
    __syncthreads();
    if (t == 0) {
        float S = 0.f, SS = 0.f;
        #pragma unroll
        for (int i = 0; i < 8; i++) { S += red[i]; SS += red[8 + i]; }
        float mu  = S * (1.0f / 768.0f);
        float var = SS * (1.0f / 768.0f) - mu * mu;
        s_mu = mu;
        s_rs = rsqrtf(var + 1e-3f);
    }
    __syncthreads();
    float mu = s_mu, rs = s_rs;
    float* op = out + (size_t)row * Cc;
    op[t]       = (x0 - mu) * rs * g[t]       + bta[t];
    op[t + 256] = (x1 - mu) * rs * g[t + 256] + bta[t + 256];
    op[t + 512] = (x2 - mu) * rs * g[t + 512] + bta[t + 512];
}

// ---------------------------------------------------------------------------
// Host-side launch helpers
// ---------------------------------------------------------------------------
static int smem_bytes(int BM, int BN, int BK) {
    return 2 * (BM * (BK + 4) + BN * (BK + 4)) * 4;
}
#define SMEM_AVBF (2 * (128 * 80 + 96 * 80))   // 35840 B

static void launch_scores(const float* qp, float* ap, float scale)
{
    static bool init = false;
    int sm = smem_bytes(128, 128, 32);
    if (!init) {
        cudaFuncSetAttribute((const void*)mma_gemm<128, 128, 32, 0>,
                             cudaFuncAttributeMaxDynamicSharedMemorySize, sm);
        init = true;
    }
    mma_gemm<128, 128, 32, 0><<<dim3(8, 8, 64), 256, sm>>>(
        qp, qp, ap, HD, HD, HD, Nn,
        (size_t)Nn * HD, (size_t)Nn * HD, (size_t)Nn * Nn,
        nullptr, nullptr, 0, scale);
}
static void launch_av(const __nv_bfloat16* pbf, const __nv_bfloat16* vt, float* xp)
{
    mma_gemm_avbf<<<dim3(1, 8, 64), 256, SMEM_AVBF>>>(
        pbf, vt, xp, Nn, Nn, Nn, Cc,
        (size_t)Nn * Nn, (size_t)Nn * HD);
}
static void launch_proj(const float* xp, const float* wt, float* yp,
                        const float* b, const float* res)
{
    static bool init = false;
    int sm = smem_bytes(128, 128, 32);
    if (!init) {
        cudaFuncSetAttribute((const void*)mma_gemm<128, 128, 32, 1>,
                             cudaFuncAttributeMaxDynamicSharedMemorySize, sm);
        init = true;
    }
    mma_gemm<128, 128, 32, 1><<<dim3(6, 64, 1), 256, sm>>>(
        xp, wt, yp, Cc, Cc, Cc, Cc,
        0, 0, 0, b, res, Cc, 1.0f);
}
static void launch_ffn1(const float* yp, const float* wt, float* hp, const float* b)
{
    static bool init = false;
    int sm = smem_bytes(128, 128, 32);
    if (!init) {
        cudaFuncSetAttribute((const void*)mma_gemm<128, 128, 32, 2>,
                             cudaFuncAttributeMaxDynamicSharedMemorySize, sm);
        init = true;
    }
    mma_gemm<128, 128, 32, 2><<<dim3(24, 64, 1), 256, sm>>>(
        yp, wt, hp, Cc, Cc, Cc, DFF,
        0, 0, 0, b, nullptr, 0, 1.0f);
}
static void launch_ffn2(const float* hp, const float* wt, float* xp,
                        const float* b, const float* res)
{
    mma_gemm<128, 128, 32, 1><<<dim3(6, 64, 1), 256, smem_bytes(128, 128, 32)>>>(
        hp, wt, xp, DFF, DFF, DFF, Cc,
        0, 0, 0, b, res, Cc, 1.0f);
}

// ---------------------------------------------------------------------------
// Launch
// ---------------------------------------------------------------------------
extern "C" void kernel_launch(void* const* d_in, const int* in_sizes, int n_in,
                              void* d_out, int out_size)
{
    (void)in_sizes; (void)n_in; (void)out_size;
    const float* enc       = (const float*)d_in[0];
    const float* qconv_w   = (const float*)d_in[1];
    const float* reatten_w = (const float*)d_in[2];
    const float* reatten_b = (const float*)d_in[3];
    const float* bn_gamma  = (const float*)d_in[4];
    const float* bn_beta   = (const float*)d_in[5];
    const float* proj_w    = (const float*)d_in[6];
    const float* proj_b    = (const float*)d_in[7];
    const float* ffn_w1    = (const float*)d_in[8];
    const float* ffn_b1    = (const float*)d_in[9];
    const float* ffn_w2    = (const float*)d_in[10];
    const float* ffn_b2    = (const float*)d_in[11];
    const float* ln1_g     = (const float*)d_in[12];
    const float* ln1_b     = (const float*)d_in[13];
    const float* ln2_g     = (const float*)d_in[14];
    const float* ln2_b     = (const float*)d_in[15];
    float* out = (float*)d_out;

    float *qp, *ap, *xp, *yp, *hp, *pwt, *w1t, *w2t;
    __nv_bfloat16 *vtp, *pbf;
    cudaGetSymbolAddress((void**)&qp,  g_q);
    cudaGetSymbolAddress((void**)&vtp, g_vt);
    cudaGetSymbolAddress((void**)&ap,  g_attn);
    cudaGetSymbolAddress((void**)&pbf, g_pbf);
    cudaGetSymbolAddress((void**)&xp,  g_x);
    cudaGetSymbolAddress((void**)&yp,  g_y);
    cudaGetSymbolAddress((void**)&hp,  g_h);
    cudaGetSymbolAddress((void**)&pwt, g_pwt);
    cudaGetSymbolAddress((void**)&w1t, g_w1t);
    cudaGetSymbolAddress((void**)&w2t, g_w2t);

    const float scale = 0.1020620726159658f;   // 96^-0.5

    // weight transposes ([K][N] -> [N][K])
    transpose_kernel<<<dim3(24, 24, 1), dim3(32, 8)>>>(proj_w, pwt, Cc, Cc, 0, 0);
    transpose_kernel<<<dim3(96, 24, 1), dim3(32, 8)>>>(ffn_w1, w1t, Cc, DFF, 0, 0);
    transpose_kernel<<<dim3(24, 96, 1), dim3(32, 8)>>>(ffn_w2, w2t, DFF, Cc, 0, 0);

    qconv_kernel<<<NT_, 256>>>(enc, qconv_w);
    // V^T per (b,h): [1024][96] fp32 -> [96][1024] bf16
    transpose_bf16_kernel<<<dim3(3, 32, 64), dim3(32, 8)>>>(qp, vtp, Nn, HD,
                                                            (size_t)Nn * HD, (size_t)Nn * HD);

    launch_scores(qp, ap, scale);
    softmax_mix_kernel<<<NT_, 256>>>(reatten_w, reatten_b, bn_gamma, bn_beta);
    launch_av(pbf, vtp, xp);
    launch_proj(xp, pwt, yp, proj_b, enc);
    layernorm_kernel<<<NT_, 256>>>(yp, yp, ln1_g, ln1_b);
    launch_ffn1(yp, w1t, hp, ffn_b1);
    launch_ffn2(hp, w2t, xp, ffn_b2, yp);
    layernorm_kernel<<<NT_, 256>>>(xp, out, ln2_g, ln2_b);
}

// round 12
// speedup vs baseline: 1.7226x; 1.3394x over previous
#include <cuda_runtime.h>
#include <cuda_bf16.h>
#include <cuda_fp16.h>
#include <cstdint>
#include <math.h>

// Problem constants
#define Bb   8
#define Nn   1024
#define Cc   768
#define Hh   8
#define HD   96
#define DFF  3072
#define NT_  (Bb * Nn)          // 8192 tokens

// ---------------------------------------------------------------------------
// Scratch (device globals — no allocation allowed)
// ---------------------------------------------------------------------------
__device__ __half g_qh[(size_t)Bb * Hh * Nn * HD];         // q fp16 [b][h][n][d]
__device__ __half g_vt[(size_t)Bb * Hh * HD * Nn];         // V^T fp16 [b][h][d][n]
__device__ float  g_attn[(size_t)Bb * Hh * Nn * Nn];       // scores fp32
__device__ __half g_ph[(size_t)Bb * Hh * Nn * Nn];         // probs fp16
__device__ __half g_xh[(size_t)NT_ * Cc];                  // attn-out fp16 (proj A)
__device__ float  g_y[(size_t)NT_ * Cc];                   // LN1 out fp32 (residual)
__device__ __half g_yh[(size_t)NT_ * Cc];                  // LN1 out fp16 (ffn1 A)
__device__ __half g_hh[(size_t)NT_ * DFF];                 // ffn hidden fp16
__device__ float  g_x[(size_t)NT_ * Cc];                   // proj-out / ffn2-out fp32
__device__ __half g_pwt[(size_t)Cc * Cc];                  // proj_w^T fp16
__device__ __half g_w1t[(size_t)DFF * Cc];                 // ffn_w1^T fp16
__device__ __half g_w2t[(size_t)Cc * DFF];                 // ffn_w2^T fp16

// ---------------------------------------------------------------------------
// helpers
// ---------------------------------------------------------------------------
__device__ __forceinline__ unsigned int smem_u32(const void* p) {
    return (unsigned int)__cvta_generic_to_shared(p);
}
__device__ __forceinline__ void cp_async16(unsigned int dst, const void* src) {
    asm volatile("cp.async.ca.shared.global [%0], [%1], 16;\n" :: "r"(dst), "l"(src));
}
__device__ __forceinline__ void cp_commit() {
    asm volatile("cp.async.commit_group;\n");
}
template<int N>
__device__ __forceinline__ void cp_wait() {
    asm volatile("cp.async.wait_group %0;\n" :: "n"(N));
}
__device__ __forceinline__ void ldmatrix_x4(unsigned int* r, unsigned int addr) {
    asm volatile("ldmatrix.sync.aligned.m8n8.x4.shared.b16 {%0,%1,%2,%3}, [%4];"
                 : "=r"(r[0]), "=r"(r[1]), "=r"(r[2]), "=r"(r[3]) : "r"(addr));
}
__device__ __forceinline__ void mma_f16(float* c, const unsigned int* a, const unsigned int* b) {
    asm volatile(
        "mma.sync.aligned.m16n8k16.row.col.f32.f16.f16.f32 "
        "{%0,%1,%2,%3}, {%4,%5,%6,%7}, {%8,%9}, {%0,%1,%2,%3};"
        : "+f"(c[0]), "+f"(c[1]), "+f"(c[2]), "+f"(c[3])
        : "r"(a[0]), "r"(a[1]), "r"(a[2]), "r"(a[3]), "r"(b[0]), "r"(b[1]));
}

// ---------------------------------------------------------------------------
// Kernel 1: per-patch 3x3 conv, q=k=v, write fp16 [b][h][n][d]
// ---------------------------------------------------------------------------
__global__ void qconv_kernel(const float* __restrict__ x, const float* __restrict__ w)
{
    __shared__ float s_in[768];
    __shared__ float s_w[81];
    int bn = blockIdx.x;
    int b  = bn >> 10, n = bn & 1023;
    int t  = threadIdx.x;                // 256
    const float* xin = x + (size_t)bn * 768;
    s_in[t]       = xin[t];
    s_in[t + 256] = xin[t + 256];
    s_in[t + 512] = xin[t + 512];
    if (t < 81) s_w[t] = w[t];
    __syncthreads();

    int r = t >> 4, c = t & 15;
    float acc0 = 0.f, acc1 = 0.f, acc2 = 0.f;
    #pragma unroll
    for (int kh = 0; kh < 3; kh++) {
        int rr = r + kh - 1;
        if (rr < 0 || rr > 15) continue;
        #pragma unroll
        for (int kw = 0; kw < 3; kw++) {
            int cc = c + kw - 1;
            if (cc < 0 || cc > 15) continue;
            const float* wp = s_w + (kh * 3 + kw) * 9;
            int ip = (rr * 16 + cc) * 3;
            #pragma unroll
            for (int ci = 0; ci < 3; ci++) {
                float v = s_in[ip + ci];
                acc0 += v * wp[ci * 3 + 0];
                acc1 += v * wp[ci * 3 + 1];
                acc2 += v * wp[ci * 3 + 2];
            }
        }
    }
    float accs[3] = {acc0, acc1, acc2};
    #pragma unroll
    for (int co = 0; co < 3; co++) {
        int cidx = t * 3 + co;
        int h = cidx / HD, d = cidx % HD;
        g_qh[(((size_t)b * Hh + h) * Nn + n) * HD + d] = __float2half(accs[co]);
    }
}

// ---------------------------------------------------------------------------
// Transpose fp32 -> fp16: in[z][R][C] fp32 -> out[z][C][R] fp16. Block (32,8).
// ---------------------------------------------------------------------------
__global__ void transpose_f2h_kernel(const float* __restrict__ in,
                                     __half* __restrict__ out,
                                     int R, int C, size_t sIn, size_t sOut)
{
    __shared__ float tile[32][33];
    int z = blockIdx.z;
    const float* ip = in + (size_t)z * sIn;
    __half* op = out + (size_t)z * sOut;
    int c0 = blockIdx.x * 32, r0 = blockIdx.y * 32;
    int tx = threadIdx.x, ty = threadIdx.y;
    #pragma unroll
    for (int j = 0; j < 4; j++)
        tile[ty + 8 * j][tx] = ip[(size_t)(r0 + ty + 8 * j) * C + c0 + tx];
    __syncthreads();
    #pragma unroll
    for (int j = 0; j < 4; j++)
        op[(size_t)(c0 + ty + 8 * j) * R + r0 + tx] = __float2half(tile[tx][ty + 8 * j]);
}

// ---------------------------------------------------------------------------
// Transpose fp16 -> fp16: in[z][R][C] -> out[z][C][R]. (for V^T from g_qh)
// ---------------------------------------------------------------------------
__global__ void transpose_h2h_kernel(const __half* __restrict__ in,
                                     __half* __restrict__ out,
                                     int R, int C, size_t sIn, size_t sOut)
{
    __shared__ float tile[32][33];
    int z = blockIdx.z;
    const __half* ip = in + (size_t)z * sIn;
    __half* op = out + (size_t)z * sOut;
    int c0 = blockIdx.x * 32, r0 = blockIdx.y * 32;
    int tx = threadIdx.x, ty = threadIdx.y;
    #pragma unroll
    for (int j = 0; j < 4; j++)
        tile[ty + 8 * j][tx] = __half2float(ip[(size_t)(r0 + ty + 8 * j) * C + c0 + tx]);
    __syncthreads();
    #pragma unroll
    for (int j = 0; j < 4; j++)
        op[(size_t)(c0 + ty + 8 * j) * R + r0 + tx] = __float2half(tile[tx][ty + 8 * j]);
}

// ---------------------------------------------------------------------------
// FP16 tensor-core GEMM (NT: A [M][K], B [N][K], both fp16 row-major).
// mma.m16n8k16, fp32 accum. BM=BN=128, BK=32, 80B padded smem rows.
// 8 warps (4x2), warp tile 32x64. cp.async 2-stage.
// MODE 0: fp32 C = acc*scale       | MODE 1: fp32 C = acc+bias+res
// MODE 2: fp16 C = gelu(acc+bias)
// ---------------------------------------------------------------------------
template<int MODE>
__global__ __launch_bounds__(256, 2)
void mma_gemm_h(const __half* __restrict__ A, const __half* __restrict__ Bm,
                void* __restrict__ Cv,
                int K, int lda, int ldb, int ldc,
                size_t strideA, size_t strideB, size_t strideC,
                const float* __restrict__ bias, const float* __restrict__ res,
                int ldres, float scale)
{
    constexpr int BM = 128, BN = 128, BK = 32;
    constexpr int ROWB = 80;                  // 64B data + 16B pad
    constexpr int ASZB = BM * ROWB;
    constexpr int BSZB = BN * ROWB;
    constexpr int MFRAG = 2;
    constexpr int NFRAG = 8;                  // warp tile 32 x 64

    extern __shared__ char smem_c[];
    char* As = smem_c;
    char* Bs = smem_c + 2 * ASZB;

    int bz = blockIdx.z;
    A  += strideA * bz;
    Bm += strideB * bz;

    int m0 = blockIdx.y * BM;
    int n0 = blockIdx.x * BN;
    int t    = threadIdx.x;
    int warp = t >> 5, lane = t & 31;
    int wm0 = (warp & 3) * 32;
    int wn0 = (warp >> 2) * 64;

    float acc[MFRAG][NFRAG][4];
    #pragma unroll
    for (int i = 0; i < MFRAG; i++)
        #pragma unroll
        for (int j = 0; j < NFRAG; j++)
            #pragma unroll
            for (int e = 0; e < 4; e++) acc[i][j][e] = 0.f;

    int arow  = lane & 15;
    int ahalf = lane >> 4;
    int brow  = (lane & 7) + ((lane >> 4) & 1) * 8;
    int bhalf = (lane >> 3) & 1;

    auto load_stage = [&](int st, int kk) {
        char* Asd = As + st * ASZB;
        char* Bsd = Bs + st * BSZB;
        #pragma unroll
        for (int v = 0; v < 2; v++) {         // 512 A groups (128 rows x 4)
            int idx = t + v * 256;
            int r = idx >> 2, g = idx & 3;
            cp_async16(smem_u32(Asd + r * ROWB + g * 16),
                       A + (size_t)(m0 + r) * lda + kk + g * 8);
        }
        #pragma unroll
        for (int v = 0; v < 2; v++) {         // 512 B groups
            int idx = t + v * 256;
            int r = idx >> 2, g = idx & 3;
            cp_async16(smem_u32(Bsd + r * ROWB + g * 16),
                       Bm + (size_t)(n0 + r) * ldb + kk + g * 8);
        }
    };

    int nIter = K / BK;
    load_stage(0, 0);
    cp_commit();

    for (int it = 0; it < nIter; ++it) {
        int s = it & 1;
        if (it + 1 < nIter) {
            load_stage(s ^ 1, (it + 1) * BK);
            cp_commit();
            cp_wait<1>();
        } else {
            cp_wait<0>();
        }
        __syncthreads();

        char* Asd = As + s * ASZB;
        char* Bsd = Bs + s * BSZB;
        #pragma unroll
        for (int ks = 0; ks < 2; ks++) {      // two k16 steps per BK=32
            unsigned int afr[MFRAG][4];
            #pragma unroll
            for (int mf = 0; mf < MFRAG; mf++) {
                unsigned int addr = smem_u32(
                    Asd + (wm0 + mf * 16 + arow) * ROWB + (ks * 2 + ahalf) * 16);
                ldmatrix_x4(afr[mf], addr);
            }
            unsigned int bfr[NFRAG][2];
            #pragma unroll
            for (int np = 0; np < 4; np++) {
                unsigned int addr = smem_u32(
                    Bsd + (wn0 + np * 16 + brow) * ROWB + (ks * 2 + bhalf) * 16);
                ldmatrix_x4(&bfr[np * 2][0], addr);
            }
            #pragma unroll
            for (int mf = 0; mf < MFRAG; mf++)
                #pragma unroll
                for (int nf = 0; nf < NFRAG; nf++)
                    mma_f16(acc[mf][nf], afr[mf], bfr[nf]);
        }
        __syncthreads();
    }

    // ---- epilogue
    float* Cf = (float*)Cv;
    __half* Ch = (__half*)Cv;
    if (MODE != 2) Cf += strideC * bz;

    #pragma unroll
    for (int mf = 0; mf < MFRAG; mf++) {
        #pragma unroll
        for (int half_ = 0; half_ < 2; half_++) {
            int row = m0 + wm0 + mf * 16 + (lane >> 2) + half_ * 8;
            #pragma unroll
            for (int nf = 0; nf < NFRAG; nf++) {
                int col = n0 + wn0 + nf * 8 + (lane & 3) * 2;
                float v0 = acc[mf][nf][half_ * 2 + 0];
                float v1 = acc[mf][nf][half_ * 2 + 1];
                if constexpr (MODE == 0) {
                    v0 *= scale; v1 *= scale;
                    *reinterpret_cast<float2*>(&Cf[(size_t)row * ldc + col]) = make_float2(v0, v1);
                } else if constexpr (MODE == 1) {
                    float2 bb = *reinterpret_cast<const float2*>(&bias[col]);
                    float2 rr = *reinterpret_cast<const float2*>(&res[(size_t)row * ldres + col]);
                    *reinterpret_cast<float2*>(&Cf[(size_t)row * ldc + col]) =
                        make_float2(v0 + bb.x + rr.x, v1 + bb.y + rr.y);
                } else {
                    float2 bb = *reinterpret_cast<const float2*>(&bias[col]);
                    v0 += bb.x; v1 += bb.y;
                    v0 = 0.5f * v0 * (1.0f + erff(v0 * 0.70710678118654752f));
                    v1 = 0.5f * v1 * (1.0f + erff(v1 * 0.70710678118654752f));
                    *reinterpret_cast<__half2*>(&Ch[(size_t)row * ldc + col]) =
                        __floats2half2_rn(v0, v1);
                }
            }
        }
    }
}

// ---------------------------------------------------------------------------
// FP16 AV GEMM: O = P[Nn x Nn] @ V via V^T [HD x Nn] NT. BM=128, BN=96.
// Epilogue: fp16 store at attn-output layout (bz=b*8+h -> C[b][row][h*96+col]).
// ---------------------------------------------------------------------------
__global__ __launch_bounds__(256, 2)
void mma_gemm_avh(const __half* __restrict__ A, const __half* __restrict__ Bm,
                  __half* __restrict__ Cm,
                  int K, int lda, int ldb, int ldc,
                  size_t strideA, size_t strideB)
{
    constexpr int BM = 128, BN = 96, BK = 32;
    constexpr int ROWB = 80;
    constexpr int ASZB = BM * ROWB;
    constexpr int BSZB = BN * ROWB;
    constexpr int MFRAG = 2;
    constexpr int NFRAG = 6;                  // warp tile 32 x 48

    extern __shared__ char smem_c[];
    char* As = smem_c;
    char* Bs = smem_c + 2 * ASZB;

    int bz = blockIdx.z;
    A  += strideA * bz;
    Bm += strideB * bz;

    int m0 = blockIdx.y * BM;
    int n0 = blockIdx.x * BN;
    int t    = threadIdx.x;
    int warp = t >> 5, lane = t & 31;
    int wm0 = (warp & 3) * 32;
    int wn0 = (warp >> 2) * 48;

    float acc[MFRAG][NFRAG][4];
    #pragma unroll
    for (int i = 0; i < MFRAG; i++)
        #pragma unroll
        for (int j = 0; j < NFRAG; j++)
            #pragma unroll
            for (int e = 0; e < 4; e++) acc[i][j][e] = 0.f;

    int arow  = lane & 15;
    int ahalf = lane >> 4;
    int brow  = (lane & 7) + ((lane >> 4) & 1) * 8;
    int bhalf = (lane >> 3) & 1;

    auto load_stage = [&](int st, int kk) {
        char* Asd = As + st * ASZB;
        char* Bsd = Bs + st * BSZB;
        #pragma unroll
        for (int v = 0; v < 2; v++) {
            int idx = t + v * 256;
            int r = idx >> 2, g = idx & 3;
            cp_async16(smem_u32(Asd + r * ROWB + g * 16),
                       A + (size_t)(m0 + r) * lda + kk + g * 8);
        }
        #pragma unroll
        for (int v = 0; v < 2; v++) {
            int idx = t + v * 256;
            if (idx < 384) {
                int r = idx >> 2, g = idx & 3;
                cp_async16(smem_u32(Bsd + r * ROWB + g * 16),
                           Bm + (size_t)(n0 + r) * ldb + kk + g * 8);
            }
        }
    };

    int nIter = K / BK;
    load_stage(0, 0);
    cp_commit();

    for (int it = 0; it < nIter; ++it) {
        int s = it & 1;
        if (it + 1 < nIter) {
            load_stage(s ^ 1, (it + 1) * BK);
            cp_commit();
            cp_wait<1>();
        } else {
            cp_wait<0>();
        }
        __syncthreads();

        char* Asd = As + s * ASZB;
        char* Bsd = Bs + s * BSZB;
        #pragma unroll
        for (int ks = 0; ks < 2; ks++) {
            unsigned int afr[MFRAG][4];
            #pragma unroll
            for (int mf = 0; mf < MFRAG; mf++) {
                unsigned int addr = smem_u32(
                    Asd + (wm0 + mf * 16 + arow) * ROWB + (ks * 2 + ahalf) * 16);
                ldmatrix_x4(afr[mf], addr);
            }
            unsigned int bfr[NFRAG][2];
            #pragma unroll
            for (int np = 0; np < 3; np++) {
                unsigned int addr = smem_u32(
                    Bsd + (wn0 + np * 16 + brow) * ROWB + (ks * 2 + bhalf) * 16);
                ldmatrix_x4(&bfr[np * 2][0], addr);
            }
            #pragma unroll
            for (int mf = 0; mf < MFRAG; mf++)
                #pragma unroll
                for (int nf = 0; nf < NFRAG; nf++)
                    mma_f16(acc[mf][nf], afr[mf], bfr[nf]);
        }
        __syncthreads();
    }

    size_t out_off = (size_t)(bz >> 3) * ((size_t)Nn * Cc) + (size_t)(bz & 7) * HD;
    #pragma unroll
    for (int mf = 0; mf < MFRAG; mf++) {
        #pragma unroll
        for (int half_ = 0; half_ < 2; half_++) {
            int row = m0 + wm0 + mf * 16 + (lane >> 2) + half_ * 8;
            #pragma unroll
            for (int nf = 0; nf < NFRAG; nf++) {
                int col = n0 + wn0 + nf * 8 + (lane & 3) * 2;
                *reinterpret_cast<__half2*>(&Cm[out_off + (size_t)row * ldc + col]) =
                    __floats2half2_rn(acc[mf][nf][half_ * 2 + 0], acc[mf][nf][half_ * 2 + 1]);
            }
        }
    }
}

// ---------------------------------------------------------------------------
// fused per-row softmax (8 heads) + head mix + BN. fp32 scores -> fp16 probs.
// ---------------------------------------------------------------------------
__global__ void softmax_mix_kernel(const float* __restrict__ rw, const float* __restrict__ rb,
                                   const float* __restrict__ bng, const float* __restrict__ bnb)
{
    __shared__ __align__(16) float sp[8][1024];
    __shared__ float s_w[64];
    __shared__ float s_s[8], s_o[8];

    int bn = blockIdx.x;
    int b  = bn >> 10, n = bn & 1023;
    int t  = threadIdx.x;                    // 256

    if (t < 64) s_w[t] = rw[t];
    if (t < 8) {
        float bs = bng[t] * rsqrtf(1.0f + 1e-3f);
        s_s[t] = bs;
        s_o[t] = rb[t] * bs + bnb[t];
    }
    #pragma unroll
    for (int h = 0; h < 8; h++) {
        const float4* rp4 = reinterpret_cast<const float4*>(
            g_attn + (((size_t)b * Hh + h) * Nn + n) * Nn);
        reinterpret_cast<float4*>(sp[h])[t] = rp4[t];
    }
    __syncthreads();

    int w = t >> 5, lane = t & 31;
    {
        float* sr = sp[w];
        float mx = -1e30f;
        for (int m = lane; m < 1024; m += 32) mx = fmaxf(mx, sr[m]);
        #pragma unroll
        for (int off = 16; off; off >>= 1) mx = fmaxf(mx, __shfl_xor_sync(0xffffffffu, mx, off));
        float sum = 0.f;
        for (int m = lane; m < 1024; m += 32) {
            float e = __expf(sr[m] - mx);
            sr[m] = e;
            sum += e;
        }
        #pragma unroll
        for (int off = 16; off; off >>= 1) sum += __shfl_xor_sync(0xffffffffu, sum, off);
        float inv = 1.0f / sum;
        for (int m = lane; m < 1024; m += 32) sr[m] *= inv;
    }
    __syncthreads();

    float4 p[8];
    #pragma unroll
    for (int h = 0; h < 8; h++) p[h] = reinterpret_cast<const float4*>(sp[h])[t];
    #pragma unroll
    for (int g = 0; g < 8; g++) {
        float4 a = make_float4(0.f, 0.f, 0.f, 0.f);
        #pragma unroll
        for (int h = 0; h < 8; h++) {
            float wgh = s_w[g * 8 + h];
            a.x = fmaf(p[h].x, wgh, a.x);
            a.y = fmaf(p[h].y, wgh, a.y);
            a.z = fmaf(p[h].z, wgh, a.z);
            a.w = fmaf(p[h].w, wgh, a.w);
        }
        float ss = s_s[g], oo = s_o[g];
        a.x = a.x * ss + oo; a.y = a.y * ss + oo;
        a.z = a.z * ss + oo; a.w = a.w * ss + oo;
        __half2 p0 = __floats2half2_rn(a.x, a.y);
        __half2 p1 = __floats2half2_rn(a.z, a.w);
        uint2 packed;
        packed.x = *reinterpret_cast<unsigned int*>(&p0);
        packed.y = *reinterpret_cast<unsigned int*>(&p1);
        reinterpret_cast<uint2*>(
            g_ph + (((size_t)b * Hh + g) * Nn + n) * Nn)[t] = packed;
    }
}

// ---------------------------------------------------------------------------
// LayerNorm over 768. Writes fp32 out; optionally also fp16 copy.
// ---------------------------------------------------------------------------
__global__ void layernorm_kernel(const float* __restrict__ in, float* __restrict__ out,
                                 __half* __restrict__ out16,
                                 const float* __restrict__ g, const float* __restrict__ bta)
{
    __shared__ float red[16];
    __shared__ float s_mu, s_rs;
    int row = blockIdx.x;
    int t   = threadIdx.x;       // 256
    const float* rp = in + (size_t)row * Cc;
    float x0 = rp[t], x1 = rp[t + 256], x2 = rp[t + 512];
    float s  = x0 + x1 + x2;
    float ss = x0 * x0 + x1 * x1 + x2 * x2;
    #pragma unroll
    for (int off = 16; off; off >>= 1) {
        s  += __shfl_xor_sync(0xffffffffu, s, off);
        ss += __shfl_xor_sync(0xffffffffu, ss, off);
    }
    int w = t >> 5, lane = t & 31;
    if (lane == 0) { red[w] = s; red[8 + w] = ss; }
    __syncthreads();
    if (t == 0) {
        float S = 0.f, SS = 0.f;
        #pragma unroll
        for (int i = 0; i < 8; i++) { S += red[i]; SS += red[8 + i]; }
        float mu  = S * (1.0f / 768.0f);
        float var = SS * (1.0f / 768.0f) - mu * mu;
        s_mu = mu;
        s_rs = rsqrtf(var + 1e-3f);
    }
    __syncthreads();
    float mu = s_mu, rs = s_rs;
    float v0 = (x0 - mu) * rs * g[t]       + bta[t];
    float v1 = (x1 - mu) * rs * g[t + 256] + bta[t + 256];
    float v2 = (x2 - mu) * rs * g[t + 512] + bta[t + 512];
    float* op = out + (size_t)row * Cc;
    op[t] = v0; op[t + 256] = v1; op[t + 512] = v2;
    if (out16) {
        __half* oh = out16 + (size_t)row * Cc;
        oh[t] = __float2half(v0);
        oh[t + 256] = __float2half(v1);
        oh[t + 512] = __float2half(v2);
    }
}

// ---------------------------------------------------------------------------
// Host-side launch helpers
// ---------------------------------------------------------------------------
#define SMEM_H   (2 * (128 * 80 + 128 * 80))   // 40960 B
#define SMEM_AVH (2 * (128 * 80 + 96 * 80))    // 35840 B

static void launch_scores(const __half* qh, float* ap, float scale)
{
    static bool init = false;
    if (!init) {
        cudaFuncSetAttribute((const void*)mma_gemm_h<0>,
                             cudaFuncAttributeMaxDynamicSharedMemorySize, SMEM_H);
        init = true;
    }
    mma_gemm_h<0><<<dim3(8, 8, 64), 256, SMEM_H>>>(
        qh, qh, ap, HD, HD, HD, Nn,
        (size_t)Nn * HD, (size_t)Nn * HD, (size_t)Nn * Nn,
        nullptr, nullptr, 0, scale);
}
static void launch_av(const __half* ph, const __half* vt, __half* xh)
{
    mma_gemm_avh<<<dim3(1, 8, 64), 256, SMEM_AVH>>>(
        ph, vt, xh, Nn, Nn, Nn, Cc,
        (size_t)Nn * Nn, (size_t)Nn * HD);
}
static void launch_proj(const __half* xh, const __half* wt, float* yp,
                        const float* b, const float* res)
{
    static bool init = false;
    if (!init) {
        cudaFuncSetAttribute((const void*)mma_gemm_h<1>,
                             cudaFuncAttributeMaxDynamicSharedMemorySize, SMEM_H);
        init = true;
    }
    mma_gemm_h<1><<<dim3(6, 64, 1), 256, SMEM_H>>>(
        xh, wt, yp, Cc, Cc, Cc, Cc,
        0, 0, 0, b, res, Cc, 1.0f);
}
static void launch_ffn1(const __half* yh, const __half* wt, __half* hh, const float* b)
{
    static bool init = false;
    if (!init) {
        cudaFuncSetAttribute((const void*)mma_gemm_h<2>,
                             cudaFuncAttributeMaxDynamicSharedMemorySize, SMEM_H);
        init = true;
    }
    mma_gemm_h<2><<<dim3(24, 64, 1), 256, SMEM_H>>>(
        yh, wt, hh, Cc, Cc, Cc, DFF,
        0, 0, 0, b, nullptr, 0, 1.0f);
}
static void launch_ffn2(const __half* hh, const __half* wt, float* xp,
                        const float* b, const float* res)
{
    mma_gemm_h<1><<<dim3(6, 64, 1), 256, SMEM_H>>>(
        hh, wt, xp, DFF, DFF, DFF, Cc,
        0, 0, 0, b, res, Cc, 1.0f);
}

// ---------------------------------------------------------------------------
// Launch
// ---------------------------------------------------------------------------
extern "C" void kernel_launch(void* const* d_in, const int* in_sizes, int n_in,
                              void* d_out, int out_size)
{
    (void)in_sizes; (void)n_in; (void)out_size;
    const float* enc       = (const float*)d_in[0];
    const float* qconv_w   = (const float*)d_in[1];
    const float* reatten_w = (const float*)d_in[2];
    const float* reatten_b = (const float*)d_in[3];
    const float* bn_gamma  = (const float*)d_in[4];
    const float* bn_beta   = (const float*)d_in[5];
    const float* proj_w    = (const float*)d_in[6];
    const float* proj_b    = (const float*)d_in[7];
    const float* ffn_w1    = (const float*)d_in[8];
    const float* ffn_b1    = (const float*)d_in[9];
    const float* ffn_w2    = (const float*)d_in[10];
    const float* ffn_b2    = (const float*)d_in[11];
    const float* ln1_g     = (const float*)d_in[12];
    const float* ln1_b     = (const float*)d_in[13];
    const float* ln2_g     = (const float*)d_in[14];
    const float* ln2_b     = (const float*)d_in[15];
    float* out = (float*)d_out;

    float *ap, *yp, *xp;
    __half *qh, *vtp, *ph, *xh, *yh, *hh, *pwt, *w1t, *w2t;
    cudaGetSymbolAddress((void**)&qh,  g_qh);
    cudaGetSymbolAddress((void**)&vtp, g_vt);
    cudaGetSymbolAddress((void**)&ap,  g_attn);
    cudaGetSymbolAddress((void**)&ph,  g_ph);
    cudaGetSymbolAddress((void**)&xh,  g_xh);
    cudaGetSymbolAddress((void**)&yp,  g_y);
    cudaGetSymbolAddress((void**)&yh,  g_yh);
    cudaGetSymbolAddress((void**)&hh,  g_hh);
    cudaGetSymbolAddress((void**)&xp,  g_x);
    cudaGetSymbolAddress((void**)&pwt, g_pwt);
    cudaGetSymbolAddress((void**)&w1t, g_w1t);
    cudaGetSymbolAddress((void**)&w2t, g_w2t);

    const float scale = 0.1020620726159658f;   // 96^-0.5

    // weight transposes ([K][N] fp32 -> [N][K] fp16)
    transpose_f2h_kernel<<<dim3(24, 24, 1), dim3(32, 8)>>>(proj_w, pwt, Cc, Cc, 0, 0);
    transpose_f2h_kernel<<<dim3(96, 24, 1), dim3(32, 8)>>>(ffn_w1, w1t, Cc, DFF, 0, 0);
    transpose_f2h_kernel<<<dim3(24, 96, 1), dim3(32, 8)>>>(ffn_w2, w2t, DFF, Cc, 0, 0);

    qconv_kernel<<<NT_, 256>>>(enc, qconv_w);
    // V^T per (b,h): [1024][96] -> [96][1024] fp16
    transpose_h2h_kernel<<<dim3(3, 32, 64), dim3(32, 8)>>>(qh, vtp, Nn, HD,
                                                           (size_t)Nn * HD, (size_t)Nn * HD);

    launch_scores(qh, ap, scale);
    softmax_mix_kernel<<<NT_, 256>>>(reatten_w, reatten_b, bn_gamma, bn_beta);
    launch_av(ph, vtp, xh);
    launch_proj(xh, pwt, yp, proj_b, enc);
    layernorm_kernel<<<NT_, 256>>>(yp, yp, yh, ln1_g, ln1_b);
    launch_ffn1(yh, w1t, hh, ffn_b1);
    launch_ffn2(hh, w2t, xp, ffn_b2, yp);
    layernorm_kernel<<<NT_, 256>>>(xp, out, nullptr, ln2_g, ln2_b);
}

// round 13
// speedup vs baseline: 1.7405x; 1.0104x over previous
#include <cuda_runtime.h>
#include <cuda_bf16.h>
#include <cuda_fp16.h>
#include <cstdint>
#include <math.h>

// Problem constants
#define Bb   8
#define Nn   1024
#define Cc   768
#define Hh   8
#define HD   96
#define DFF  3072
#define NT_  (Bb * Nn)          // 8192 tokens

// ---------------------------------------------------------------------------
// Scratch (device globals — no allocation allowed)
// ---------------------------------------------------------------------------
__device__ __half g_qh[(size_t)Bb * Hh * Nn * HD];         // q fp16 [b][h][n][d]
__device__ __half g_vt[(size_t)Bb * Hh * HD * Nn];         // V^T fp16 [b][h][d][n]
__device__ __half g_attn[(size_t)Bb * Hh * Nn * Nn];       // scores fp16
__device__ __half g_ph[(size_t)Bb * Hh * Nn * Nn];         // probs fp16
__device__ __half g_xh[(size_t)NT_ * Cc];                  // attn-out fp16 (proj A)
__device__ float  g_y[(size_t)NT_ * Cc];                   // LN1 out fp32 (residual)
__device__ __half g_yh[(size_t)NT_ * Cc];                  // LN1 out fp16 (ffn1 A)
__device__ __half g_hh[(size_t)NT_ * DFF];                 // ffn hidden fp16
__device__ float  g_x[(size_t)NT_ * Cc];                   // proj-out / ffn2-out fp32
__device__ __half g_pwt[(size_t)Cc * Cc];                  // proj_w^T fp16
__device__ __half g_w1t[(size_t)DFF * Cc];                 // ffn_w1^T fp16
__device__ __half g_w2t[(size_t)Cc * DFF];                 // ffn_w2^T fp16

// ---------------------------------------------------------------------------
// helpers
// ---------------------------------------------------------------------------
__device__ __forceinline__ unsigned int smem_u32(const void* p) {
    return (unsigned int)__cvta_generic_to_shared(p);
}
__device__ __forceinline__ void cp_async16(unsigned int dst, const void* src) {
    asm volatile("cp.async.ca.shared.global [%0], [%1], 16;\n" :: "r"(dst), "l"(src));
}
__device__ __forceinline__ void cp_commit() {
    asm volatile("cp.async.commit_group;\n");
}
template<int N>
__device__ __forceinline__ void cp_wait() {
    asm volatile("cp.async.wait_group %0;\n" :: "n"(N));
}
__device__ __forceinline__ void ldmatrix_x4(unsigned int* r, unsigned int addr) {
    asm volatile("ldmatrix.sync.aligned.m8n8.x4.shared.b16 {%0,%1,%2,%3}, [%4];"
                 : "=r"(r[0]), "=r"(r[1]), "=r"(r[2]), "=r"(r[3]) : "r"(addr));
}
__device__ __forceinline__ void mma_f16(float* c, const unsigned int* a, const unsigned int* b) {
    asm volatile(
        "mma.sync.aligned.m16n8k16.row.col.f32.f16.f16.f32 "
        "{%0,%1,%2,%3}, {%4,%5,%6,%7}, {%8,%9}, {%0,%1,%2,%3};"
        : "+f"(c[0]), "+f"(c[1]), "+f"(c[2]), "+f"(c[3])
        : "r"(a[0]), "r"(a[1]), "r"(a[2]), "r"(a[3]), "r"(b[0]), "r"(b[1]));
}

// ---------------------------------------------------------------------------
// Kernel 1: per-patch 3x3 conv, q=k=v, write fp16 [b][h][n][d]
// ---------------------------------------------------------------------------
__global__ void qconv_kernel(const float* __restrict__ x, const float* __restrict__ w)
{
    __shared__ float s_in[768];
    __shared__ float s_w[81];
    int bn = blockIdx.x;
    int b  = bn >> 10, n = bn & 1023;
    int t  = threadIdx.x;                // 256
    const float* xin = x + (size_t)bn * 768;
    s_in[t]       = xin[t];
    s_in[t + 256] = xin[t + 256];
    s_in[t + 512] = xin[t + 512];
    if (t < 81) s_w[t] = w[t];
    __syncthreads();

    int r = t >> 4, c = t & 15;
    float acc0 = 0.f, acc1 = 0.f, acc2 = 0.f;
    #pragma unroll
    for (int kh = 0; kh < 3; kh++) {
        int rr = r + kh - 1;
        if (rr < 0 || rr > 15) continue;
        #pragma unroll
        for (int kw = 0; kw < 3; kw++) {
            int cc = c + kw - 1;
            if (cc < 0 || cc > 15) continue;
            const float* wp = s_w + (kh * 3 + kw) * 9;
            int ip = (rr * 16 + cc) * 3;
            #pragma unroll
            for (int ci = 0; ci < 3; ci++) {
                float v = s_in[ip + ci];
                acc0 += v * wp[ci * 3 + 0];
                acc1 += v * wp[ci * 3 + 1];
                acc2 += v * wp[ci * 3 + 2];
            }
        }
    }
    float accs[3] = {acc0, acc1, acc2};
    #pragma unroll
    for (int co = 0; co < 3; co++) {
        int cidx = t * 3 + co;
        int h = cidx / HD, d = cidx % HD;
        g_qh[(((size_t)b * Hh + h) * Nn + n) * HD + d] = __float2half(accs[co]);
    }
}

// ---------------------------------------------------------------------------
// Transpose fp32 -> fp16: in[z][R][C] fp32 -> out[z][C][R] fp16. Block (32,8).
// ---------------------------------------------------------------------------
__global__ void transpose_f2h_kernel(const float* __restrict__ in,
                                     __half* __restrict__ out,
                                     int R, int C, size_t sIn, size_t sOut)
{
    __shared__ float tile[32][33];
    int z = blockIdx.z;
    const float* ip = in + (size_t)z * sIn;
    __half* op = out + (size_t)z * sOut;
    int c0 = blockIdx.x * 32, r0 = blockIdx.y * 32;
    int tx = threadIdx.x, ty = threadIdx.y;
    #pragma unroll
    for (int j = 0; j < 4; j++)
        tile[ty + 8 * j][tx] = ip[(size_t)(r0 + ty + 8 * j) * C + c0 + tx];
    __syncthreads();
    #pragma unroll
    for (int j = 0; j < 4; j++)
        op[(size_t)(c0 + ty + 8 * j) * R + r0 + tx] = __float2half(tile[tx][ty + 8 * j]);
}

// ---------------------------------------------------------------------------
// Transpose fp16 -> fp16: in[z][R][C] -> out[z][C][R]. (for V^T from g_qh)
// ---------------------------------------------------------------------------
__global__ void transpose_h2h_kernel(const __half* __restrict__ in,
                                     __half* __restrict__ out,
                                     int R, int C, size_t sIn, size_t sOut)
{
    __shared__ float tile[32][33];
    int z = blockIdx.z;
    const __half* ip = in + (size_t)z * sIn;
    __half* op = out + (size_t)z * sOut;
    int c0 = blockIdx.x * 32, r0 = blockIdx.y * 32;
    int tx = threadIdx.x, ty = threadIdx.y;
    #pragma unroll
    for (int j = 0; j < 4; j++)
        tile[ty + 8 * j][tx] = __half2float(ip[(size_t)(r0 + ty + 8 * j) * C + c0 + tx]);
    __syncthreads();
    #pragma unroll
    for (int j = 0; j < 4; j++)
        op[(size_t)(c0 + ty + 8 * j) * R + r0 + tx] = __float2half(tile[tx][ty + 8 * j]);
}

// ---------------------------------------------------------------------------
// FP16 tensor-core GEMM (NT: A [M][K], B [N][K], both fp16 row-major).
// mma.m16n8k16, fp32 accum. BM=BN=128, BK=32, 80B padded smem rows.
// MODE 0: fp16 C = acc*scale | MODE 1: fp32 C = acc+bias+res | MODE 2: fp16 gelu
// ---------------------------------------------------------------------------
template<int MODE>
__global__ __launch_bounds__(256, 2)
void mma_gemm_h(const __half* __restrict__ A, const __half* __restrict__ Bm,
                void* __restrict__ Cv,
                int K, int lda, int ldb, int ldc,
                size_t strideA, size_t strideB, size_t strideC,
                const float* __restrict__ bias, const float* __restrict__ res,
                int ldres, float scale)
{
    constexpr int BM = 128, BN = 128, BK = 32;
    constexpr int ROWB = 80;
    constexpr int ASZB = BM * ROWB;
    constexpr int BSZB = BN * ROWB;
    constexpr int MFRAG = 2;
    constexpr int NFRAG = 8;

    extern __shared__ char smem_c[];
    char* As = smem_c;
    char* Bs = smem_c + 2 * ASZB;

    int bz = blockIdx.z;
    A  += strideA * bz;
    Bm += strideB * bz;

    int m0 = blockIdx.y * BM;
    int n0 = blockIdx.x * BN;
    int t    = threadIdx.x;
    int warp = t >> 5, lane = t & 31;
    int wm0 = (warp & 3) * 32;
    int wn0 = (warp >> 2) * 64;

    float acc[MFRAG][NFRAG][4];
    #pragma unroll
    for (int i = 0; i < MFRAG; i++)
        #pragma unroll
        for (int j = 0; j < NFRAG; j++)
            #pragma unroll
            for (int e = 0; e < 4; e++) acc[i][j][e] = 0.f;

    int arow  = lane & 15;
    int ahalf = lane >> 4;
    int brow  = (lane & 7) + ((lane >> 4) & 1) * 8;
    int bhalf = (lane >> 3) & 1;

    auto load_stage = [&](int st, int kk) {
        char* Asd = As + st * ASZB;
        char* Bsd = Bs + st * BSZB;
        #pragma unroll
        for (int v = 0; v < 2; v++) {
            int idx = t + v * 256;
            int r = idx >> 2, g = idx & 3;
            cp_async16(smem_u32(Asd + r * ROWB + g * 16),
                       A + (size_t)(m0 + r) * lda + kk + g * 8);
        }
        #pragma unroll
        for (int v = 0; v < 2; v++) {
            int idx = t + v * 256;
            int r = idx >> 2, g = idx & 3;
            cp_async16(smem_u32(Bsd + r * ROWB + g * 16),
                       Bm + (size_t)(n0 + r) * ldb + kk + g * 8);
        }
    };

    int nIter = K / BK;
    load_stage(0, 0);
    cp_commit();

    for (int it = 0; it < nIter; ++it) {
        int s = it & 1;
        if (it + 1 < nIter) {
            load_stage(s ^ 1, (it + 1) * BK);
            cp_commit();
            cp_wait<1>();
        } else {
            cp_wait<0>();
        }
        __syncthreads();

        char* Asd = As + s * ASZB;
        char* Bsd = Bs + s * BSZB;
        #pragma unroll
        for (int ks = 0; ks < 2; ks++) {
            unsigned int afr[MFRAG][4];
            #pragma unroll
            for (int mf = 0; mf < MFRAG; mf++) {
                unsigned int addr = smem_u32(
                    Asd + (wm0 + mf * 16 + arow) * ROWB + (ks * 2 + ahalf) * 16);
                ldmatrix_x4(afr[mf], addr);
            }
            unsigned int bfr[NFRAG][2];
            #pragma unroll
            for (int np = 0; np < 4; np++) {
                unsigned int addr = smem_u32(
                    Bsd + (wn0 + np * 16 + brow) * ROWB + (ks * 2 + bhalf) * 16);
                ldmatrix_x4(&bfr[np * 2][0], addr);
            }
            #pragma unroll
            for (int mf = 0; mf < MFRAG; mf++)
                #pragma unroll
                for (int nf = 0; nf < NFRAG; nf++)
                    mma_f16(acc[mf][nf], afr[mf], bfr[nf]);
        }
        __syncthreads();
    }

    // ---- epilogue
    float* Cf = (float*)Cv;
    __half* Ch = (__half*)Cv;
    if (MODE == 0) Ch += strideC * bz;
    if (MODE == 1) Cf += strideC * bz;

    #pragma unroll
    for (int mf = 0; mf < MFRAG; mf++) {
        #pragma unroll
        for (int half_ = 0; half_ < 2; half_++) {
            int row = m0 + wm0 + mf * 16 + (lane >> 2) + half_ * 8;
            #pragma unroll
            for (int nf = 0; nf < NFRAG; nf++) {
                int col = n0 + wn0 + nf * 8 + (lane & 3) * 2;
                float v0 = acc[mf][nf][half_ * 2 + 0];
                float v1 = acc[mf][nf][half_ * 2 + 1];
                if constexpr (MODE == 0) {
                    *reinterpret_cast<__half2*>(&Ch[(size_t)row * ldc + col]) =
                        __floats2half2_rn(v0 * scale, v1 * scale);
                } else if constexpr (MODE == 1) {
                    float2 bb = *reinterpret_cast<const float2*>(&bias[col]);
                    float2 rr = *reinterpret_cast<const float2*>(&res[(size_t)row * ldres + col]);
                    *reinterpret_cast<float2*>(&Cf[(size_t)row * ldc + col]) =
                        make_float2(v0 + bb.x + rr.x, v1 + bb.y + rr.y);
                } else {
                    float2 bb = *reinterpret_cast<const float2*>(&bias[col]);
                    v0 += bb.x; v1 += bb.y;
                    v0 = 0.5f * v0 * (1.0f + erff(v0 * 0.70710678118654752f));
                    v1 = 0.5f * v1 * (1.0f + erff(v1 * 0.70710678118654752f));
                    *reinterpret_cast<__half2*>(&Ch[(size_t)row * ldc + col]) =
                        __floats2half2_rn(v0, v1);
                }
            }
        }
    }
}

// ---------------------------------------------------------------------------
// FP16 AV GEMM: O = P[Nn x Nn] @ V via V^T [HD x Nn] NT. BM=128, BN=96.
// ---------------------------------------------------------------------------
__global__ __launch_bounds__(256, 2)
void mma_gemm_avh(const __half* __restrict__ A, const __half* __restrict__ Bm,
                  __half* __restrict__ Cm,
                  int K, int lda, int ldb, int ldc,
                  size_t strideA, size_t strideB)
{
    constexpr int BM = 128, BN = 96, BK = 32;
    constexpr int ROWB = 80;
    constexpr int ASZB = BM * ROWB;
    constexpr int BSZB = BN * ROWB;
    constexpr int MFRAG = 2;
    constexpr int NFRAG = 6;

    extern __shared__ char smem_c[];
    char* As = smem_c;
    char* Bs = smem_c + 2 * ASZB;

    int bz = blockIdx.z;
    A  += strideA * bz;
    Bm += strideB * bz;

    int m0 = blockIdx.y * BM;
    int n0 = blockIdx.x * BN;
    int t    = threadIdx.x;
    int warp = t >> 5, lane = t & 31;
    int wm0 = (warp & 3) * 32;
    int wn0 = (warp >> 2) * 48;

    float acc[MFRAG][NFRAG][4];
    #pragma unroll
    for (int i = 0; i < MFRAG; i++)
        #pragma unroll
        for (int j = 0; j < NFRAG; j++)
            #pragma unroll
            for (int e = 0; e < 4; e++) acc[i][j][e] = 0.f;

    int arow  = lane & 15;
    int ahalf = lane >> 4;
    int brow  = (lane & 7) + ((lane >> 4) & 1) * 8;
    int bhalf = (lane >> 3) & 1;

    auto load_stage = [&](int st, int kk) {
        char* Asd = As + st * ASZB;
        char* Bsd = Bs + st * BSZB;
        #pragma unroll
        for (int v = 0; v < 2; v++) {
            int idx = t + v * 256;
            int r = idx >> 2, g = idx & 3;
            cp_async16(smem_u32(Asd + r * ROWB + g * 16),
                       A + (size_t)(m0 + r) * lda + kk + g * 8);
        }
        #pragma unroll
        for (int v = 0; v < 2; v++) {
            int idx = t + v * 256;
            if (idx < 384) {
                int r = idx >> 2, g = idx & 3;
                cp_async16(smem_u32(Bsd + r * ROWB + g * 16),
                           Bm + (size_t)(n0 + r) * ldb + kk + g * 8);
            }
        }
    };

    int nIter = K / BK;
    load_stage(0, 0);
    cp_commit();

    for (int it = 0; it < nIter; ++it) {
        int s = it & 1;
        if (it + 1 < nIter) {
            load_stage(s ^ 1, (it + 1) * BK);
            cp_commit();
            cp_wait<1>();
        } else {
            cp_wait<0>();
        }
        __syncthreads();

        char* Asd = As + s * ASZB;
        char* Bsd = Bs + s * BSZB;
        #pragma unroll
        for (int ks = 0; ks < 2; ks++) {
            unsigned int afr[MFRAG][4];
            #pragma unroll
            for (int mf = 0; mf < MFRAG; mf++) {
                unsigned int addr = smem_u32(
                    Asd + (wm0 + mf * 16 + arow) * ROWB + (ks * 2 + ahalf) * 16);
                ldmatrix_x4(afr[mf], addr);
            }
            unsigned int bfr[NFRAG][2];
            #pragma unroll
            for (int np = 0; np < 3; np++) {
                unsigned int addr = smem_u32(
                    Bsd + (wn0 + np * 16 + brow) * ROWB + (ks * 2 + bhalf) * 16);
                ldmatrix_x4(&bfr[np * 2][0], addr);
            }
            #pragma unroll
            for (int mf = 0; mf < MFRAG; mf++)
                #pragma unroll
                for (int nf = 0; nf < NFRAG; nf++)
                    mma_f16(acc[mf][nf], afr[mf], bfr[nf]);
        }
        __syncthreads();
    }

    size_t out_off = (size_t)(bz >> 3) * ((size_t)Nn * Cc) + (size_t)(bz & 7) * HD;
    #pragma unroll
    for (int mf = 0; mf < MFRAG; mf++) {
        #pragma unroll
        for (int half_ = 0; half_ < 2; half_++) {
            int row = m0 + wm0 + mf * 16 + (lane >> 2) + half_ * 8;
            #pragma unroll
            for (int nf = 0; nf < NFRAG; nf++) {
                int col = n0 + wn0 + nf * 8 + (lane & 3) * 2;
                *reinterpret_cast<__half2*>(&Cm[out_off + (size_t)row * ldc + col]) =
                    __floats2half2_rn(acc[mf][nf][half_ * 2 + 0], acc[mf][nf][half_ * 2 + 1]);
            }
        }
    }
}

// ---------------------------------------------------------------------------
// fused per-row softmax (8 heads) + head mix + BN. fp16 scores -> fp16 probs.
// ---------------------------------------------------------------------------
__global__ void softmax_mix_kernel(const float* __restrict__ rw, const float* __restrict__ rb,
                                   const float* __restrict__ bng, const float* __restrict__ bnb)
{
    __shared__ __align__(16) float sp[8][1024];
    __shared__ float s_w[64];
    __shared__ float s_s[8], s_o[8];

    int bn = blockIdx.x;
    int b  = bn >> 10, n = bn & 1023;
    int t  = threadIdx.x;                    // 256

    if (t < 64) s_w[t] = rw[t];
    if (t < 8) {
        float bs = bng[t] * rsqrtf(1.0f + 1e-3f);
        s_s[t] = bs;
        s_o[t] = rb[t] * bs + bnb[t];
    }
    #pragma unroll
    for (int h = 0; h < 8; h++) {
        uint2 raw = reinterpret_cast<const uint2*>(
            g_attn + (((size_t)b * Hh + h) * Nn + n) * Nn)[t];
        __half2 h0 = *reinterpret_cast<__half2*>(&raw.x);
        __half2 h1 = *reinterpret_cast<__half2*>(&raw.y);
        float2 f0 = __half22float2(h0);
        float2 f1 = __half22float2(h1);
        reinterpret_cast<float4*>(sp[h])[t] = make_float4(f0.x, f0.y, f1.x, f1.y);
    }
    __syncthreads();

    int w = t >> 5, lane = t & 31;
    {
        float* sr = sp[w];
        float mx = -1e30f;
        for (int m = lane; m < 1024; m += 32) mx = fmaxf(mx, sr[m]);
        #pragma unroll
        for (int off = 16; off; off >>= 1) mx = fmaxf(mx, __shfl_xor_sync(0xffffffffu, mx, off));
        float sum = 0.f;
        for (int m = lane; m < 1024; m += 32) {
            float e = __expf(sr[m] - mx);
            sr[m] = e;
            sum += e;
        }
        #pragma unroll
        for (int off = 16; off; off >>= 1) sum += __shfl_xor_sync(0xffffffffu, sum, off);
        float inv = 1.0f / sum;
        for (int m = lane; m < 1024; m += 32) sr[m] *= inv;
    }
    __syncthreads();

    float4 p[8];
    #pragma unroll
    for (int h = 0; h < 8; h++) p[h] = reinterpret_cast<const float4*>(sp[h])[t];
    #pragma unroll
    for (int g = 0; g < 8; g++) {
        float4 a = make_float4(0.f, 0.f, 0.f, 0.f);
        #pragma unroll
        for (int h = 0; h < 8; h++) {
            float wgh = s_w[g * 8 + h];
            a.x = fmaf(p[h].x, wgh, a.x);
            a.y = fmaf(p[h].y, wgh, a.y);
            a.z = fmaf(p[h].z, wgh, a.z);
            a.w = fmaf(p[h].w, wgh, a.w);
        }
        float ss = s_s[g], oo = s_o[g];
        a.x = a.x * ss + oo; a.y = a.y * ss + oo;
        a.z = a.z * ss + oo; a.w = a.w * ss + oo;
        __half2 p0 = __floats2half2_rn(a.x, a.y);
        __half2 p1 = __floats2half2_rn(a.z, a.w);
        uint2 packed;
        packed.x = *reinterpret_cast<unsigned int*>(&p0);
        packed.y = *reinterpret_cast<unsigned int*>(&p1);
        reinterpret_cast<uint2*>(
            g_ph + (((size_t)b * Hh + g) * Nn + n) * Nn)[t] = packed;
    }
}

// ---------------------------------------------------------------------------
// LayerNorm over 768. Writes fp32 out; optionally also fp16 copy.
// ---------------------------------------------------------------------------
__global__ void layernorm_kernel(const float* __restrict__ in, float* __restrict__ out,
                                 __half* __restrict__ out16,
                                 const float* __restrict__ g, const float* __restrict__ bta)
{
    __shared__ float red[16];
    __shared__ float s_mu, s_rs;
    int row = blockIdx.x;
    int t   = threadIdx.x;       // 256
    const float* rp = in + (size_t)row * Cc;
    float x0 = rp[t], x1 = rp[t + 256], x2 = rp[t + 512];
    float s  = x0 + x1 + x2;
    float ss = x0 * x0 + x1 * x1 + x2 * x2;
    #pragma unroll
    for (int off = 16; off; off >>= 1) {
        s  += __shfl_xor_sync(0xffffffffu, s, off);
        ss += __shfl_xor_sync(0xffffffffu, ss, off);
    }
    int w = t >> 5, lane = t & 31;
    if (lane == 0) { red[w] = s; red[8 + w] = ss; }
    __syncthreads();
    if (t == 0) {
        float S = 0.f, SS = 0.f;
        #pragma unroll
        for (int i = 0; i < 8; i++) { S += red[i]; SS += red[8 + i]; }
        float mu  = S * (1.0f / 768.0f);
        float var = SS * (1.0f / 768.0f) - mu * mu;
        s_mu = mu;
        s_rs = rsqrtf(var + 1e-3f);
    }
    __syncthreads();
    float mu = s_mu, rs = s_rs;
    float v0 = (x0 - mu) * rs * g[t]       + bta[t];
    float v1 = (x1 - mu) * rs * g[t + 256] + bta[t + 256];
    float v2 = (x2 - mu) * rs * g[t + 512] + bta[t + 512];
    float* op = out + (size_t)row * Cc;
    op[t] = v0; op[t + 256] = v1; op[t + 512] = v2;
    if (out16) {
        __half* oh = out16 + (size_t)row * Cc;
        oh[t] = __float2half(v0);
        oh[t + 256] = __float2half(v1);
        oh[t + 512] = __float2half(v2);
    }
}

// ---------------------------------------------------------------------------
// Host-side launch helpers
// ---------------------------------------------------------------------------
#define SMEM_H   (2 * (128 * 80 + 128 * 80))   // 40960 B
#define SMEM_AVH (2 * (128 * 80 + 96 * 80))    // 35840 B

static void launch_scores(const __half* qh, __half* ap, float scale)
{
    static bool init = false;
    if (!init) {
        cudaFuncSetAttribute((const void*)mma_gemm_h<0>,
                             cudaFuncAttributeMaxDynamicSharedMemorySize, SMEM_H);
        init = true;
    }
    mma_gemm_h<0><<<dim3(8, 8, 64), 256, SMEM_H>>>(
        qh, qh, ap, HD, HD, HD, Nn,
        (size_t)Nn * HD, (size_t)Nn * HD, (size_t)Nn * Nn,
        nullptr, nullptr, 0, scale);
}
static void launch_av(const __half* ph, const __half* vt, __half* xh)
{
    mma_gemm_avh<<<dim3(1, 8, 64), 256, SMEM_AVH>>>(
        ph, vt, xh, Nn, Nn, Nn, Cc,
        (size_t)Nn * Nn, (size_t)Nn * HD);
}
static void launch_proj(const __half* xh, const __half* wt, float* yp,
                        const float* b, const float* res)
{
    static bool init = false;
    if (!init) {
        cudaFuncSetAttribute((const void*)mma_gemm_h<1>,
                             cudaFuncAttributeMaxDynamicSharedMemorySize, SMEM_H);
        init = true;
    }
    mma_gemm_h<1><<<dim3(6, 64, 1), 256, SMEM_H>>>(
        xh, wt, yp, Cc, Cc, Cc, Cc,
        0, 0, 0, b, res, Cc, 1.0f);
}
static void launch_ffn1(const __half* yh, const __half* wt, __half* hh, const float* b)
{
    static bool init = false;
    if (!init) {
        cudaFuncSetAttribute((const void*)mma_gemm_h<2>,
                             cudaFuncAttributeMaxDynamicSharedMemorySize, SMEM_H);
        init = true;
    }
    mma_gemm_h<2><<<dim3(24, 64, 1), 256, SMEM_H>>>(
        yh, wt, hh, Cc, Cc, Cc, DFF,
        0, 0, 0, b, nullptr, 0, 1.0f);
}
static void launch_ffn2(const __half* hh, const __half* wt, float* xp,
                        const float* b, const float* res)
{
    mma_gemm_h<1><<<dim3(6, 64, 1), 256, SMEM_H>>>(
        hh, wt, xp, DFF, DFF, DFF, Cc,
        0, 0, 0, b, res, Cc, 1.0f);
}

// ---------------------------------------------------------------------------
// Launch
// ---------------------------------------------------------------------------
extern "C" void kernel_launch(void* const* d_in, const int* in_sizes, int n_in,
                              void* d_out, int out_size)
{
    (void)in_sizes; (void)n_in; (void)out_size;
    const float* enc       = (const float*)d_in[0];
    const float* qconv_w   = (const float*)d_in[1];
    const float* reatten_w = (const float*)d_in[2];
    const float* reatten_b = (const float*)d_in[3];
    const float* bn_gamma  = (const float*)d_in[4];
    const float* bn_beta   = (const float*)d_in[5];
    const float* proj_w    = (const float*)d_in[6];
    const float* proj_b    = (const float*)d_in[7];
    const float* ffn_w1    = (const float*)d_in[8];
    const float* ffn_b1    = (const float*)d_in[9];
    const float* ffn_w2    = (const float*)d_in[10];
    const float* ffn_b2    = (const float*)d_in[11];
    const float* ln1_g     = (const float*)d_in[12];
    const float* ln1_b     = (const float*)d_in[13];
    const float* ln2_g     = (const float*)d_in[14];
    const float* ln2_b     = (const float*)d_in[15];
    float* out = (float*)d_out;

    float *yp, *xp;
    __half *qh, *vtp, *ap, *ph, *xh, *yh, *hh, *pwt, *w1t, *w2t;
    cudaGetSymbolAddress((void**)&qh,  g_qh);
    cudaGetSymbolAddress((void**)&vtp, g_vt);
    cudaGetSymbolAddress((void**)&ap,  g_attn);
    cudaGetSymbolAddress((void**)&ph,  g_ph);
    cudaGetSymbolAddress((void**)&xh,  g_xh);
    cudaGetSymbolAddress((void**)&yp,  g_y);
    cudaGetSymbolAddress((void**)&yh,  g_yh);
    cudaGetSymbolAddress((void**)&hh,  g_hh);
    cudaGetSymbolAddress((void**)&xp,  g_x);
    cudaGetSymbolAddress((void**)&pwt, g_pwt);
    cudaGetSymbolAddress((void**)&w1t, g_w1t);
    cudaGetSymbolAddress((void**)&w2t, g_w2t);

    const float scale = 0.1020620726159658f;   // 96^-0.5

    // weight transposes ([K][N] fp32 -> [N][K] fp16)
    transpose_f2h_kernel<<<dim3(24, 24, 1), dim3(32, 8)>>>(proj_w, pwt, Cc, Cc, 0, 0);
    transpose_f2h_kernel<<<dim3(96, 24, 1), dim3(32, 8)>>>(ffn_w1, w1t, Cc, DFF, 0, 0);
    transpose_f2h_kernel<<<dim3(24, 96, 1), dim3(32, 8)>>>(ffn_w2, w2t, DFF, Cc, 0, 0);

    qconv_kernel<<<NT_, 256>>>(enc, qconv_w);
    transpose_h2h_kernel<<<dim3(3, 32, 64), dim3(32, 8)>>>(qh, vtp, Nn, HD,
                                                           (size_t)Nn * HD, (size_t)Nn * HD);

    launch_scores(qh, ap, scale);
    softmax_mix_kernel<<<NT_, 256>>>(reatten_w, reatten_b, bn_gamma, bn_beta);
    launch_av(ph, vtp, xh);
    launch_proj(xh, pwt, yp, proj_b, enc);
    layernorm_kernel<<<NT_, 256>>>(yp, yp, yh, ln1_g, ln1_b);
    launch_ffn1(yh, w1t, hh, ffn_b1);
    launch_ffn2(hh, w2t, xp, ffn_b2, yp);
    layernorm_kernel<<<NT_, 256>>>(xp, out, nullptr, ln2_g, ln2_b);
}

// round 14
// speedup vs baseline: 1.9379x; 1.1134x over previous
#include <cuda_runtime.h>
#include <cuda_bf16.h>
#include <cuda_fp16.h>
#include <cstdint>
#include <math.h>

// Problem constants
#define Bb   8
#define Nn   1024
#define Cc   768
#define Hh   8
#define HD   96
#define DFF  3072
#define NT_  (Bb * Nn)          // 8192 tokens

// ---------------------------------------------------------------------------
// Scratch (device globals — no allocation allowed)
// ---------------------------------------------------------------------------
__device__ __half g_qh[(size_t)Bb * Hh * Nn * HD];         // q fp16 [b][h][n][d]
__device__ __half g_vt[(size_t)Bb * Hh * HD * Nn];         // V^T fp16 [b][h][d][n]
__device__ __half g_attn[(size_t)Bb * Hh * Nn * Nn];       // scores fp16
__device__ __half g_ph[(size_t)Bb * Hh * Nn * Nn];         // probs fp16
__device__ __half g_xh[(size_t)NT_ * Cc];                  // attn-out fp16 (proj A)
__device__ float  g_y[(size_t)NT_ * Cc];                   // LN1 out fp32 (residual)
__device__ __half g_yh[(size_t)NT_ * Cc];                  // LN1 out fp16 (ffn1 A)
__device__ __half g_hh[(size_t)NT_ * DFF];                 // ffn hidden fp16
__device__ float  g_x[(size_t)NT_ * Cc];                   // proj-out / ffn2-out fp32
__device__ __half g_pwt[(size_t)Cc * Cc];                  // proj_w^T fp16
__device__ __half g_w1t[(size_t)DFF * Cc];                 // ffn_w1^T fp16
__device__ __half g_w2t[(size_t)Cc * DFF];                 // ffn_w2^T fp16

// ---------------------------------------------------------------------------
// helpers
// ---------------------------------------------------------------------------
__device__ __forceinline__ unsigned int smem_u32(const void* p) {
    return (unsigned int)__cvta_generic_to_shared(p);
}
__device__ __forceinline__ void cp_async16(unsigned int dst, const void* src) {
    asm volatile("cp.async.ca.shared.global [%0], [%1], 16;\n" :: "r"(dst), "l"(src));
}
__device__ __forceinline__ void cp_commit() {
    asm volatile("cp.async.commit_group;\n");
}
template<int N>
__device__ __forceinline__ void cp_wait() {
    asm volatile("cp.async.wait_group %0;\n" :: "n"(N));
}
__device__ __forceinline__ void ldmatrix_x4(unsigned int* r, unsigned int addr) {
    asm volatile("ldmatrix.sync.aligned.m8n8.x4.shared.b16 {%0,%1,%2,%3}, [%4];"
                 : "=r"(r[0]), "=r"(r[1]), "=r"(r[2]), "=r"(r[3]) : "r"(addr));
}
__device__ __forceinline__ void mma_f16(float* c, const unsigned int* a, const unsigned int* b) {
    asm volatile(
        "mma.sync.aligned.m16n8k16.row.col.f32.f16.f16.f32 "
        "{%0,%1,%2,%3}, {%4,%5,%6,%7}, {%8,%9}, {%0,%1,%2,%3};"
        : "+f"(c[0]), "+f"(c[1]), "+f"(c[2]), "+f"(c[3])
        : "r"(a[0]), "r"(a[1]), "r"(a[2]), "r"(a[3]), "r"(b[0]), "r"(b[1]));
}

// ---------------------------------------------------------------------------
// Kernel 1: per-patch 3x3 conv, q=k=v, write fp16 [b][h][n][d]
// ---------------------------------------------------------------------------
__global__ void qconv_kernel(const float* __restrict__ x, const float* __restrict__ w)
{
    __shared__ float s_in[768];
    __shared__ float s_w[81];
    int bn = blockIdx.x;
    int b  = bn >> 10, n = bn & 1023;
    int t  = threadIdx.x;                // 256
    const float* xin = x + (size_t)bn * 768;
    s_in[t]       = xin[t];
    s_in[t + 256] = xin[t + 256];
    s_in[t + 512] = xin[t + 512];
    if (t < 81) s_w[t] = w[t];
    __syncthreads();

    int r = t >> 4, c = t & 15;
    float acc0 = 0.f, acc1 = 0.f, acc2 = 0.f;
    #pragma unroll
    for (int kh = 0; kh < 3; kh++) {
        int rr = r + kh - 1;
        if (rr < 0 || rr > 15) continue;
        #pragma unroll
        for (int kw = 0; kw < 3; kw++) {
            int cc = c + kw - 1;
            if (cc < 0 || cc > 15) continue;
            const float* wp = s_w + (kh * 3 + kw) * 9;
            int ip = (rr * 16 + cc) * 3;
            #pragma unroll
            for (int ci = 0; ci < 3; ci++) {
                float v = s_in[ip + ci];
                acc0 += v * wp[ci * 3 + 0];
                acc1 += v * wp[ci * 3 + 1];
                acc2 += v * wp[ci * 3 + 2];
            }
        }
    }
    float accs[3] = {acc0, acc1, acc2};
    #pragma unroll
    for (int co = 0; co < 3; co++) {
        int cidx = t * 3 + co;
        int h = cidx / HD, d = cidx % HD;
        g_qh[(((size_t)b * Hh + h) * Nn + n) * HD + d] = __float2half(accs[co]);
    }
}

// ---------------------------------------------------------------------------
// Transpose fp32 -> fp16: in[z][R][C] fp32 -> out[z][C][R] fp16. Block (32,8).
// ---------------------------------------------------------------------------
__global__ void transpose_f2h_kernel(const float* __restrict__ in,
                                     __half* __restrict__ out,
                                     int R, int C, size_t sIn, size_t sOut)
{
    __shared__ float tile[32][33];
    int z = blockIdx.z;
    const float* ip = in + (size_t)z * sIn;
    __half* op = out + (size_t)z * sOut;
    int c0 = blockIdx.x * 32, r0 = blockIdx.y * 32;
    int tx = threadIdx.x, ty = threadIdx.y;
    #pragma unroll
    for (int j = 0; j < 4; j++)
        tile[ty + 8 * j][tx] = ip[(size_t)(r0 + ty + 8 * j) * C + c0 + tx];
    __syncthreads();
    #pragma unroll
    for (int j = 0; j < 4; j++)
        op[(size_t)(c0 + ty + 8 * j) * R + r0 + tx] = __float2half(tile[tx][ty + 8 * j]);
}

// ---------------------------------------------------------------------------
// Transpose fp16 -> fp16: in[z][R][C] -> out[z][C][R]. (for V^T from g_qh)
// ---------------------------------------------------------------------------
__global__ void transpose_h2h_kernel(const __half* __restrict__ in,
                                     __half* __restrict__ out,
                                     int R, int C, size_t sIn, size_t sOut)
{
    __shared__ float tile[32][33];
    int z = blockIdx.z;
    const __half* ip = in + (size_t)z * sIn;
    __half* op = out + (size_t)z * sOut;
    int c0 = blockIdx.x * 32, r0 = blockIdx.y * 32;
    int tx = threadIdx.x, ty = threadIdx.y;
    #pragma unroll
    for (int j = 0; j < 4; j++)
        tile[ty + 8 * j][tx] = __half2float(ip[(size_t)(r0 + ty + 8 * j) * C + c0 + tx]);
    __syncthreads();
    #pragma unroll
    for (int j = 0; j < 4; j++)
        op[(size_t)(c0 + ty + 8 * j) * R + r0 + tx] = __float2half(tile[tx][ty + 8 * j]);
}

// ---------------------------------------------------------------------------
// FP16 tensor-core GEMM (NT: A [M][K], B [N][K], both fp16 row-major).
// mma.m16n8k16, fp32 accum. BM=BN=128, templated BK (32 or 64).
// Padded rows: ROWB = BK*2 + 16 bytes (odd multiple of 16B -> conflict-free).
// MODE 0: fp16 C = acc*scale | MODE 1: fp32 C = acc+bias+res | MODE 2: fp16 gelu
// ---------------------------------------------------------------------------
template<int BK, int MODE>
__global__ __launch_bounds__(256, 2)
void mma_gemm_h(const __half* __restrict__ A, const __half* __restrict__ Bm,
                void* __restrict__ Cv,
                int K, int lda, int ldb, int ldc,
                size_t strideA, size_t strideB, size_t strideC,
                const float* __restrict__ bias, const float* __restrict__ res,
                int ldres, float scale)
{
    constexpr int BM = 128, BN = 128;
    constexpr int ROWB = BK * 2 + 16;
    constexpr int ASZB = BM * ROWB;
    constexpr int BSZB = BN * ROWB;
    constexpr int MFRAG = 2;
    constexpr int NFRAG = 8;
    constexpr int GPR = BK / 8;               // 16B groups per row

    extern __shared__ char smem_c[];
    char* As = smem_c;
    char* Bs = smem_c + 2 * ASZB;

    int bz = blockIdx.z;
    A  += strideA * bz;
    Bm += strideB * bz;

    int m0 = blockIdx.y * BM;
    int n0 = blockIdx.x * BN;
    int t    = threadIdx.x;
    int warp = t >> 5, lane = t & 31;
    int wm0 = (warp & 3) * 32;
    int wn0 = (warp >> 2) * 64;

    float acc[MFRAG][NFRAG][4];
    #pragma unroll
    for (int i = 0; i < MFRAG; i++)
        #pragma unroll
        for (int j = 0; j < NFRAG; j++)
            #pragma unroll
            for (int e = 0; e < 4; e++) acc[i][j][e] = 0.f;

    int arow  = lane & 15;
    int ahalf = lane >> 4;
    int brow  = (lane & 7) + ((lane >> 4) & 1) * 8;
    int bhalf = (lane >> 3) & 1;

    auto load_stage = [&](int st, int kk) {
        char* Asd = As + st * ASZB;
        char* Bsd = Bs + st * BSZB;
        #pragma unroll
        for (int v = 0; v < BM * GPR / 256; v++) {
            int idx = t + v * 256;
            int r = idx / GPR, g = idx % GPR;
            cp_async16(smem_u32(Asd + r * ROWB + g * 16),
                       A + (size_t)(m0 + r) * lda + kk + g * 8);
        }
        #pragma unroll
        for (int v = 0; v < BN * GPR / 256; v++) {
            int idx = t + v * 256;
            int r = idx / GPR, g = idx % GPR;
            cp_async16(smem_u32(Bsd + r * ROWB + g * 16),
                       Bm + (size_t)(n0 + r) * ldb + kk + g * 8);
        }
    };

    int nIter = K / BK;
    load_stage(0, 0);
    cp_commit();

    for (int it = 0; it < nIter; ++it) {
        int s = it & 1;
        if (it + 1 < nIter) {
            load_stage(s ^ 1, (it + 1) * BK);
            cp_commit();
            cp_wait<1>();
        } else {
            cp_wait<0>();
        }
        __syncthreads();

        char* Asd = As + s * ASZB;
        char* Bsd = Bs + s * BSZB;
        #pragma unroll
        for (int ks = 0; ks < BK / 16; ks++) {
            unsigned int afr[MFRAG][4];
            #pragma unroll
            for (int mf = 0; mf < MFRAG; mf++) {
                unsigned int addr = smem_u32(
                    Asd + (wm0 + mf * 16 + arow) * ROWB + (ks * 2 + ahalf) * 16);
                ldmatrix_x4(afr[mf], addr);
            }
            unsigned int bfr[NFRAG][2];
            #pragma unroll
            for (int np = 0; np < 4; np++) {
                unsigned int addr = smem_u32(
                    Bsd + (wn0 + np * 16 + brow) * ROWB + (ks * 2 + bhalf) * 16);
                ldmatrix_x4(&bfr[np * 2][0], addr);
            }
            #pragma unroll
            for (int mf = 0; mf < MFRAG; mf++)
                #pragma unroll
                for (int nf = 0; nf < NFRAG; nf++)
                    mma_f16(acc[mf][nf], afr[mf], bfr[nf]);
        }
        __syncthreads();
    }

    // ---- epilogue
    float* Cf = (float*)Cv;
    __half* Ch = (__half*)Cv;
    if (MODE == 0) Ch += strideC * bz;
    if (MODE == 1) Cf += strideC * bz;

    #pragma unroll
    for (int mf = 0; mf < MFRAG; mf++) {
        #pragma unroll
        for (int half_ = 0; half_ < 2; half_++) {
            int row = m0 + wm0 + mf * 16 + (lane >> 2) + half_ * 8;
            #pragma unroll
            for (int nf = 0; nf < NFRAG; nf++) {
                int col = n0 + wn0 + nf * 8 + (lane & 3) * 2;
                float v0 = acc[mf][nf][half_ * 2 + 0];
                float v1 = acc[mf][nf][half_ * 2 + 1];
                if constexpr (MODE == 0) {
                    *reinterpret_cast<__half2*>(&Ch[(size_t)row * ldc + col]) =
                        __floats2half2_rn(v0 * scale, v1 * scale);
                } else if constexpr (MODE == 1) {
                    float2 bb = *reinterpret_cast<const float2*>(&bias[col]);
                    float2 rr = *reinterpret_cast<const float2*>(&res[(size_t)row * ldres + col]);
                    *reinterpret_cast<float2*>(&Cf[(size_t)row * ldc + col]) =
                        make_float2(v0 + bb.x + rr.x, v1 + bb.y + rr.y);
                } else {
                    float2 bb = *reinterpret_cast<const float2*>(&bias[col]);
                    v0 += bb.x; v1 += bb.y;
                    v0 = 0.5f * v0 * (1.0f + erff(v0 * 0.70710678118654752f));
                    v1 = 0.5f * v1 * (1.0f + erff(v1 * 0.70710678118654752f));
                    *reinterpret_cast<__half2*>(&Ch[(size_t)row * ldc + col]) =
                        __floats2half2_rn(v0, v1);
                }
            }
        }
    }
}

// ---------------------------------------------------------------------------
// FP16 AV GEMM: O = P[Nn x Nn] @ V via V^T [HD x Nn] NT. BM=128, BN=96, BK=64.
// ---------------------------------------------------------------------------
__global__ __launch_bounds__(256, 2)
void mma_gemm_avh(const __half* __restrict__ A, const __half* __restrict__ Bm,
                  __half* __restrict__ Cm,
                  int K, int lda, int ldb, int ldc,
                  size_t strideA, size_t strideB)
{
    constexpr int BM = 128, BN = 96, BK = 64;
    constexpr int ROWB = BK * 2 + 16;         // 144
    constexpr int ASZB = BM * ROWB;
    constexpr int BSZB = BN * ROWB;
    constexpr int MFRAG = 2;
    constexpr int NFRAG = 6;
    constexpr int GPR = BK / 8;               // 8

    extern __shared__ char smem_c[];
    char* As = smem_c;
    char* Bs = smem_c + 2 * ASZB;

    int bz = blockIdx.z;
    A  += strideA * bz;
    Bm += strideB * bz;

    int m0 = blockIdx.y * BM;
    int n0 = blockIdx.x * BN;
    int t    = threadIdx.x;
    int warp = t >> 5, lane = t & 31;
    int wm0 = (warp & 3) * 32;
    int wn0 = (warp >> 2) * 48;

    float acc[MFRAG][NFRAG][4];
    #pragma unroll
    for (int i = 0; i < MFRAG; i++)
        #pragma unroll
        for (int j = 0; j < NFRAG; j++)
            #pragma unroll
            for (int e = 0; e < 4; e++) acc[i][j][e] = 0.f;

    int arow  = lane & 15;
    int ahalf = lane >> 4;
    int brow  = (lane & 7) + ((lane >> 4) & 1) * 8;
    int bhalf = (lane >> 3) & 1;

    auto load_stage = [&](int st, int kk) {
        char* Asd = As + st * ASZB;
        char* Bsd = Bs + st * BSZB;
        #pragma unroll
        for (int v = 0; v < BM * GPR / 256; v++) {   // 4
            int idx = t + v * 256;
            int r = idx / GPR, g = idx % GPR;
            cp_async16(smem_u32(Asd + r * ROWB + g * 16),
                       A + (size_t)(m0 + r) * lda + kk + g * 8);
        }
        #pragma unroll
        for (int v = 0; v < BN * GPR / 256; v++) {   // 3
            int idx = t + v * 256;
            int r = idx / GPR, g = idx % GPR;
            cp_async16(smem_u32(Bsd + r * ROWB + g * 16),
                       Bm + (size_t)(n0 + r) * ldb + kk + g * 8);
        }
    };

    int nIter = K / BK;
    load_stage(0, 0);
    cp_commit();

    for (int it = 0; it < nIter; ++it) {
        int s = it & 1;
        if (it + 1 < nIter) {
            load_stage(s ^ 1, (it + 1) * BK);
            cp_commit();
            cp_wait<1>();
        } else {
            cp_wait<0>();
        }
        __syncthreads();

        char* Asd = As + s * ASZB;
        char* Bsd = Bs + s * BSZB;
        #pragma unroll
        for (int ks = 0; ks < BK / 16; ks++) {
            unsigned int afr[MFRAG][4];
            #pragma unroll
            for (int mf = 0; mf < MFRAG; mf++) {
                unsigned int addr = smem_u32(
                    Asd + (wm0 + mf * 16 + arow) * ROWB + (ks * 2 + ahalf) * 16);
                ldmatrix_x4(afr[mf], addr);
            }
            unsigned int bfr[NFRAG][2];
            #pragma unroll
            for (int np = 0; np < 3; np++) {
                unsigned int addr = smem_u32(
                    Bsd + (wn0 + np * 16 + brow) * ROWB + (ks * 2 + bhalf) * 16);
                ldmatrix_x4(&bfr[np * 2][0], addr);
            }
            #pragma unroll
            for (int mf = 0; mf < MFRAG; mf++)
                #pragma unroll
                for (int nf = 0; nf < NFRAG; nf++)
                    mma_f16(acc[mf][nf], afr[mf], bfr[nf]);
        }
        __syncthreads();
    }

    size_t out_off = (size_t)(bz >> 3) * ((size_t)Nn * Cc) + (size_t)(bz & 7) * HD;
    #pragma unroll
    for (int mf = 0; mf < MFRAG; mf++) {
        #pragma unroll
        for (int half_ = 0; half_ < 2; half_++) {
            int row = m0 + wm0 + mf * 16 + (lane >> 2) + half_ * 8;
            #pragma unroll
            for (int nf = 0; nf < NFRAG; nf++) {
                int col = n0 + wn0 + nf * 8 + (lane & 3) * 2;
                *reinterpret_cast<__half2*>(&Cm[out_off + (size_t)row * ldc + col]) =
                    __floats2half2_rn(acc[mf][nf][half_ * 2 + 0], acc[mf][nf][half_ * 2 + 1]);
            }
        }
    }
}

// ---------------------------------------------------------------------------
// fused per-row softmax (8 heads) + head mix + BN. fp16 scores -> fp16 probs.
// ---------------------------------------------------------------------------
__global__ void softmax_mix_kernel(const float* __restrict__ rw, const float* __restrict__ rb,
                                   const float* __restrict__ bng, const float* __restrict__ bnb)
{
    __shared__ __align__(16) float sp[8][1024];
    __shared__ float s_w[64];
    __shared__ float s_s[8], s_o[8];

    int bn = blockIdx.x;
    int b  = bn >> 10, n = bn & 1023;
    int t  = threadIdx.x;                    // 256

    if (t < 64) s_w[t] = rw[t];
    if (t < 8) {
        float bs = bng[t] * rsqrtf(1.0f + 1e-3f);
        s_s[t] = bs;
        s_o[t] = rb[t] * bs + bnb[t];
    }
    #pragma unroll
    for (int h = 0; h < 8; h++) {
        uint2 raw = reinterpret_cast<const uint2*>(
            g_attn + (((size_t)b * Hh + h) * Nn + n) * Nn)[t];
        __half2 h0 = *reinterpret_cast<__half2*>(&raw.x);
        __half2 h1 = *reinterpret_cast<__half2*>(&raw.y);
        float2 f0 = __half22float2(h0);
        float2 f1 = __half22float2(h1);
        reinterpret_cast<float4*>(sp[h])[t] = make_float4(f0.x, f0.y, f1.x, f1.y);
    }
    __syncthreads();

    int w = t >> 5, lane = t & 31;
    {
        float* sr = sp[w];
        float mx = -1e30f;
        for (int m = lane; m < 1024; m += 32) mx = fmaxf(mx, sr[m]);
        #pragma unroll
        for (int off = 16; off; off >>= 1) mx = fmaxf(mx, __shfl_xor_sync(0xffffffffu, mx, off));
        float sum = 0.f;
        for (int m = lane; m < 1024; m += 32) {
            float e = __expf(sr[m] - mx);
            sr[m] = e;
            sum += e;
        }
        #pragma unroll
        for (int off = 16; off; off >>= 1) sum += __shfl_xor_sync(0xffffffffu, sum, off);
        float inv = 1.0f / sum;
        for (int m = lane; m < 1024; m += 32) sr[m] *= inv;
    }
    __syncthreads();

    float4 p[8];
    #pragma unroll
    for (int h = 0; h < 8; h++) p[h] = reinterpret_cast<const float4*>(sp[h])[t];
    #pragma unroll
    for (int g = 0; g < 8; g++) {
        float4 a = make_float4(0.f, 0.f, 0.f, 0.f);
        #pragma unroll
        for (int h = 0; h < 8; h++) {
            float wgh = s_w[g * 8 + h];
            a.x = fmaf(p[h].x, wgh, a.x);
            a.y = fmaf(p[h].y, wgh, a.y);
            a.z = fmaf(p[h].z, wgh, a.z);
            a.w = fmaf(p[h].w, wgh, a.w);
        }
        float ss = s_s[g], oo = s_o[g];
        a.x = a.x * ss + oo; a.y = a.y * ss + oo;
        a.z = a.z * ss + oo; a.w = a.w * ss + oo;
        __half2 p0 = __floats2half2_rn(a.x, a.y);
        __half2 p1 = __floats2half2_rn(a.z, a.w);
        uint2 packed;
        packed.x = *reinterpret_cast<unsigned int*>(&p0);
        packed.y = *reinterpret_cast<unsigned int*>(&p1);
        reinterpret_cast<uint2*>(
            g_ph + (((size_t)b * Hh + g) * Nn + n) * Nn)[t] = packed;
    }
}

// ---------------------------------------------------------------------------
// LayerNorm over 768. Writes fp32 out; optionally also fp16 copy.
// ---------------------------------------------------------------------------
__global__ void layernorm_kernel(const float* __restrict__ in, float* __restrict__ out,
                                 __half* __restrict__ out16,
                                 const float* __restrict__ g, const float* __restrict__ bta)
{
    __shared__ float red[16];
    __shared__ float s_mu, s_rs;
    int row = blockIdx.x;
    int t   = threadIdx.x;       // 256
    const float* rp = in + (size_t)row * Cc;
    float x0 = rp[t], x1 = rp[t + 256], x2 = rp[t + 512];
    float s  = x0 + x1 + x2;
    float ss = x0 * x0 + x1 * x1 + x2 * x2;
    #pragma unroll
    for (int off = 16; off; off >>= 1) {
        s  += __shfl_xor_sync(0xffffffffu, s, off);
        ss += __shfl_xor_sync(0xffffffffu, ss, off);
    }
    int w = t >> 5, lane = t & 31;
    if (lane == 0) { red[w] = s; red[8 + w] = ss; }
    __syncthreads();
    if (t == 0) {
        float S = 0.f, SS = 0.f;
        #pragma unroll
        for (int i = 0; i < 8; i++) { S += red[i]; SS += red[8 + i]; }
        float mu  = S * (1.0f / 768.0f);
        float var = SS * (1.0f / 768.0f) - mu * mu;
        s_mu = mu;
        s_rs = rsqrtf(var + 1e-3f);
    }
    __syncthreads();
    float mu = s_mu, rs = s_rs;
    float v0 = (x0 - mu) * rs * g[t]       + bta[t];
    float v1 = (x1 - mu) * rs * g[t + 256] + bta[t + 256];
    float v2 = (x2 - mu) * rs * g[t + 512] + bta[t + 512];
    float* op = out + (size_t)row * Cc;
    op[t] = v0; op[t + 256] = v1; op[t + 512] = v2;
    if (out16) {
        __half* oh = out16 + (size_t)row * Cc;
        oh[t] = __float2half(v0);
        oh[t + 256] = __float2half(v1);
        oh[t + 512] = __float2half(v2);
    }
}

// ---------------------------------------------------------------------------
// Host-side launch helpers
// ---------------------------------------------------------------------------
#define SMEM_H32 (2 * (128 * 80 + 128 * 80))     // 40960 B (BK=32)
#define SMEM_H64 (2 * (128 * 144 + 128 * 144))   // 73728 B (BK=64)
#define SMEM_AVH (2 * (128 * 144 + 96 * 144))    // 64512 B (BK=64)

static void launch_scores(const __half* qh, __half* ap, float scale)
{
    static bool init = false;
    if (!init) {
        cudaFuncSetAttribute((const void*)mma_gemm_h<32, 0>,
                             cudaFuncAttributeMaxDynamicSharedMemorySize, SMEM_H32);
        init = true;
    }
    mma_gemm_h<32, 0><<<dim3(8, 8, 64), 256, SMEM_H32>>>(
        qh, qh, ap, HD, HD, HD, Nn,
        (size_t)Nn * HD, (size_t)Nn * HD, (size_t)Nn * Nn,
        nullptr, nullptr, 0, scale);
}
static void launch_av(const __half* ph, const __half* vt, __half* xh)
{
    static bool init = false;
    if (!init) {
        cudaFuncSetAttribute((const void*)mma_gemm_avh,
                             cudaFuncAttributeMaxDynamicSharedMemorySize, SMEM_AVH);
        init = true;
    }
    mma_gemm_avh<<<dim3(1, 8, 64), 256, SMEM_AVH>>>(
        ph, vt, xh, Nn, Nn, Nn, Cc,
        (size_t)Nn * Nn, (size_t)Nn * HD);
}
static void launch_proj(const __half* xh, const __half* wt, float* yp,
                        const float* b, const float* res)
{
    static bool init = false;
    if (!init) {
        cudaFuncSetAttribute((const void*)mma_gemm_h<64, 1>,
                             cudaFuncAttributeMaxDynamicSharedMemorySize, SMEM_H64);
        init = true;
    }
    mma_gemm_h<64, 1><<<dim3(6, 64, 1), 256, SMEM_H64>>>(
        xh, wt, yp, Cc, Cc, Cc, Cc,
        0, 0, 0, b, res, Cc, 1.0f);
}
static void launch_ffn1(const __half* yh, const __half* wt, __half* hh, const float* b)
{
    static bool init = false;
    if (!init) {
        cudaFuncSetAttribute((const void*)mma_gemm_h<64, 2>,
                             cudaFuncAttributeMaxDynamicSharedMemorySize, SMEM_H64);
        init = true;
    }
    mma_gemm_h<64, 2><<<dim3(24, 64, 1), 256, SMEM_H64>>>(
        yh, wt, hh, Cc, Cc, Cc, DFF,
        0, 0, 0, b, nullptr, 0, 1.0f);
}
static void launch_ffn2(const __half* hh, const __half* wt, float* xp,
                        const float* b, const float* res)
{
    mma_gemm_h<64, 1><<<dim3(6, 64, 1), 256, SMEM_H64>>>(
        hh, wt, xp, DFF, DFF, DFF, Cc,
        0, 0, 0, b, res, Cc, 1.0f);
}

// ---------------------------------------------------------------------------
// Launch
// ---------------------------------------------------------------------------
extern "C" void kernel_launch(void* const* d_in, const int* in_sizes, int n_in,
                              void* d_out, int out_size)
{
    (void)in_sizes; (void)n_in; (void)out_size;
    const float* enc       = (const float*)d_in[0];
    const float* qconv_w   = (const float*)d_in[1];
    const float* reatten_w = (const float*)d_in[2];
    const float* reatten_b = (const float*)d_in[3];
    const float* bn_gamma  = (const float*)d_in[4];
    const float* bn_beta   = (const float*)d_in[5];
    const float* proj_w    = (const float*)d_in[6];
    const float* proj_b    = (const float*)d_in[7];
    const float* ffn_w1    = (const float*)d_in[8];
    const float* ffn_b1    = (const float*)d_in[9];
    const float* ffn_w2    = (const float*)d_in[10];
    const float* ffn_b2    = (const float*)d_in[11];
    const float* ln1_g     = (const float*)d_in[12];
    const float* ln1_b     = (const float*)d_in[13];
    const float* ln2_g     = (const float*)d_in[14];
    const float* ln2_b     = (const float*)d_in[15];
    float* out = (float*)d_out;

    float *yp, *xp;
    __half *qh, *vtp, *ap, *ph, *xh, *yh, *hh, *pwt, *w1t, *w2t;
    cudaGetSymbolAddress((void**)&qh,  g_qh);
    cudaGetSymbolAddress((void**)&vtp, g_vt);
    cudaGetSymbolAddress((void**)&ap,  g_attn);
    cudaGetSymbolAddress((void**)&ph,  g_ph);
    cudaGetSymbolAddress((void**)&xh,  g_xh);
    cudaGetSymbolAddress((void**)&yp,  g_y);
    cudaGetSymbolAddress((void**)&yh,  g_yh);
    cudaGetSymbolAddress((void**)&hh,  g_hh);
    cudaGetSymbolAddress((void**)&xp,  g_x);
    cudaGetSymbolAddress((void**)&pwt, g_pwt);
    cudaGetSymbolAddress((void**)&w1t, g_w1t);
    cudaGetSymbolAddress((void**)&w2t, g_w2t);

    const float scale = 0.1020620726159658f;   // 96^-0.5

    // weight transposes ([K][N] fp32 -> [N][K] fp16)
    transpose_f2h_kernel<<<dim3(24, 24, 1), dim3(32, 8)>>>(proj_w, pwt, Cc, Cc, 0, 0);
    transpose_f2h_kernel<<<dim3(96, 24, 1), dim3(32, 8)>>>(ffn_w1, w1t, Cc, DFF, 0, 0);
    transpose_f2h_kernel<<<dim3(24, 96, 1), dim3(32, 8)>>>(ffn_w2, w2t, DFF, Cc, 0, 0);

    qconv_kernel<<<NT_, 256>>>(enc, qconv_w);
    transpose_h2h_kernel<<<dim3(3, 32, 64), dim3(32, 8)>>>(qh, vtp, Nn, HD,
                                                           (size_t)Nn * HD, (size_t)Nn * HD);

    launch_scores(qh, ap, scale);
    softmax_mix_kernel<<<NT_, 256>>>(reatten_w, reatten_b, bn_gamma, bn_beta);
    launch_av(ph, vtp, xh);
    launch_proj(xh, pwt, yp, proj_b, enc);
    layernorm_kernel<<<NT_, 256>>>(yp, yp, yh, ln1_g, ln1_b);
    launch_ffn1(yh, w1t, hh, ffn_b1);
    launch_ffn2(hh, w2t, xp, ffn_b2, yp);
    layernorm_kernel<<<NT_, 256>>>(xp, out, nullptr, ln2_g, ln2_b);
}

// round 15
// speedup vs baseline: 1.9535x; 1.0081x over previous
#include <cuda_runtime.h>
#include <cuda_bf16.h>
#include <cuda_fp16.h>
#include <cstdint>
#include <math.h>

// Problem constants
#define Bb   8
#define Nn   1024
#define Cc   768
#define Hh   8
#define HD   96
#define DFF  3072
#define NT_  (Bb * Nn)          // 8192 tokens

// ---------------------------------------------------------------------------
// Scratch (device globals — no allocation allowed)
// ---------------------------------------------------------------------------
__device__ __half g_qh[(size_t)Bb * Hh * Nn * HD];         // q fp16 [b][h][n][d]
__device__ __half g_vt[(size_t)Bb * Hh * HD * Nn];         // V^T fp16 [b][h][d][n]
__device__ __half g_attn[(size_t)Bb * Hh * Nn * Nn];       // scores fp16
__device__ __half g_ph[(size_t)Bb * Hh * Nn * Nn];         // probs fp16
__device__ __half g_xh[(size_t)NT_ * Cc];                  // attn-out fp16 (proj A)
__device__ float  g_y[(size_t)NT_ * Cc];                   // LN1 out fp32 (residual)
__device__ __half g_yh[(size_t)NT_ * Cc];                  // LN1 out fp16 (ffn1 A)
__device__ __half g_hh[(size_t)NT_ * DFF];                 // ffn hidden fp16
__device__ float  g_x[(size_t)NT_ * Cc];                   // proj-out / ffn2-out fp32
__device__ __half g_pwt[(size_t)Cc * Cc];                  // proj_w^T fp16
__device__ __half g_w1t[(size_t)DFF * Cc];                 // ffn_w1^T fp16
__device__ __half g_w2t[(size_t)Cc * DFF];                 // ffn_w2^T fp16

// ---------------------------------------------------------------------------
// helpers
// ---------------------------------------------------------------------------
__device__ __forceinline__ unsigned int smem_u32(const void* p) {
    return (unsigned int)__cvta_generic_to_shared(p);
}
__device__ __forceinline__ void cp_async16(unsigned int dst, const void* src) {
    asm volatile("cp.async.ca.shared.global [%0], [%1], 16;\n" :: "r"(dst), "l"(src));
}
__device__ __forceinline__ void cp_commit() {
    asm volatile("cp.async.commit_group;\n");
}
template<int N>
__device__ __forceinline__ void cp_wait() {
    asm volatile("cp.async.wait_group %0;\n" :: "n"(N));
}
__device__ __forceinline__ void ldmatrix_x4(unsigned int* r, unsigned int addr) {
    asm volatile("ldmatrix.sync.aligned.m8n8.x4.shared.b16 {%0,%1,%2,%3}, [%4];"
                 : "=r"(r[0]), "=r"(r[1]), "=r"(r[2]), "=r"(r[3]) : "r"(addr));
}
__device__ __forceinline__ void mma_f16(float* c, const unsigned int* a, const unsigned int* b) {
    asm volatile(
        "mma.sync.aligned.m16n8k16.row.col.f32.f16.f16.f32 "
        "{%0,%1,%2,%3}, {%4,%5,%6,%7}, {%8,%9}, {%0,%1,%2,%3};"
        : "+f"(c[0]), "+f"(c[1]), "+f"(c[2]), "+f"(c[3])
        : "r"(a[0]), "r"(a[1]), "r"(a[2]), "r"(a[3]), "r"(b[0]), "r"(b[1]));
}

// ---------------------------------------------------------------------------
// Kernel 1: per-patch 3x3 conv, q=k=v, write fp16 [b][h][n][d]
// ---------------------------------------------------------------------------
__global__ void qconv_kernel(const float* __restrict__ x, const float* __restrict__ w)
{
    __shared__ float s_in[768];
    __shared__ float s_w[81];
    int bn = blockIdx.x;
    int b  = bn >> 10, n = bn & 1023;
    int t  = threadIdx.x;                // 256
    const float* xin = x + (size_t)bn * 768;
    s_in[t]       = xin[t];
    s_in[t + 256] = xin[t + 256];
    s_in[t + 512] = xin[t + 512];
    if (t < 81) s_w[t] = w[t];
    __syncthreads();

    int r = t >> 4, c = t & 15;
    float acc0 = 0.f, acc1 = 0.f, acc2 = 0.f;
    #pragma unroll
    for (int kh = 0; kh < 3; kh++) {
        int rr = r + kh - 1;
        if (rr < 0 || rr > 15) continue;
        #pragma unroll
        for (int kw = 0; kw < 3; kw++) {
            int cc = c + kw - 1;
            if (cc < 0 || cc > 15) continue;
            const float* wp = s_w + (kh * 3 + kw) * 9;
            int ip = (rr * 16 + cc) * 3;
            #pragma unroll
            for (int ci = 0; ci < 3; ci++) {
                float v = s_in[ip + ci];
                acc0 += v * wp[ci * 3 + 0];
                acc1 += v * wp[ci * 3 + 1];
                acc2 += v * wp[ci * 3 + 2];
            }
        }
    }
    float accs[3] = {acc0, acc1, acc2};
    #pragma unroll
    for (int co = 0; co < 3; co++) {
        int cidx = t * 3 + co;
        int h = cidx / HD, d = cidx % HD;
        g_qh[(((size_t)b * Hh + h) * Nn + n) * HD + d] = __float2half(accs[co]);
    }
}

// ---------------------------------------------------------------------------
// Transpose fp32 -> fp16: in[z][R][C] fp32 -> out[z][C][R] fp16. Block (32,8).
// ---------------------------------------------------------------------------
__global__ void transpose_f2h_kernel(const float* __restrict__ in,
                                     __half* __restrict__ out,
                                     int R, int C, size_t sIn, size_t sOut)
{
    __shared__ float tile[32][33];
    int z = blockIdx.z;
    const float* ip = in + (size_t)z * sIn;
    __half* op = out + (size_t)z * sOut;
    int c0 = blockIdx.x * 32, r0 = blockIdx.y * 32;
    int tx = threadIdx.x, ty = threadIdx.y;
    #pragma unroll
    for (int j = 0; j < 4; j++)
        tile[ty + 8 * j][tx] = ip[(size_t)(r0 + ty + 8 * j) * C + c0 + tx];
    __syncthreads();
    #pragma unroll
    for (int j = 0; j < 4; j++)
        op[(size_t)(c0 + ty + 8 * j) * R + r0 + tx] = __float2half(tile[tx][ty + 8 * j]);
}

// ---------------------------------------------------------------------------
// Transpose fp16 -> fp16: in[z][R][C] -> out[z][C][R]. (for V^T from g_qh)
// ---------------------------------------------------------------------------
__global__ void transpose_h2h_kernel(const __half* __restrict__ in,
                                     __half* __restrict__ out,
                                     int R, int C, size_t sIn, size_t sOut)
{
    __shared__ float tile[32][33];
    int z = blockIdx.z;
    const __half* ip = in + (size_t)z * sIn;
    __half* op = out + (size_t)z * sOut;
    int c0 = blockIdx.x * 32, r0 = blockIdx.y * 32;
    int tx = threadIdx.x, ty = threadIdx.y;
    #pragma unroll
    for (int j = 0; j < 4; j++)
        tile[ty + 8 * j][tx] = __half2float(ip[(size_t)(r0 + ty + 8 * j) * C + c0 + tx]);
    __syncthreads();
    #pragma unroll
    for (int j = 0; j < 4; j++)
        op[(size_t)(c0 + ty + 8 * j) * R + r0 + tx] = __float2half(tile[tx][ty + 8 * j]);
}

// ---------------------------------------------------------------------------
// Scores GEMM, single-stage: K=96 entirely in smem (no mainloop).
// A=B=q fp16 NT. BM=BN=128, ROWB=208 (192B data + 16B pad, conflict-free).
// Epilogue: fp16 C = acc*scale.
// ---------------------------------------------------------------------------
__global__ __launch_bounds__(256, 2)
void mma_gemm_sc(const __half* __restrict__ A, const __half* __restrict__ Bm,
                 __half* __restrict__ Cm,
                 int lda, int ldb, int ldc,
                 size_t strideA, size_t strideB, size_t strideC, float scale)
{
    constexpr int BM = 128, BN = 128, KK = 96;
    constexpr int ROWB = KK * 2 + 16;          // 208
    constexpr int ASZB = BM * ROWB;
    constexpr int MFRAG = 2;
    constexpr int NFRAG = 8;
    constexpr int GPR = KK / 8;                // 12 x 16B groups per row

    extern __shared__ char smem_c[];
    char* As = smem_c;
    char* Bs = smem_c + ASZB;

    int bz = blockIdx.z;
    A  += strideA * bz;
    Bm += strideB * bz;
    Cm += strideC * bz;

    int m0 = blockIdx.y * BM;
    int n0 = blockIdx.x * BN;
    int t    = threadIdx.x;
    int warp = t >> 5, lane = t & 31;
    int wm0 = (warp & 3) * 32;
    int wn0 = (warp >> 2) * 64;

    float acc[MFRAG][NFRAG][4];
    #pragma unroll
    for (int i = 0; i < MFRAG; i++)
        #pragma unroll
        for (int j = 0; j < NFRAG; j++)
            #pragma unroll
            for (int e = 0; e < 4; e++) acc[i][j][e] = 0.f;

    int arow  = lane & 15;
    int ahalf = lane >> 4;
    int brow  = (lane & 7) + ((lane >> 4) & 1) * 8;
    int bhalf = (lane >> 3) & 1;

    // single-stage load of the full K=96 tiles
    #pragma unroll
    for (int v = 0; v < BM * GPR / 256; v++) {   // 6
        int idx = t + v * 256;
        int r = idx / GPR, g = idx % GPR;
        cp_async16(smem_u32(As + r * ROWB + g * 16),
                   A + (size_t)(m0 + r) * lda + g * 8);
    }
    #pragma unroll
    for (int v = 0; v < BN * GPR / 256; v++) {   // 6
        int idx = t + v * 256;
        int r = idx / GPR, g = idx % GPR;
        cp_async16(smem_u32(Bs + r * ROWB + g * 16),
                   Bm + (size_t)(n0 + r) * ldb + g * 8);
    }
    cp_commit();
    cp_wait<0>();
    __syncthreads();

    #pragma unroll
    for (int ks = 0; ks < KK / 16; ks++) {       // 6 k16 steps
        unsigned int afr[MFRAG][4];
        #pragma unroll
        for (int mf = 0; mf < MFRAG; mf++) {
            unsigned int addr = smem_u32(
                As + (wm0 + mf * 16 + arow) * ROWB + (ks * 2 + ahalf) * 16);
            ldmatrix_x4(afr[mf], addr);
        }
        unsigned int bfr[NFRAG][2];
        #pragma unroll
        for (int np = 0; np < 4; np++) {
            unsigned int addr = smem_u32(
                Bs + (wn0 + np * 16 + brow) * ROWB + (ks * 2 + bhalf) * 16);
            ldmatrix_x4(&bfr[np * 2][0], addr);
        }
        #pragma unroll
        for (int mf = 0; mf < MFRAG; mf++)
            #pragma unroll
            for (int nf = 0; nf < NFRAG; nf++)
                mma_f16(acc[mf][nf], afr[mf], bfr[nf]);
    }

    #pragma unroll
    for (int mf = 0; mf < MFRAG; mf++) {
        #pragma unroll
        for (int half_ = 0; half_ < 2; half_++) {
            int row = m0 + wm0 + mf * 16 + (lane >> 2) + half_ * 8;
            #pragma unroll
            for (int nf = 0; nf < NFRAG; nf++) {
                int col = n0 + wn0 + nf * 8 + (lane & 3) * 2;
                *reinterpret_cast<__half2*>(&Cm[(size_t)row * ldc + col]) =
                    __floats2half2_rn(acc[mf][nf][half_ * 2 + 0] * scale,
                                      acc[mf][nf][half_ * 2 + 1] * scale);
            }
        }
    }
}

// ---------------------------------------------------------------------------
// FP16 tensor-core GEMM (NT), BK=64, cp.async 2-stage. (R14 winner config)
// MODE 1: fp32 C = acc+bias+res | MODE 2: fp16 C = gelu(acc+bias)
// ---------------------------------------------------------------------------
template<int BK, int MODE>
__global__ __launch_bounds__(256, 2)
void mma_gemm_h(const __half* __restrict__ A, const __half* __restrict__ Bm,
                void* __restrict__ Cv,
                int K, int lda, int ldb, int ldc,
                size_t strideA, size_t strideB, size_t strideC,
                const float* __restrict__ bias, const float* __restrict__ res,
                int ldres, float scale)
{
    constexpr int BM = 128, BN = 128;
    constexpr int ROWB = BK * 2 + 16;
    constexpr int ASZB = BM * ROWB;
    constexpr int BSZB = BN * ROWB;
    constexpr int MFRAG = 2;
    constexpr int NFRAG = 8;
    constexpr int GPR = BK / 8;

    extern __shared__ char smem_c[];
    char* As = smem_c;
    char* Bs = smem_c + 2 * ASZB;

    int bz = blockIdx.z;
    A  += strideA * bz;
    Bm += strideB * bz;

    int m0 = blockIdx.y * BM;
    int n0 = blockIdx.x * BN;
    int t    = threadIdx.x;
    int warp = t >> 5, lane = t & 31;
    int wm0 = (warp & 3) * 32;
    int wn0 = (warp >> 2) * 64;

    float acc[MFRAG][NFRAG][4];
    #pragma unroll
    for (int i = 0; i < MFRAG; i++)
        #pragma unroll
        for (int j = 0; j < NFRAG; j++)
            #pragma unroll
            for (int e = 0; e < 4; e++) acc[i][j][e] = 0.f;

    int arow  = lane & 15;
    int ahalf = lane >> 4;
    int brow  = (lane & 7) + ((lane >> 4) & 1) * 8;
    int bhalf = (lane >> 3) & 1;

    auto load_stage = [&](int st, int kk) {
        char* Asd = As + st * ASZB;
        char* Bsd = Bs + st * BSZB;
        #pragma unroll
        for (int v = 0; v < BM * GPR / 256; v++) {
            int idx = t + v * 256;
            int r = idx / GPR, g = idx % GPR;
            cp_async16(smem_u32(Asd + r * ROWB + g * 16),
                       A + (size_t)(m0 + r) * lda + kk + g * 8);
        }
        #pragma unroll
        for (int v = 0; v < BN * GPR / 256; v++) {
            int idx = t + v * 256;
            int r = idx / GPR, g = idx % GPR;
            cp_async16(smem_u32(Bsd + r * ROWB + g * 16),
                       Bm + (size_t)(n0 + r) * ldb + kk + g * 8);
        }
    };

    int nIter = K / BK;
    load_stage(0, 0);
    cp_commit();

    for (int it = 0; it < nIter; ++it) {
        int s = it & 1;
        if (it + 1 < nIter) {
            load_stage(s ^ 1, (it + 1) * BK);
            cp_commit();
            cp_wait<1>();
        } else {
            cp_wait<0>();
        }
        __syncthreads();

        char* Asd = As + s * ASZB;
        char* Bsd = Bs + s * BSZB;
        #pragma unroll
        for (int ks = 0; ks < BK / 16; ks++) {
            unsigned int afr[MFRAG][4];
            #pragma unroll
            for (int mf = 0; mf < MFRAG; mf++) {
                unsigned int addr = smem_u32(
                    Asd + (wm0 + mf * 16 + arow) * ROWB + (ks * 2 + ahalf) * 16);
                ldmatrix_x4(afr[mf], addr);
            }
            unsigned int bfr[NFRAG][2];
            #pragma unroll
            for (int np = 0; np < 4; np++) {
                unsigned int addr = smem_u32(
                    Bsd + (wn0 + np * 16 + brow) * ROWB + (ks * 2 + bhalf) * 16);
                ldmatrix_x4(&bfr[np * 2][0], addr);
            }
            #pragma unroll
            for (int mf = 0; mf < MFRAG; mf++)
                #pragma unroll
                for (int nf = 0; nf < NFRAG; nf++)
                    mma_f16(acc[mf][nf], afr[mf], bfr[nf]);
        }
        __syncthreads();
    }

    // ---- epilogue
    float* Cf = (float*)Cv;
    __half* Ch = (__half*)Cv;
    if (MODE == 1) Cf += strideC * bz;

    #pragma unroll
    for (int mf = 0; mf < MFRAG; mf++) {
        #pragma unroll
        for (int half_ = 0; half_ < 2; half_++) {
            int row = m0 + wm0 + mf * 16 + (lane >> 2) + half_ * 8;
            #pragma unroll
            for (int nf = 0; nf < NFRAG; nf++) {
                int col = n0 + wn0 + nf * 8 + (lane & 3) * 2;
                float v0 = acc[mf][nf][half_ * 2 + 0];
                float v1 = acc[mf][nf][half_ * 2 + 1];
                if constexpr (MODE == 1) {
                    float2 bb = *reinterpret_cast<const float2*>(&bias[col]);
                    float2 rr = *reinterpret_cast<const float2*>(&res[(size_t)row * ldres + col]);
                    *reinterpret_cast<float2*>(&Cf[(size_t)row * ldc + col]) =
                        make_float2(v0 + bb.x + rr.x, v1 + bb.y + rr.y);
                } else {
                    float2 bb = *reinterpret_cast<const float2*>(&bias[col]);
                    v0 += bb.x; v1 += bb.y;
                    v0 = 0.5f * v0 * (1.0f + erff(v0 * 0.70710678118654752f));
                    v1 = 0.5f * v1 * (1.0f + erff(v1 * 0.70710678118654752f));
                    *reinterpret_cast<__half2*>(&Ch[(size_t)row * ldc + col]) =
                        __floats2half2_rn(v0, v1);
                }
            }
        }
    }
    (void)scale;
}

// ---------------------------------------------------------------------------
// FP16 AV GEMM: O = P[Nn x Nn] @ V via V^T [HD x Nn] NT. BM=128, BN=96, BK=64.
// ---------------------------------------------------------------------------
__global__ __launch_bounds__(256, 2)
void mma_gemm_avh(const __half* __restrict__ A, const __half* __restrict__ Bm,
                  __half* __restrict__ Cm,
                  int K, int lda, int ldb, int ldc,
                  size_t strideA, size_t strideB)
{
    constexpr int BM = 128, BN = 96, BK = 64;
    constexpr int ROWB = BK * 2 + 16;         // 144
    constexpr int ASZB = BM * ROWB;
    constexpr int BSZB = BN * ROWB;
    constexpr int MFRAG = 2;
    constexpr int NFRAG = 6;
    constexpr int GPR = BK / 8;               // 8

    extern __shared__ char smem_c[];
    char* As = smem_c;
    char* Bs = smem_c + 2 * ASZB;

    int bz = blockIdx.z;
    A  += strideA * bz;
    Bm += strideB * bz;

    int m0 = blockIdx.y * BM;
    int n0 = blockIdx.x * BN;
    int t    = threadIdx.x;
    int warp = t >> 5, lane = t & 31;
    int wm0 = (warp & 3) * 32;
    int wn0 = (warp >> 2) * 48;

    float acc[MFRAG][NFRAG][4];
    #pragma unroll
    for (int i = 0; i < MFRAG; i++)
        #pragma unroll
        for (int j = 0; j < NFRAG; j++)
            #pragma unroll
            for (int e = 0; e < 4; e++) acc[i][j][e] = 0.f;

    int arow  = lane & 15;
    int ahalf = lane >> 4;
    int brow  = (lane & 7) + ((lane >> 4) & 1) * 8;
    int bhalf = (lane >> 3) & 1;

    auto load_stage = [&](int st, int kk) {
        char* Asd = As + st * ASZB;
        char* Bsd = Bs + st * BSZB;
        #pragma unroll
        for (int v = 0; v < BM * GPR / 256; v++) {   // 4
            int idx = t + v * 256;
            int r = idx / GPR, g = idx % GPR;
            cp_async16(smem_u32(Asd + r * ROWB + g * 16),
                       A + (size_t)(m0 + r) * lda + kk + g * 8);
        }
        #pragma unroll
        for (int v = 0; v < BN * GPR / 256; v++) {   // 3
            int idx = t + v * 256;
            int r = idx / GPR, g = idx % GPR;
            cp_async16(smem_u32(Bsd + r * ROWB + g * 16),
                       Bm + (size_t)(n0 + r) * ldb + kk + g * 8);
        }
    };

    int nIter = K / BK;
    load_stage(0, 0);
    cp_commit();

    for (int it = 0; it < nIter; ++it) {
        int s = it & 1;
        if (it + 1 < nIter) {
            load_stage(s ^ 1, (it + 1) * BK);
            cp_commit();
            cp_wait<1>();
        } else {
            cp_wait<0>();
        }
        __syncthreads();

        char* Asd = As + s * ASZB;
        char* Bsd = Bs + s * BSZB;
        #pragma unroll
        for (int ks = 0; ks < BK / 16; ks++) {
            unsigned int afr[MFRAG][4];
            #pragma unroll
            for (int mf = 0; mf < MFRAG; mf++) {
                unsigned int addr = smem_u32(
                    Asd + (wm0 + mf * 16 + arow) * ROWB + (ks * 2 + ahalf) * 16);
                ldmatrix_x4(afr[mf], addr);
            }
            unsigned int bfr[NFRAG][2];
            #pragma unroll
            for (int np = 0; np < 3; np++) {
                unsigned int addr = smem_u32(
                    Bsd + (wn0 + np * 16 + brow) * ROWB + (ks * 2 + bhalf) * 16);
                ldmatrix_x4(&bfr[np * 2][0], addr);
            }
            #pragma unroll
            for (int mf = 0; mf < MFRAG; mf++)
                #pragma unroll
                for (int nf = 0; nf < NFRAG; nf++)
                    mma_f16(acc[mf][nf], afr[mf], bfr[nf]);
        }
        __syncthreads();
    }

    size_t out_off = (size_t)(bz >> 3) * ((size_t)Nn * Cc) + (size_t)(bz & 7) * HD;
    #pragma unroll
    for (int mf = 0; mf < MFRAG; mf++) {
        #pragma unroll
        for (int half_ = 0; half_ < 2; half_++) {
            int row = m0 + wm0 + mf * 16 + (lane >> 2) + half_ * 8;
            #pragma unroll
            for (int nf = 0; nf < NFRAG; nf++) {
                int col = n0 + wn0 + nf * 8 + (lane & 3) * 2;
                *reinterpret_cast<__half2*>(&Cm[out_off + (size_t)row * ldc + col]) =
                    __floats2half2_rn(acc[mf][nf][half_ * 2 + 0], acc[mf][nf][half_ * 2 + 1]);
            }
        }
    }
}

// ---------------------------------------------------------------------------
// fused per-row softmax (8 heads) + head mix + BN. fp16 scores -> fp16 probs.
// ---------------------------------------------------------------------------
__global__ void softmax_mix_kernel(const float* __restrict__ rw, const float* __restrict__ rb,
                                   const float* __restrict__ bng, const float* __restrict__ bnb)
{
    __shared__ __align__(16) float sp[8][1024];
    __shared__ float s_w[64];
    __shared__ float s_s[8], s_o[8];

    int bn = blockIdx.x;
    int b  = bn >> 10, n = bn & 1023;
    int t  = threadIdx.x;                    // 256

    if (t < 64) s_w[t] = rw[t];
    if (t < 8) {
        float bs = bng[t] * rsqrtf(1.0f + 1e-3f);
        s_s[t] = bs;
        s_o[t] = rb[t] * bs + bnb[t];
    }
    #pragma unroll
    for (int h = 0; h < 8; h++) {
        uint2 raw = reinterpret_cast<const uint2*>(
            g_attn + (((size_t)b * Hh + h) * Nn + n) * Nn)[t];
        __half2 h0 = *reinterpret_cast<__half2*>(&raw.x);
        __half2 h1 = *reinterpret_cast<__half2*>(&raw.y);
        float2 f0 = __half22float2(h0);
        float2 f1 = __half22float2(h1);
        reinterpret_cast<float4*>(sp[h])[t] = make_float4(f0.x, f0.y, f1.x, f1.y);
    }
    __syncthreads();

    int w = t >> 5, lane = t & 31;
    {
        float* sr = sp[w];
        float mx = -1e30f;
        for (int m = lane; m < 1024; m += 32) mx = fmaxf(mx, sr[m]);
        #pragma unroll
        for (int off = 16; off; off >>= 1) mx = fmaxf(mx, __shfl_xor_sync(0xffffffffu, mx, off));
        float sum = 0.f;
        for (int m = lane; m < 1024; m += 32) {
            float e = __expf(sr[m] - mx);
            sr[m] = e;
            sum += e;
        }
        #pragma unroll
        for (int off = 16; off; off >>= 1) sum += __shfl_xor_sync(0xffffffffu, sum, off);
        float inv = 1.0f / sum;
        for (int m = lane; m < 1024; m += 32) sr[m] *= inv;
    }
    __syncthreads();

    float4 p[8];
    #pragma unroll
    for (int h = 0; h < 8; h++) p[h] = reinterpret_cast<const float4*>(sp[h])[t];
    #pragma unroll
    for (int g = 0; g < 8; g++) {
        float4 a = make_float4(0.f, 0.f, 0.f, 0.f);
        #pragma unroll
        for (int h = 0; h < 8; h++) {
            float wgh = s_w[g * 8 + h];
            a.x = fmaf(p[h].x, wgh, a.x);
            a.y = fmaf(p[h].y, wgh, a.y);
            a.z = fmaf(p[h].z, wgh, a.z);
            a.w = fmaf(p[h].w, wgh, a.w);
        }
        float ss = s_s[g], oo = s_o[g];
        a.x = a.x * ss + oo; a.y = a.y * ss + oo;
        a.z = a.z * ss + oo; a.w = a.w * ss + oo;
        __half2 p0 = __floats2half2_rn(a.x, a.y);
        __half2 p1 = __floats2half2_rn(a.z, a.w);
        uint2 packed;
        packed.x = *reinterpret_cast<unsigned int*>(&p0);
        packed.y = *reinterpret_cast<unsigned int*>(&p1);
        reinterpret_cast<uint2*>(
            g_ph + (((size_t)b * Hh + g) * Nn + n) * Nn)[t] = packed;
    }
}

// ---------------------------------------------------------------------------
// LayerNorm over 768. Writes fp32 out; optionally also fp16 copy.
// ---------------------------------------------------------------------------
__global__ void layernorm_kernel(const float* __restrict__ in, float* __restrict__ out,
                                 __half* __restrict__ out16,
                                 const float* __restrict__ g, const float* __restrict__ bta)
{
    __shared__ float red[16];
    __shared__ float s_mu, s_rs;
    int row = blockIdx.x;
    int t   = threadIdx.x;       // 256
    const float* rp = in + (size_t)row * Cc;
    float x0 = rp[t], x1 = rp[t + 256], x2 = rp[t + 512];
    float s  = x0 + x1 + x2;
    float ss = x0 * x0 + x1 * x1 + x2 * x2;
    #pragma unroll
    for (int off = 16; off; off >>= 1) {
        s  += __shfl_xor_sync(0xffffffffu, s, off);
        ss += __shfl_xor_sync(0xffffffffu, ss, off);
    }
    int w = t >> 5, lane = t & 31;
    if (lane == 0) { red[w] = s; red[8 + w] = ss; }
    __syncthreads();
    if (t == 0) {
        float S = 0.f, SS = 0.f;
        #pragma unroll
        for (int i = 0; i < 8; i++) { S += red[i]; SS += red[8 + i]; }
        float mu  = S * (1.0f / 768.0f);
        float var = SS * (1.0f / 768.0f) - mu * mu;
        s_mu = mu;
        s_rs = rsqrtf(var + 1e-3f);
    }
    __syncthreads();
    float mu = s_mu, rs = s_rs;
    float v0 = (x0 - mu) * rs * g[t]       + bta[t];
    float v1 = (x1 - mu) * rs * g[t + 256] + bta[t + 256];
    float v2 = (x2 - mu) * rs * g[t + 512] + bta[t + 512];
    float* op = out + (size_t)row * Cc;
    op[t] = v0; op[t + 256] = v1; op[t + 512] = v2;
    if (out16) {
        __half* oh = out16 + (size_t)row * Cc;
        oh[t] = __float2half(v0);
        oh[t + 256] = __float2half(v1);
        oh[t + 512] = __float2half(v2);
    }
}

// ---------------------------------------------------------------------------
// Host-side launch helpers
// ---------------------------------------------------------------------------
#define SMEM_SC  (2 * 128 * 208)                 // 53248 B (single stage A+B)
#define SMEM_H64 (2 * (128 * 144 + 128 * 144))   // 73728 B (BK=64, 2-stage)
#define SMEM_AVH (2 * (128 * 144 + 96 * 144))    // 64512 B (BK=64, 2-stage)

static void launch_scores(const __half* qh, __half* ap, float scale)
{
    static bool init = false;
    if (!init) {
        cudaFuncSetAttribute((const void*)mma_gemm_sc,
                             cudaFuncAttributeMaxDynamicSharedMemorySize, SMEM_SC);
        init = true;
    }
    mma_gemm_sc<<<dim3(8, 8, 64), 256, SMEM_SC>>>(
        qh, qh, ap, HD, HD, Nn,
        (size_t)Nn * HD, (size_t)Nn * HD, (size_t)Nn * Nn, scale);
}
static void launch_av(const __half* ph, const __half* vt, __half* xh)
{
    static bool init = false;
    if (!init) {
        cudaFuncSetAttribute((const void*)mma_gemm_avh,
                             cudaFuncAttributeMaxDynamicSharedMemorySize, SMEM_AVH);
        init = true;
    }
    mma_gemm_avh<<<dim3(1, 8, 64), 256, SMEM_AVH>>>(
        ph, vt, xh, Nn, Nn, Nn, Cc,
        (size_t)Nn * Nn, (size_t)Nn * HD);
}
static void launch_proj(const __half* xh, const __half* wt, float* yp,
                        const float* b, const float* res)
{
    static bool init = false;
    if (!init) {
        cudaFuncSetAttribute((const void*)mma_gemm_h<64, 1>,
                             cudaFuncAttributeMaxDynamicSharedMemorySize, SMEM_H64);
        init = true;
    }
    mma_gemm_h<64, 1><<<dim3(6, 64, 1), 256, SMEM_H64>>>(
        xh, wt, yp, Cc, Cc, Cc, Cc,
        0, 0, 0, b, res, Cc, 1.0f);
}
static void launch_ffn1(const __half* yh, const __half* wt, __half* hh, const float* b)
{
    static bool init = false;
    if (!init) {
        cudaFuncSetAttribute((const void*)mma_gemm_h<64, 2>,
                             cudaFuncAttributeMaxDynamicSharedMemorySize, SMEM_H64);
        init = true;
    }
    mma_gemm_h<64, 2><<<dim3(24, 64, 1), 256, SMEM_H64>>>(
        yh, wt, hh, Cc, Cc, Cc, DFF,
        0, 0, 0, b, nullptr, 0, 1.0f);
}
static void launch_ffn2(const __half* hh, const __half* wt, float* xp,
                        const float* b, const float* res)
{
    mma_gemm_h<64, 1><<<dim3(6, 64, 1), 256, SMEM_H64>>>(
        hh, wt, xp, DFF, DFF, DFF, Cc,
        0, 0, 0, b, res, Cc, 1.0f);
}

// ---------------------------------------------------------------------------
// Launch
// ---------------------------------------------------------------------------
extern "C" void kernel_launch(void* const* d_in, const int* in_sizes, int n_in,
                              void* d_out, int out_size)
{
    (void)in_sizes; (void)n_in; (void)out_size;
    const float* enc       = (const float*)d_in[0];
    const float* qconv_w   = (const float*)d_in[1];
    const float* reatten_w = (const float*)d_in[2];
    const float* reatten_b = (const float*)d_in[3];
    const float* bn_gamma  = (const float*)d_in[4];
    const float* bn_beta   = (const float*)d_in[5];
    const float* proj_w    = (const float*)d_in[6];
    const float* proj_b    = (const float*)d_in[7];
    const float* ffn_w1    = (const float*)d_in[8];
    const float* ffn_b1    = (const float*)d_in[9];
    const float* ffn_w2    = (const float*)d_in[10];
    const float* ffn_b2    = (const float*)d_in[11];
    const float* ln1_g     = (const float*)d_in[12];
    const float* ln1_b     = (const float*)d_in[13];
    const float* ln2_g     = (const float*)d_in[14];
    const float* ln2_b     = (const float*)d_in[15];
    float* out = (float*)d_out;

    float *yp, *xp;
    __half *qh, *vtp, *ap, *ph, *xh, *yh, *hh, *pwt, *w1t, *w2t;
    cudaGetSymbolAddress((void**)&qh,  g_qh);
    cudaGetSymbolAddress((void**)&vtp, g_vt);
    cudaGetSymbolAddress((void**)&ap,  g_attn);
    cudaGetSymbolAddress((void**)&ph,  g_ph);
    cudaGetSymbolAddress((void**)&xh,  g_xh);
    cudaGetSymbolAddress((void**)&yp,  g_y);
    cudaGetSymbolAddress((void**)&yh,  g_yh);
    cudaGetSymbolAddress((void**)&hh,  g_hh);
    cudaGetSymbolAddress((void**)&xp,  g_x);
    cudaGetSymbolAddress((void**)&pwt, g_pwt);
    cudaGetSymbolAddress((void**)&w1t, g_w1t);
    cudaGetSymbolAddress((void**)&w2t, g_w2t);

    const float scale = 0.1020620726159658f;   // 96^-0.5

    // weight transposes ([K][N] fp32 -> [N][K] fp16)
    transpose_f2h_kernel<<<dim3(24, 24, 1), dim3(32, 8)>>>(proj_w, pwt, Cc, Cc, 0, 0);
    transpose_f2h_kernel<<<dim3(96, 24, 1), dim3(32, 8)>>>(ffn_w1, w1t, Cc, DFF, 0, 0);
    transpose_f2h_kernel<<<dim3(24, 96, 1), dim3(32, 8)>>>(ffn_w2, w2t, DFF, Cc, 0, 0);

    qconv_kernel<<<NT_, 256>>>(enc, qconv_w);
    transpose_h2h_kernel<<<dim3(3, 32, 64), dim3(32, 8)>>>(qh, vtp, Nn, HD,
                                                           (size_t)Nn * HD, (size_t)Nn * HD);

    launch_scores(qh, ap, scale);
    softmax_mix_kernel<<<NT_, 256>>>(reatten_w, reatten_b, bn_gamma, bn_beta);
    launch_av(ph, vtp, xh);
    launch_proj(xh, pwt, yp, proj_b, enc);
    layernorm_kernel<<<NT_, 256>>>(yp, yp, yh, ln1_g, ln1_b);
    launch_ffn1(yh, w1t, hh, ffn_b1);
    launch_ffn2(hh, w2t, xp, ffn_b2, yp);
    layernorm_kernel<<<NT_, 256>>>(xp, out, nullptr, ln2_g, ln2_b);
}

// round 16
// speedup vs baseline: 2.0226x; 1.0354x over previous
#include <cuda_runtime.h>
#include <cuda_bf16.h>
#include <cuda_fp16.h>
#include <cstdint>
#include <math.h>

// Problem constants
#define Bb   8
#define Nn   1024
#define Cc   768
#define Hh   8
#define HD   96
#define DFF  3072
#define NT_  (Bb * Nn)          // 8192 tokens

// ---------------------------------------------------------------------------
// Scratch (device globals — no allocation allowed)
// ---------------------------------------------------------------------------
__device__ __half g_qh[(size_t)Bb * Hh * Nn * HD];         // q fp16 [b][h][n][d]
__device__ __half g_vt[(size_t)Bb * Hh * HD * Nn];         // V^T fp16 [b][h][d][n]
__device__ __half g_attn[(size_t)Bb * Hh * Nn * Nn];       // scores fp16
__device__ __half g_ph[(size_t)Bb * Hh * Nn * Nn];         // probs fp16
__device__ __half g_xh[(size_t)NT_ * Cc];                  // attn-out fp16 (proj A)
__device__ float  g_y[(size_t)NT_ * Cc];                   // LN1 out fp32 (residual)
__device__ __half g_yh[(size_t)NT_ * Cc];                  // LN1 out fp16 (ffn1 A)
__device__ __half g_hh[(size_t)NT_ * DFF];                 // ffn hidden fp16
__device__ float  g_x[(size_t)NT_ * Cc];                   // proj-out / ffn2-out fp32
__device__ __half g_pwt[(size_t)Cc * Cc];                  // proj_w^T fp16
__device__ __half g_w1t[(size_t)DFF * Cc];                 // ffn_w1^T fp16
__device__ __half g_w2t[(size_t)Cc * DFF];                 // ffn_w2^T fp16

// ---------------------------------------------------------------------------
// helpers
// ---------------------------------------------------------------------------
__device__ __forceinline__ unsigned int smem_u32(const void* p) {
    return (unsigned int)__cvta_generic_to_shared(p);
}
__device__ __forceinline__ void cp_async16(unsigned int dst, const void* src) {
    asm volatile("cp.async.ca.shared.global [%0], [%1], 16;\n" :: "r"(dst), "l"(src));
}
__device__ __forceinline__ void cp_commit() {
    asm volatile("cp.async.commit_group;\n");
}
template<int N>
__device__ __forceinline__ void cp_wait() {
    asm volatile("cp.async.wait_group %0;\n" :: "n"(N));
}
__device__ __forceinline__ void ldmatrix_x4(unsigned int* r, unsigned int addr) {
    asm volatile("ldmatrix.sync.aligned.m8n8.x4.shared.b16 {%0,%1,%2,%3}, [%4];"
                 : "=r"(r[0]), "=r"(r[1]), "=r"(r[2]), "=r"(r[3]) : "r"(addr));
}
__device__ __forceinline__ void mma_f16(float* c, const unsigned int* a, const unsigned int* b) {
    asm volatile(
        "mma.sync.aligned.m16n8k16.row.col.f32.f16.f16.f32 "
        "{%0,%1,%2,%3}, {%4,%5,%6,%7}, {%8,%9}, {%0,%1,%2,%3};"
        : "+f"(c[0]), "+f"(c[1]), "+f"(c[2]), "+f"(c[3])
        : "r"(a[0]), "r"(a[1]), "r"(a[2]), "r"(a[3]), "r"(b[0]), "r"(b[1]));
}

// ---------------------------------------------------------------------------
// Kernel 1: per-patch 3x3 conv, q=k=v, write fp16 [b][h][n][d]
// ---------------------------------------------------------------------------
__global__ void qconv_kernel(const float* __restrict__ x, const float* __restrict__ w)
{
    __shared__ float s_in[768];
    __shared__ float s_w[81];
    int bn = blockIdx.x;
    int b  = bn >> 10, n = bn & 1023;
    int t  = threadIdx.x;                // 256
    const float* xin = x + (size_t)bn * 768;
    s_in[t]       = xin[t];
    s_in[t + 256] = xin[t + 256];
    s_in[t + 512] = xin[t + 512];
    if (t < 81) s_w[t] = w[t];
    __syncthreads();

    int r = t >> 4, c = t & 15;
    float acc0 = 0.f, acc1 = 0.f, acc2 = 0.f;
    #pragma unroll
    for (int kh = 0; kh < 3; kh++) {
        int rr = r + kh - 1;
        if (rr < 0 || rr > 15) continue;
        #pragma unroll
        for (int kw = 0; kw < 3; kw++) {
            int cc = c + kw - 1;
            if (cc < 0 || cc > 15) continue;
            const float* wp = s_w + (kh * 3 + kw) * 9;
            int ip = (rr * 16 + cc) * 3;
            #pragma unroll
            for (int ci = 0; ci < 3; ci++) {
                float v = s_in[ip + ci];
                acc0 += v * wp[ci * 3 + 0];
                acc1 += v * wp[ci * 3 + 1];
                acc2 += v * wp[ci * 3 + 2];
            }
        }
    }
    float accs[3] = {acc0, acc1, acc2};
    #pragma unroll
    for (int co = 0; co < 3; co++) {
        int cidx = t * 3 + co;
        int h = cidx / HD, d = cidx % HD;
        g_qh[(((size_t)b * Hh + h) * Nn + n) * HD + d] = __float2half(accs[co]);
    }
}

// ---------------------------------------------------------------------------
// Transpose fp32 -> fp16: in[z][R][C] fp32 -> out[z][C][R] fp16. Block (32,8).
// ---------------------------------------------------------------------------
__global__ void transpose_f2h_kernel(const float* __restrict__ in,
                                     __half* __restrict__ out,
                                     int R, int C, size_t sIn, size_t sOut)
{
    __shared__ float tile[32][33];
    int z = blockIdx.z;
    const float* ip = in + (size_t)z * sIn;
    __half* op = out + (size_t)z * sOut;
    int c0 = blockIdx.x * 32, r0 = blockIdx.y * 32;
    int tx = threadIdx.x, ty = threadIdx.y;
    #pragma unroll
    for (int j = 0; j < 4; j++)
        tile[ty + 8 * j][tx] = ip[(size_t)(r0 + ty + 8 * j) * C + c0 + tx];
    __syncthreads();
    #pragma unroll
    for (int j = 0; j < 4; j++)
        op[(size_t)(c0 + ty + 8 * j) * R + r0 + tx] = __float2half(tile[tx][ty + 8 * j]);
}

// ---------------------------------------------------------------------------
// Transpose fp16 -> fp16: in[z][R][C] -> out[z][C][R]. (for V^T from g_qh)
// ---------------------------------------------------------------------------
__global__ void transpose_h2h_kernel(const __half* __restrict__ in,
                                     __half* __restrict__ out,
                                     int R, int C, size_t sIn, size_t sOut)
{
    __shared__ float tile[32][33];
    int z = blockIdx.z;
    const __half* ip = in + (size_t)z * sIn;
    __half* op = out + (size_t)z * sOut;
    int c0 = blockIdx.x * 32, r0 = blockIdx.y * 32;
    int tx = threadIdx.x, ty = threadIdx.y;
    #pragma unroll
    for (int j = 0; j < 4; j++)
        tile[ty + 8 * j][tx] = __half2float(ip[(size_t)(r0 + ty + 8 * j) * C + c0 + tx]);
    __syncthreads();
    #pragma unroll
    for (int j = 0; j < 4; j++)
        op[(size_t)(c0 + ty + 8 * j) * R + r0 + tx] = __float2half(tile[tx][ty + 8 * j]);
}

// ---------------------------------------------------------------------------
// Scores GEMM, single-stage: K=96 entirely in smem (no mainloop).
// ---------------------------------------------------------------------------
__global__ __launch_bounds__(256, 2)
void mma_gemm_sc(const __half* __restrict__ A, const __half* __restrict__ Bm,
                 __half* __restrict__ Cm,
                 int lda, int ldb, int ldc,
                 size_t strideA, size_t strideB, size_t strideC, float scale)
{
    constexpr int BM = 128, BN = 128, KK = 96;
    constexpr int ROWB = KK * 2 + 16;          // 208
    constexpr int ASZB = BM * ROWB;
    constexpr int MFRAG = 2;
    constexpr int NFRAG = 8;
    constexpr int GPR = KK / 8;                // 12

    extern __shared__ char smem_c[];
    char* As = smem_c;
    char* Bs = smem_c + ASZB;

    int bz = blockIdx.z;
    A  += strideA * bz;
    Bm += strideB * bz;
    Cm += strideC * bz;

    int m0 = blockIdx.y * BM;
    int n0 = blockIdx.x * BN;
    int t    = threadIdx.x;
    int warp = t >> 5, lane = t & 31;
    int wm0 = (warp & 3) * 32;
    int wn0 = (warp >> 2) * 64;

    float acc[MFRAG][NFRAG][4];
    #pragma unroll
    for (int i = 0; i < MFRAG; i++)
        #pragma unroll
        for (int j = 0; j < NFRAG; j++)
            #pragma unroll
            for (int e = 0; e < 4; e++) acc[i][j][e] = 0.f;

    int arow  = lane & 15;
    int ahalf = lane >> 4;
    int brow  = (lane & 7) + ((lane >> 4) & 1) * 8;
    int bhalf = (lane >> 3) & 1;

    #pragma unroll
    for (int v = 0; v < BM * GPR / 256; v++) {
        int idx = t + v * 256;
        int r = idx / GPR, g = idx % GPR;
        cp_async16(smem_u32(As + r * ROWB + g * 16),
                   A + (size_t)(m0 + r) * lda + g * 8);
    }
    #pragma unroll
    for (int v = 0; v < BN * GPR / 256; v++) {
        int idx = t + v * 256;
        int r = idx / GPR, g = idx % GPR;
        cp_async16(smem_u32(Bs + r * ROWB + g * 16),
                   Bm + (size_t)(n0 + r) * ldb + g * 8);
    }
    cp_commit();
    cp_wait<0>();
    __syncthreads();

    #pragma unroll
    for (int ks = 0; ks < KK / 16; ks++) {
        unsigned int afr[MFRAG][4];
        #pragma unroll
        for (int mf = 0; mf < MFRAG; mf++) {
            unsigned int addr = smem_u32(
                As + (wm0 + mf * 16 + arow) * ROWB + (ks * 2 + ahalf) * 16);
            ldmatrix_x4(afr[mf], addr);
        }
        unsigned int bfr[NFRAG][2];
        #pragma unroll
        for (int np = 0; np < 4; np++) {
            unsigned int addr = smem_u32(
                Bs + (wn0 + np * 16 + brow) * ROWB + (ks * 2 + bhalf) * 16);
            ldmatrix_x4(&bfr[np * 2][0], addr);
        }
        #pragma unroll
        for (int mf = 0; mf < MFRAG; mf++)
            #pragma unroll
            for (int nf = 0; nf < NFRAG; nf++)
                mma_f16(acc[mf][nf], afr[mf], bfr[nf]);
    }

    #pragma unroll
    for (int mf = 0; mf < MFRAG; mf++) {
        #pragma unroll
        for (int half_ = 0; half_ < 2; half_++) {
            int row = m0 + wm0 + mf * 16 + (lane >> 2) + half_ * 8;
            #pragma unroll
            for (int nf = 0; nf < NFRAG; nf++) {
                int col = n0 + wn0 + nf * 8 + (lane & 3) * 2;
                *reinterpret_cast<__half2*>(&Cm[(size_t)row * ldc + col]) =
                    __floats2half2_rn(acc[mf][nf][half_ * 2 + 0] * scale,
                                      acc[mf][nf][half_ * 2 + 1] * scale);
            }
        }
    }
}

// ---------------------------------------------------------------------------
// FP16 tensor-core GEMM (NT), BK=64, cp.async 2-stage.
// MODE 1: fp32 C = acc+bias+res | MODE 2: fp16 C = gelu(acc+bias)
// ---------------------------------------------------------------------------
template<int BK, int MODE>
__global__ __launch_bounds__(256, 2)
void mma_gemm_h(const __half* __restrict__ A, const __half* __restrict__ Bm,
                void* __restrict__ Cv,
                int K, int lda, int ldb, int ldc,
                size_t strideA, size_t strideB, size_t strideC,
                const float* __restrict__ bias, const float* __restrict__ res,
                int ldres, float scale)
{
    constexpr int BM = 128, BN = 128;
    constexpr int ROWB = BK * 2 + 16;
    constexpr int ASZB = BM * ROWB;
    constexpr int BSZB = BN * ROWB;
    constexpr int MFRAG = 2;
    constexpr int NFRAG = 8;
    constexpr int GPR = BK / 8;

    extern __shared__ char smem_c[];
    char* As = smem_c;
    char* Bs = smem_c + 2 * ASZB;

    int bz = blockIdx.z;
    A  += strideA * bz;
    Bm += strideB * bz;

    int m0 = blockIdx.y * BM;
    int n0 = blockIdx.x * BN;
    int t    = threadIdx.x;
    int warp = t >> 5, lane = t & 31;
    int wm0 = (warp & 3) * 32;
    int wn0 = (warp >> 2) * 64;

    float acc[MFRAG][NFRAG][4];
    #pragma unroll
    for (int i = 0; i < MFRAG; i++)
        #pragma unroll
        for (int j = 0; j < NFRAG; j++)
            #pragma unroll
            for (int e = 0; e < 4; e++) acc[i][j][e] = 0.f;

    int arow  = lane & 15;
    int ahalf = lane >> 4;
    int brow  = (lane & 7) + ((lane >> 4) & 1) * 8;
    int bhalf = (lane >> 3) & 1;

    auto load_stage = [&](int st, int kk) {
        char* Asd = As + st * ASZB;
        char* Bsd = Bs + st * BSZB;
        #pragma unroll
        for (int v = 0; v < BM * GPR / 256; v++) {
            int idx = t + v * 256;
            int r = idx / GPR, g = idx % GPR;
            cp_async16(smem_u32(Asd + r * ROWB + g * 16),
                       A + (size_t)(m0 + r) * lda + kk + g * 8);
        }
        #pragma unroll
        for (int v = 0; v < BN * GPR / 256; v++) {
            int idx = t + v * 256;
            int r = idx / GPR, g = idx % GPR;
            cp_async16(smem_u32(Bsd + r * ROWB + g * 16),
                       Bm + (size_t)(n0 + r) * ldb + kk + g * 8);
        }
    };

    int nIter = K / BK;
    load_stage(0, 0);
    cp_commit();

    for (int it = 0; it < nIter; ++it) {
        int s = it & 1;
        if (it + 1 < nIter) {
            load_stage(s ^ 1, (it + 1) * BK);
            cp_commit();
            cp_wait<1>();
        } else {
            cp_wait<0>();
        }
        __syncthreads();

        char* Asd = As + s * ASZB;
        char* Bsd = Bs + s * BSZB;
        #pragma unroll
        for (int ks = 0; ks < BK / 16; ks++) {
            unsigned int afr[MFRAG][4];
            #pragma unroll
            for (int mf = 0; mf < MFRAG; mf++) {
                unsigned int addr = smem_u32(
                    Asd + (wm0 + mf * 16 + arow) * ROWB + (ks * 2 + ahalf) * 16);
                ldmatrix_x4(afr[mf], addr);
            }
            unsigned int bfr[NFRAG][2];
            #pragma unroll
            for (int np = 0; np < 4; np++) {
                unsigned int addr = smem_u32(
                    Bsd + (wn0 + np * 16 + brow) * ROWB + (ks * 2 + bhalf) * 16);
                ldmatrix_x4(&bfr[np * 2][0], addr);
            }
            #pragma unroll
            for (int mf = 0; mf < MFRAG; mf++)
                #pragma unroll
                for (int nf = 0; nf < NFRAG; nf++)
                    mma_f16(acc[mf][nf], afr[mf], bfr[nf]);
        }
        __syncthreads();
    }

    // ---- epilogue
    float* Cf = (float*)Cv;
    __half* Ch = (__half*)Cv;
    if (MODE == 1) Cf += strideC * bz;

    #pragma unroll
    for (int mf = 0; mf < MFRAG; mf++) {
        #pragma unroll
        for (int half_ = 0; half_ < 2; half_++) {
            int row = m0 + wm0 + mf * 16 + (lane >> 2) + half_ * 8;
            #pragma unroll
            for (int nf = 0; nf < NFRAG; nf++) {
                int col = n0 + wn0 + nf * 8 + (lane & 3) * 2;
                float v0 = acc[mf][nf][half_ * 2 + 0];
                float v1 = acc[mf][nf][half_ * 2 + 1];
                if constexpr (MODE == 1) {
                    float2 bb = *reinterpret_cast<const float2*>(&bias[col]);
                    float2 rr = *reinterpret_cast<const float2*>(&res[(size_t)row * ldres + col]);
                    *reinterpret_cast<float2*>(&Cf[(size_t)row * ldc + col]) =
                        make_float2(v0 + bb.x + rr.x, v1 + bb.y + rr.y);
                } else {
                    float2 bb = *reinterpret_cast<const float2*>(&bias[col]);
                    v0 += bb.x; v1 += bb.y;
                    v0 = 0.5f * v0 * (1.0f + erff(v0 * 0.70710678118654752f));
                    v1 = 0.5f * v1 * (1.0f + erff(v1 * 0.70710678118654752f));
                    *reinterpret_cast<__half2*>(&Ch[(size_t)row * ldc + col]) =
                        __floats2half2_rn(v0, v1);
                }
            }
        }
    }
    (void)scale;
}

// ---------------------------------------------------------------------------
// FP16 AV GEMM: O = P[Nn x Nn] @ V via V^T [HD x Nn] NT. BM=128, BN=96, BK=64.
// ---------------------------------------------------------------------------
__global__ __launch_bounds__(256, 2)
void mma_gemm_avh(const __half* __restrict__ A, const __half* __restrict__ Bm,
                  __half* __restrict__ Cm,
                  int K, int lda, int ldb, int ldc,
                  size_t strideA, size_t strideB)
{
    constexpr int BM = 128, BN = 96, BK = 64;
    constexpr int ROWB = BK * 2 + 16;         // 144
    constexpr int ASZB = BM * ROWB;
    constexpr int BSZB = BN * ROWB;
    constexpr int MFRAG = 2;
    constexpr int NFRAG = 6;
    constexpr int GPR = BK / 8;               // 8

    extern __shared__ char smem_c[];
    char* As = smem_c;
    char* Bs = smem_c + 2 * ASZB;

    int bz = blockIdx.z;
    A  += strideA * bz;
    Bm += strideB * bz;

    int m0 = blockIdx.y * BM;
    int n0 = blockIdx.x * BN;
    int t    = threadIdx.x;
    int warp = t >> 5, lane = t & 31;
    int wm0 = (warp & 3) * 32;
    int wn0 = (warp >> 2) * 48;

    float acc[MFRAG][NFRAG][4];
    #pragma unroll
    for (int i = 0; i < MFRAG; i++)
        #pragma unroll
        for (int j = 0; j < NFRAG; j++)
            #pragma unroll
            for (int e = 0; e < 4; e++) acc[i][j][e] = 0.f;

    int arow  = lane & 15;
    int ahalf = lane >> 4;
    int brow  = (lane & 7) + ((lane >> 4) & 1) * 8;
    int bhalf = (lane >> 3) & 1;

    auto load_stage = [&](int st, int kk) {
        char* Asd = As + st * ASZB;
        char* Bsd = Bs + st * BSZB;
        #pragma unroll
        for (int v = 0; v < BM * GPR / 256; v++) {   // 4
            int idx = t + v * 256;
            int r = idx / GPR, g = idx % GPR;
            cp_async16(smem_u32(Asd + r * ROWB + g * 16),
                       A + (size_t)(m0 + r) * lda + kk + g * 8);
        }
        #pragma unroll
        for (int v = 0; v < BN * GPR / 256; v++) {   // 3
            int idx = t + v * 256;
            int r = idx / GPR, g = idx % GPR;
            cp_async16(smem_u32(Bsd + r * ROWB + g * 16),
                       Bm + (size_t)(n0 + r) * ldb + kk + g * 8);
        }
    };

    int nIter = K / BK;
    load_stage(0, 0);
    cp_commit();

    for (int it = 0; it < nIter; ++it) {
        int s = it & 1;
        if (it + 1 < nIter) {
            load_stage(s ^ 1, (it + 1) * BK);
            cp_commit();
            cp_wait<1>();
        } else {
            cp_wait<0>();
        }
        __syncthreads();

        char* Asd = As + s * ASZB;
        char* Bsd = Bs + s * BSZB;
        #pragma unroll
        for (int ks = 0; ks < BK / 16; ks++) {
            unsigned int afr[MFRAG][4];
            #pragma unroll
            for (int mf = 0; mf < MFRAG; mf++) {
                unsigned int addr = smem_u32(
                    Asd + (wm0 + mf * 16 + arow) * ROWB + (ks * 2 + ahalf) * 16);
                ldmatrix_x4(afr[mf], addr);
            }
            unsigned int bfr[NFRAG][2];
            #pragma unroll
            for (int np = 0; np < 3; np++) {
                unsigned int addr = smem_u32(
                    Bsd + (wn0 + np * 16 + brow) * ROWB + (ks * 2 + bhalf) * 16);
                ldmatrix_x4(&bfr[np * 2][0], addr);
            }
            #pragma unroll
            for (int mf = 0; mf < MFRAG; mf++)
                #pragma unroll
                for (int nf = 0; nf < NFRAG; nf++)
                    mma_f16(acc[mf][nf], afr[mf], bfr[nf]);
        }
        __syncthreads();
    }

    size_t out_off = (size_t)(bz >> 3) * ((size_t)Nn * Cc) + (size_t)(bz & 7) * HD;
    #pragma unroll
    for (int mf = 0; mf < MFRAG; mf++) {
        #pragma unroll
        for (int half_ = 0; half_ < 2; half_++) {
            int row = m0 + wm0 + mf * 16 + (lane >> 2) + half_ * 8;
            #pragma unroll
            for (int nf = 0; nf < NFRAG; nf++) {
                int col = n0 + wn0 + nf * 8 + (lane & 3) * 2;
                *reinterpret_cast<__half2*>(&Cm[out_off + (size_t)row * ldc + col]) =
                    __floats2half2_rn(acc[mf][nf][half_ * 2 + 0], acc[mf][nf][half_ * 2 + 1]);
            }
        }
    }
}

// ---------------------------------------------------------------------------
// fused softmax (no max shift; scores bounded) + head mix + BN.
// Register-resident: thread t owns m=4t..4t+3 for all 8 heads. One sync.
// ---------------------------------------------------------------------------
__global__ void softmax_mix_kernel(const float* __restrict__ rw, const float* __restrict__ rb,
                                   const float* __restrict__ bng, const float* __restrict__ bnb)
{
    __shared__ float red[8][8];          // [warp][head]
    __shared__ float s_w[64];
    __shared__ float s_s[8], s_o[8];

    int bn = blockIdx.x;
    int b  = bn >> 10, n = bn & 1023;
    int t  = threadIdx.x;                // 256
    int w  = t >> 5, lane = t & 31;

    if (t < 64) s_w[t] = rw[t];
    if (t < 8) {
        float bs = bng[t] * rsqrtf(1.0f + 1e-3f);
        s_s[t] = bs;
        s_o[t] = rb[t] * bs + bnb[t];
    }

    // load scores, exponentiate in registers, accumulate per-head partial sums
    float4 p[8];
    float psum[8];
    #pragma unroll
    for (int h = 0; h < 8; h++) {
        uint2 raw = reinterpret_cast<const uint2*>(
            g_attn + (((size_t)b * Hh + h) * Nn + n) * Nn)[t];
        __half2 h0 = *reinterpret_cast<__half2*>(&raw.x);
        __half2 h1 = *reinterpret_cast<__half2*>(&raw.y);
        float2 f0 = __half22float2(h0);
        float2 f1 = __half22float2(h1);
        float4 e;
        e.x = __expf(f0.x); e.y = __expf(f0.y);
        e.z = __expf(f1.x); e.w = __expf(f1.y);
        p[h] = e;
        psum[h] = (e.x + e.y) + (e.z + e.w);
    }
    // warp reduction per head
    #pragma unroll
    for (int h = 0; h < 8; h++) {
        #pragma unroll
        for (int off = 16; off; off >>= 1)
            psum[h] += __shfl_xor_sync(0xffffffffu, psum[h], off);
    }
    if (lane == 0) {
        #pragma unroll
        for (int h = 0; h < 8; h++) red[w][h] = psum[h];
    }
    __syncthreads();

    // block total + normalize p in registers
    #pragma unroll
    for (int h = 0; h < 8; h++) {
        float s = 0.f;
        #pragma unroll
        for (int ww = 0; ww < 8; ww++) s += red[ww][h];
        float inv = 1.0f / s;
        p[h].x *= inv; p[h].y *= inv; p[h].z *= inv; p[h].w *= inv;
    }

    // head mix + BN, write fp16
    #pragma unroll
    for (int g = 0; g < 8; g++) {
        float4 a = make_float4(0.f, 0.f, 0.f, 0.f);
        #pragma unroll
        for (int h = 0; h < 8; h++) {
            float wgh = s_w[g * 8 + h];
            a.x = fmaf(p[h].x, wgh, a.x);
            a.y = fmaf(p[h].y, wgh, a.y);
            a.z = fmaf(p[h].z, wgh, a.z);
            a.w = fmaf(p[h].w, wgh, a.w);
        }
        float ss = s_s[g], oo = s_o[g];
        a.x = a.x * ss + oo; a.y = a.y * ss + oo;
        a.z = a.z * ss + oo; a.w = a.w * ss + oo;
        __half2 p0 = __floats2half2_rn(a.x, a.y);
        __half2 p1 = __floats2half2_rn(a.z, a.w);
        uint2 packed;
        packed.x = *reinterpret_cast<unsigned int*>(&p0);
        packed.y = *reinterpret_cast<unsigned int*>(&p1);
        reinterpret_cast<uint2*>(
            g_ph + (((size_t)b * Hh + g) * Nn + n) * Nn)[t] = packed;
    }
}

// ---------------------------------------------------------------------------
// LayerNorm over 768. Writes fp32 out; optionally also fp16 copy.
// ---------------------------------------------------------------------------
__global__ void layernorm_kernel(const float* __restrict__ in, float* __restrict__ out,
                                 __half* __restrict__ out16,
                                 const float* __restrict__ g, const float* __restrict__ bta)
{
    __shared__ float red[16];
    __shared__ float s_mu, s_rs;
    int row = blockIdx.x;
    int t   = threadIdx.x;       // 256
    const float* rp = in + (size_t)row * Cc;
    float x0 = rp[t], x1 = rp[t + 256], x2 = rp[t + 512];
    float s  = x0 + x1 + x2;
    float ss = x0 * x0 + x1 * x1 + x2 * x2;
    #pragma unroll
    for (int off = 16; off; off >>= 1) {
        s  += __shfl_xor_sync(0xffffffffu, s, off);
        ss += __shfl_xor_sync(0xffffffffu, ss, off);
    }
    int w = t >> 5, lane = t & 31;
    if (lane == 0) { red[w] = s; red[8 + w] = ss; }
    __syncthreads();
    if (t == 0) {
        float S = 0.f, SS = 0.f;
        #pragma unroll
        for (int i = 0; i < 8; i++) { S += red[i]; SS += red[8 + i]; }
        float mu  = S * (1.0f / 768.0f);
        float var = SS * (1.0f / 768.0f) - mu * mu;
        s_mu = mu;
        s_rs = rsqrtf(var + 1e-3f);
    }
    __syncthreads();
    float mu = s_mu, rs = s_rs;
    float v0 = (x0 - mu) * rs * g[t]       + bta[t];
    float v1 = (x1 - mu) * rs * g[t + 256] + bta[t + 256];
    float v2 = (x2 - mu) * rs * g[t + 512] + bta[t + 512];
    float* op = out + (size_t)row * Cc;
    op[t] = v0; op[t + 256] = v1; op[t + 512] = v2;
    if (out16) {
        __half* oh = out16 + (size_t)row * Cc;
        oh[t] = __float2half(v0);
        oh[t + 256] = __float2half(v1);
        oh[t + 512] = __float2half(v2);
    }
}

// ---------------------------------------------------------------------------
// Host-side launch helpers
// ---------------------------------------------------------------------------
#define SMEM_SC  (2 * 128 * 208)                 // 53248 B
#define SMEM_H64 (2 * (128 * 144 + 128 * 144))   // 73728 B
#define SMEM_AVH (2 * (128 * 144 + 96 * 144))    // 64512 B

static void launch_scores(const __half* qh, __half* ap, float scale)
{
    static bool init = false;
    if (!init) {
        cudaFuncSetAttribute((const void*)mma_gemm_sc,
                             cudaFuncAttributeMaxDynamicSharedMemorySize, SMEM_SC);
        init = true;
    }
    mma_gemm_sc<<<dim3(8, 8, 64), 256, SMEM_SC>>>(
        qh, qh, ap, HD, HD, Nn,
        (size_t)Nn * HD, (size_t)Nn * HD, (size_t)Nn * Nn, scale);
}
static void launch_av(const __half* ph, const __half* vt, __half* xh)
{
    static bool init = false;
    if (!init) {
        cudaFuncSetAttribute((const void*)mma_gemm_avh,
                             cudaFuncAttributeMaxDynamicSharedMemorySize, SMEM_AVH);
        init = true;
    }
    mma_gemm_avh<<<dim3(1, 8, 64), 256, SMEM_AVH>>>(
        ph, vt, xh, Nn, Nn, Nn, Cc,
        (size_t)Nn * Nn, (size_t)Nn * HD);
}
static void launch_proj(const __half* xh, const __half* wt, float* yp,
                        const float* b, const float* res)
{
    static bool init = false;
    if (!init) {
        cudaFuncSetAttribute((const void*)mma_gemm_h<64, 1>,
                             cudaFuncAttributeMaxDynamicSharedMemorySize, SMEM_H64);
        init = true;
    }
    mma_gemm_h<64, 1><<<dim3(6, 64, 1), 256, SMEM_H64>>>(
        xh, wt, yp, Cc, Cc, Cc, Cc,
        0, 0, 0, b, res, Cc, 1.0f);
}
static void launch_ffn1(const __half* yh, const __half* wt, __half* hh, const float* b)
{
    static bool init = false;
    if (!init) {
        cudaFuncSetAttribute((const void*)mma_gemm_h<64, 2>,
                             cudaFuncAttributeMaxDynamicSharedMemorySize, SMEM_H64);
        init = true;
    }
    mma_gemm_h<64, 2><<<dim3(24, 64, 1), 256, SMEM_H64>>>(
        yh, wt, hh, Cc, Cc, Cc, DFF,
        0, 0, 0, b, nullptr, 0, 1.0f);
}
static void launch_ffn2(const __half* hh, const __half* wt, float* xp,
                        const float* b, const float* res)
{
    mma_gemm_h<64, 1><<<dim3(6, 64, 1), 256, SMEM_H64>>>(
        hh, wt, xp, DFF, DFF, DFF, Cc,
        0, 0, 0, b, res, Cc, 1.0f);
}

// ---------------------------------------------------------------------------
// Launch
// ---------------------------------------------------------------------------
extern "C" void kernel_launch(void* const* d_in, const int* in_sizes, int n_in,
                              void* d_out, int out_size)
{
    (void)in_sizes; (void)n_in; (void)out_size;
    const float* enc       = (const float*)d_in[0];
    const float* qconv_w   = (const float*)d_in[1];
    const float* reatten_w = (const float*)d_in[2];
    const float* reatten_b = (const float*)d_in[3];
    const float* bn_gamma  = (const float*)d_in[4];
    const float* bn_beta   = (const float*)d_in[5];
    const float* proj_w    = (const float*)d_in[6];
    const float* proj_b    = (const float*)d_in[7];
    const float* ffn_w1    = (const float*)d_in[8];
    const float* ffn_b1    = (const float*)d_in[9];
    const float* ffn_w2    = (const float*)d_in[10];
    const float* ffn_b2    = (const float*)d_in[11];
    const float* ln1_g     = (const float*)d_in[12];
    const float* ln1_b     = (const float*)d_in[13];
    const float* ln2_g     = (const float*)d_in[14];
    const float* ln2_b     = (const float*)d_in[15];
    float* out = (float*)d_out;

    float *yp, *xp;
    __half *qh, *vtp, *ap, *ph, *xh, *yh, *hh, *pwt, *w1t, *w2t;
    cudaGetSymbolAddress((void**)&qh,  g_qh);
    cudaGetSymbolAddress((void**)&vtp, g_vt);
    cudaGetSymbolAddress((void**)&ap,  g_attn);
    cudaGetSymbolAddress((void**)&ph,  g_ph);
    cudaGetSymbolAddress((void**)&xh,  g_xh);
    cudaGetSymbolAddress((void**)&yp,  g_y);
    cudaGetSymbolAddress((void**)&yh,  g_yh);
    cudaGetSymbolAddress((void**)&hh,  g_hh);
    cudaGetSymbolAddress((void**)&xp,  g_x);
    cudaGetSymbolAddress((void**)&pwt, g_pwt);
    cudaGetSymbolAddress((void**)&w1t, g_w1t);
    cudaGetSymbolAddress((void**)&w2t, g_w2t);

    const float scale = 0.1020620726159658f;   // 96^-0.5

    // weight transposes ([K][N] fp32 -> [N][K] fp16)
    transpose_f2h_kernel<<<dim3(24, 24, 1), dim3(32, 8)>>>(proj_w, pwt, Cc, Cc, 0, 0);
    transpose_f2h_kernel<<<dim3(96, 24, 1), dim3(32, 8)>>>(ffn_w1, w1t, Cc, DFF, 0, 0);
    transpose_f2h_kernel<<<dim3(24, 96, 1), dim3(32, 8)>>>(ffn_w2, w2t, DFF, Cc, 0, 0);

    qconv_kernel<<<NT_, 256>>>(enc, qconv_w);
    transpose_h2h_kernel<<<dim3(3, 32, 64), dim3(32, 8)>>>(qh, vtp, Nn, HD,
                                                           (size_t)Nn * HD, (size_t)Nn * HD);

    launch_scores(qh, ap, scale);
    softmax_mix_kernel<<<NT_, 256>>>(reatten_w, reatten_b, bn_gamma, bn_beta);
    launch_av(ph, vtp, xh);
    launch_proj(xh, pwt, yp, proj_b, enc);
    layernorm_kernel<<<NT_, 256>>>(yp, yp, yh, ln1_g, ln1_b);
    launch_ffn1(yh, w1t, hh, ffn_b1);
    launch_ffn2(hh, w2t, xp, ffn_b2, yp);
    layernorm_kernel<<<NT_, 256>>>(xp, out, nullptr, ln2_g, ln2_b);
}